// round 5
// baseline (speedup 1.0000x reference)
#include <cuda_runtime.h>
#include <cuda_bf16.h>
#include <math.h>
#include <stdint.h>

// ---------------- problem constants ----------------
#define BSZ      2
#define SEQ      2048
#define NTOK     4096          // B*N
#define CACHE_T  512
#define KVLEN    2560
#define DM       768
#define NH       12
#define HD       64
#define FFD      3072
#define KSZ      31
#define EPSF     1e-5f

// ---------------- scratch (device globals; no allocation) ----------------
__device__ __align__(128) float g_h[NTOK * FFD];
__device__ __align__(128) float g_x1[NTOK * DM];
__device__ __align__(128) float g_x2[NTOK * DM];
__device__ __align__(128) float g_qkv[NTOK * 3 * NH * HD];
__device__ __align__(128) float g_tmp[NTOK * DM];
__device__ __align__(128) float g_conv[NTOK * DM];
__device__ float g_mean[DM];
__device__ float g_var[DM];
__device__ __align__(128) __nv_bfloat16 g_a2[NTOK * 2 * DM];             // (M,1536) hi|lo
__device__ __align__(128) __nv_bfloat16 g_ah[(size_t)NTOK * 2 * FFD];    // (M,6144) hi|lo
__device__ __align__(128) __nv_bfloat16 g_b2[(size_t)FFD * 2 * DM];      // weights (N,2K)
__device__ __align__(128) __nv_bfloat16 g_qh[BSZ * NH * SEQ * HD];
__device__ __align__(128) __nv_bfloat16 g_ql[BSZ * NH * SEQ * HD];
__device__ __align__(128) __nv_bfloat16 g_kh[BSZ * NH * KVLEN * HD];
__device__ __align__(128) __nv_bfloat16 g_kl[BSZ * NH * KVLEN * HD];
__device__ __align__(128) __nv_bfloat16 g_vth[BSZ * NH * HD * KVLEN];    // (b,h,d,t)
__device__ __align__(128) __nv_bfloat16 g_vtl[BSZ * NH * HD * KVLEN];

// ---------------- helpers ----------------
__device__ __forceinline__ float gelu_tanh(float x) {
    const float c = 0.7978845608028654f;
    float t = tanhf(c * (x + 0.044715f * x * x * x));
    return 0.5f * x * (1.0f + t);
}
__device__ __forceinline__ float sigmoidf_(float x) {
    return 1.0f / (1.0f + expf(-x));
}
__device__ __forceinline__ uint32_t smem_u32(const void* p) {
    uint32_t a;
    asm("{ .reg .u64 t; cvta.to.shared.u64 t, %1; cvt.u32.u64 %0, t; }"
        : "=r"(a) : "l"(p));
    return a;
}
__device__ __forceinline__ void cpasync16(uint32_t dst, const void* src) {
    asm volatile("cp.async.cg.shared.global [%0], [%1], 16;" :: "r"(dst), "l"(src));
}
__device__ __forceinline__ void cpcommit() {
    asm volatile("cp.async.commit_group;");
}
#define CP_WAIT(N) asm volatile("cp.async.wait_group %0;" :: "n"(N))
__device__ __forceinline__ void ldmx4(uint32_t r[4], uint32_t a) {
    asm volatile("ldmatrix.sync.aligned.m8n8.x4.shared.b16 {%0,%1,%2,%3}, [%4];"
                 : "=r"(r[0]), "=r"(r[1]), "=r"(r[2]), "=r"(r[3]) : "r"(a));
}
__device__ __forceinline__ void mma16816(float c[4], const uint32_t a[4],
                                         uint32_t b0, uint32_t b1) {
    asm volatile(
        "mma.sync.aligned.m16n8k16.row.col.f32.bf16.bf16.f32 "
        "{%0,%1,%2,%3}, {%4,%5,%6,%7}, {%8,%9}, {%0,%1,%2,%3};"
        : "+f"(c[0]), "+f"(c[1]), "+f"(c[2]), "+f"(c[3])
        : "r"(a[0]), "r"(a[1]), "r"(a[2]), "r"(a[3]), "r"(b0), "r"(b1));
}
__device__ __forceinline__ void splitpair(float x, float y,
                                          uint32_t& hi, uint32_t& lo) {
    __nv_bfloat16 hx = __float2bfloat16(x), hy = __float2bfloat16(y);
    __nv_bfloat162 H; H.x = hx; H.y = hy;
    __nv_bfloat162 L = __floats2bfloat162_rn(x - __bfloat162float(hx),
                                             y - __bfloat162float(hy));
    hi = *reinterpret_cast<uint32_t*>(&H);
    lo = *reinterpret_cast<uint32_t*>(&L);
}

// ---------------- weight conversion: W (K,N) fp32 -> (N,2K) bf16 hi|lo ----------------
__global__ void convB_kernel(const float* __restrict__ W,
                             __nv_bfloat16* __restrict__ out, int K, int N) {
    __shared__ float t[32][33];
    int k0 = blockIdx.x * 32, n0 = blockIdx.y * 32;
    int tx = threadIdx.x, ty = threadIdx.y;   // 32 x 8
    #pragma unroll
    for (int i = ty; i < 32; i += 8)
        t[i][tx] = W[(size_t)(k0 + i) * N + n0 + tx];
    __syncthreads();
    #pragma unroll
    for (int i = ty; i < 32; i += 8) {
        float v = t[tx][i];                   // W[k0+tx][n0+i]
        __nv_bfloat16 h = __float2bfloat16(v);
        float lo = v - __bfloat162float(h);
        size_t b = (size_t)(n0 + i) * (2 * K) + k0 + tx;
        out[b] = h;
        out[b + K] = __float2bfloat16(lo);
    }
}

// ---------------- warp-MMA bf16 GEMM, 3-pass split, 128x128x64 tile ----------------
// 128 threads, 4 warps (2m x 2n), warp tile 64x64. 3-stage cp.async pipeline.
// A2 (M,2K) K-major hi|lo, B2 (N,2K) K-major hi|lo.
// out_bf16=0: C fp32 (M,N) bias/act/scale/res.  out_bf16=1: C bf16 (M,2N) hi|lo.
__global__ __launch_bounds__(128, 2)
void hgemm_mma(const __nv_bfloat16* __restrict__ A2,
               const __nv_bfloat16* __restrict__ B2,
               void* __restrict__ Cout, int M, int N, int K,
               const float* __restrict__ bias, const float* __restrict__ res,
               float scale, int act, int out_bf16) {
    extern __shared__ __align__(16) unsigned char dsm[];
    uint32_t sbase = smem_u32(dsm);

    int tid = threadIdx.x;
    int lane = tid & 31;
    int wid = tid >> 5;
    int wm = (wid >> 1) * 64;
    int wn = (wid & 1) * 64;
    int bm = blockIdx.y * 128;
    int bn = blockIdx.x * 128;

    int kpp = K >> 6;
    int nkb = 3 * kpp;
    int sw_t = tid & 7;

    float acc[4][8][4];
    #pragma unroll
    for (int a = 0; a < 4; a++)
        #pragma unroll
        for (int b = 0; b < 8; b++)
            #pragma unroll
            for (int c = 0; c < 4; c++) acc[a][b][c] = 0.f;

    // one thread per tile row (128 rows); 8 x 16B chunks each for A and B
    auto issue = [&](int kb, int buf) {
        int p = kb / kpp;
        int off = (kb - p * kpp) << 6;
        int aCol = ((p == 2) ? K : 0) + off;
        int bCol = ((p == 1) ? K : 0) + off;
        const __nv_bfloat16* ag = A2 + (size_t)(bm + tid) * (2 * K) + aCol;
        const __nv_bfloat16* bg = B2 + (size_t)(bn + tid) * (2 * K) + bCol;
        uint32_t abuf = sbase + buf * 32768 + tid * 128;
        uint32_t bbuf = abuf + 16384;
        #pragma unroll
        for (int j = 0; j < 8; j++) {
            uint32_t phys = (uint32_t)((j ^ sw_t) * 16);
            cpasync16(abuf + phys, ag + j * 8);
            cpasync16(bbuf + phys, bg + j * 8);
        }
        cpcommit();
    };

    issue(0, 0);
    issue(1, 1);

    int rA = lane & 15;
    int kq = lane >> 4;
    int swA = rA & 7;

    for (int kb = 0; kb < nkb; kb++) {
        if (kb + 1 < nkb) { CP_WAIT(1); } else { CP_WAIT(0); }
        __syncthreads();
        if (kb + 2 < nkb) issue(kb + 2, (kb + 2) % 3);

        uint32_t Ab = sbase + (kb % 3) * 32768;
        uint32_t Bb = Ab + 16384;

        #pragma unroll
        for (int ks = 0; ks < 4; ks++) {
            uint32_t phys = (uint32_t)(((ks * 2 + kq) ^ swA) * 16);
            uint32_t af[4][4];
            #pragma unroll
            for (int mt = 0; mt < 4; mt++)
                ldmx4(af[mt], Ab + (uint32_t)(wm + mt * 16 + rA) * 128 + phys);
            uint32_t bf[8][2];
            #pragma unroll
            for (int g = 0; g < 4; g++) {
                uint32_t r[4];
                ldmx4(r, Bb + (uint32_t)(wn + g * 16 + rA) * 128 + phys);
                bf[2 * g][0] = r[0]; bf[2 * g][1] = r[2];
                bf[2 * g + 1][0] = r[1]; bf[2 * g + 1][1] = r[3];
            }
            #pragma unroll
            for (int mt = 0; mt < 4; mt++)
                #pragma unroll
                for (int nt = 0; nt < 8; nt++)
                    mma16816(acc[mt][nt], af[mt], bf[nt][0], bf[nt][1]);
        }
        // no trailing sync: next iteration's top barrier guards buffer reuse
    }

    int gq = lane >> 2;
    int tg = lane & 3;
    #pragma unroll
    for (int mt = 0; mt < 4; mt++) {
        #pragma unroll
        for (int nt = 0; nt < 8; nt++) {
            int row0 = bm + wm + mt * 16 + gq;
            int col = bn + wn + nt * 8 + 2 * tg;
            float bv0 = bias ? bias[col] : 0.f;
            float bv1 = bias ? bias[col + 1] : 0.f;
            #pragma unroll
            for (int half = 0; half < 2; half++) {
                int row = row0 + half * 8;
                float v0 = acc[mt][nt][2 * half + 0] + bv0;
                float v1 = acc[mt][nt][2 * half + 1] + bv1;
                if (act == 1) { v0 = gelu_tanh(v0); v1 = gelu_tanh(v1); }
                v0 *= scale; v1 *= scale;
                if (!out_bf16) {
                    float* C = (float*)Cout;
                    if (res) {
                        v0 += res[(size_t)row * N + col];
                        v1 += res[(size_t)row * N + col + 1];
                    }
                    *(float2*)&C[(size_t)row * N + col] = make_float2(v0, v1);
                } else {
                    __nv_bfloat16* C2 = (__nv_bfloat16*)Cout;
                    uint32_t hi, lo;
                    splitpair(v0, v1, hi, lo);
                    *(uint32_t*)&C2[(size_t)row * 2 * N + col] = hi;
                    *(uint32_t*)&C2[(size_t)row * 2 * N + N + col] = lo;
                }
            }
        }
    }
}

// ---------------- rmsnorm fp32 out (final) ----------------
__global__ void rmsnorm_kernel(const float* __restrict__ x,
                               const float* __restrict__ w,
                               float* __restrict__ y) {
    int row = blockIdx.x;
    const float* xr = x + (size_t)row * DM;
    float ss = 0.f;
    for (int i = threadIdx.x; i < DM; i += blockDim.x) {
        float v = xr[i];
        ss += v * v;
    }
    #pragma unroll
    for (int o = 16; o > 0; o >>= 1) ss += __shfl_xor_sync(0xffffffffu, ss, o);
    __shared__ float red[8];
    if ((threadIdx.x & 31) == 0) red[threadIdx.x >> 5] = ss;
    __syncthreads();
    __shared__ float s_r;
    if (threadIdx.x == 0) {
        float t = 0.f;
        #pragma unroll
        for (int i = 0; i < 8; i++) t += red[i];
        s_r = rsqrtf(t / (float)DM + EPSF);
    }
    __syncthreads();
    float r = s_r;
    float* yr = y + (size_t)row * DM;
    for (int i = threadIdx.x; i < DM; i += blockDim.x)
        yr[i] = xr[i] * r * w[i];
}

// ---------------- rmsnorm -> bf16 hi|lo A2 format ----------------
__global__ void rmsnorm_bf16_kernel(const float* __restrict__ x,
                                    const float* __restrict__ w,
                                    __nv_bfloat16* __restrict__ y) {
    int row = blockIdx.x;
    const float* xr = x + (size_t)row * DM;
    float ss = 0.f;
    for (int i = threadIdx.x; i < DM; i += blockDim.x) {
        float v = xr[i];
        ss += v * v;
    }
    #pragma unroll
    for (int o = 16; o > 0; o >>= 1) ss += __shfl_xor_sync(0xffffffffu, ss, o);
    __shared__ float red[8];
    if ((threadIdx.x & 31) == 0) red[threadIdx.x >> 5] = ss;
    __syncthreads();
    __shared__ float s_r;
    if (threadIdx.x == 0) {
        float t = 0.f;
        #pragma unroll
        for (int i = 0; i < 8; i++) t += red[i];
        s_r = rsqrtf(t / (float)DM + EPSF);
    }
    __syncthreads();
    float r = s_r;
    __nv_bfloat16* yr = y + (size_t)row * (2 * DM);
    for (int i = threadIdx.x; i < DM; i += blockDim.x) {
        float v = xr[i] * r * w[i];
        __nv_bfloat16 h = __float2bfloat16(v);
        yr[i] = h;
        yr[DM + i] = __float2bfloat16(v - __bfloat162float(h));
    }
}

// ---------------- qkv postproc: head rmsnorm + rope + split outputs ----------------
__global__ __launch_bounds__(128)
void qkv_post_kernel(const float* __restrict__ qkv,
                     const float* __restrict__ qnw, const float* __restrict__ knw,
                     __nv_bfloat16* __restrict__ Qh, __nv_bfloat16* __restrict__ Ql,
                     __nv_bfloat16* __restrict__ Kh, __nv_bfloat16* __restrict__ Kl,
                     __nv_bfloat16* __restrict__ Vth, __nv_bfloat16* __restrict__ Vtl,
                     float* __restrict__ kv_out) {
    int w = blockIdx.x * 4 + (threadIdx.x >> 5);
    int lane = threadIdx.x & 31;
    int h = w % NH;
    int tok = w / NH;
    int b = tok / SEQ;
    int n = tok % SEQ;

    const float* base = qkv + (size_t)tok * (3 * NH * HD) + h * (HD * 3);
    float q1 = base[lane * 3 + 0], q2 = base[(lane + 32) * 3 + 0];
    float k1 = base[lane * 3 + 1], k2 = base[(lane + 32) * 3 + 1];
    float v1 = base[lane * 3 + 2], v2 = base[(lane + 32) * 3 + 2];

    float sq = q1 * q1 + q2 * q2;
    #pragma unroll
    for (int o = 16; o > 0; o >>= 1) sq += __shfl_xor_sync(0xffffffffu, sq, o);
    float rq = rsqrtf(sq / 64.f + EPSF);
    q1 *= rq * qnw[lane]; q2 *= rq * qnw[lane + 32];

    float sk = k1 * k1 + k2 * k2;
    #pragma unroll
    for (int o = 16; o > 0; o >>= 1) sk += __shfl_xor_sync(0xffffffffu, sk, o);
    float rk = rsqrtf(sk / 64.f + EPSF);
    k1 *= rk * knw[lane]; k2 *= rk * knw[lane + 32];

    int t = CACHE_T + n;
    size_t kb = ((((size_t)b * KVLEN + t) * 2 + 0) * NH + h) * HD;
    kv_out[kb + lane] = k1;
    kv_out[kb + lane + 32] = k2;
    kv_out[kb + NH * HD + lane] = v1;
    kv_out[kb + NH * HD + lane + 32] = v2;

    float inv = 1.0f / powf(10000.0f, (float)lane / 32.0f);
    float ang = (float)t * inv;
    float c = cosf(ang), s = sinf(ang);

    int bh = b * NH + h;
    float qa = (q1 * c - q2 * s) * 0.125f;
    float qb2 = (q2 * c + q1 * s) * 0.125f;
    size_t qoff = ((size_t)bh * SEQ + n) * HD;
    {
        __nv_bfloat16 h1 = __float2bfloat16(qa);
        __nv_bfloat16 h2 = __float2bfloat16(qb2);
        Qh[qoff + lane] = h1;
        Qh[qoff + lane + 32] = h2;
        Ql[qoff + lane] = __float2bfloat16(qa - __bfloat162float(h1));
        Ql[qoff + lane + 32] = __float2bfloat16(qb2 - __bfloat162float(h2));
    }
    float ka = k1 * c - k2 * s;
    float kb2 = k2 * c + k1 * s;
    size_t koff = ((size_t)bh * KVLEN + t) * HD;
    {
        __nv_bfloat16 h1 = __float2bfloat16(ka);
        __nv_bfloat16 h2 = __float2bfloat16(kb2);
        Kh[koff + lane] = h1;
        Kh[koff + lane + 32] = h2;
        Kl[koff + lane] = __float2bfloat16(ka - __bfloat162float(h1));
        Kl[koff + lane + 32] = __float2bfloat16(kb2 - __bfloat162float(h2));
    }
    size_t voff = ((size_t)bh * HD) * KVLEN + t;
    {
        __nv_bfloat16 h1 = __float2bfloat16(v1);
        __nv_bfloat16 h2 = __float2bfloat16(v2);
        Vth[voff + (size_t)lane * KVLEN] = h1;
        Vth[voff + (size_t)(lane + 32) * KVLEN] = h2;
        Vtl[voff + (size_t)lane * KVLEN] = __float2bfloat16(v1 - __bfloat162float(h1));
        Vtl[voff + (size_t)(lane + 32) * KVLEN] = __float2bfloat16(v2 - __bfloat162float(h2));
    }
}

// ---------------- cached tokens: copy + rope + split ----------------
__global__ __launch_bounds__(128)
void cache_kernel(const float* __restrict__ cached,
                  __nv_bfloat16* __restrict__ Kh, __nv_bfloat16* __restrict__ Kl,
                  __nv_bfloat16* __restrict__ Vth, __nv_bfloat16* __restrict__ Vtl,
                  float* __restrict__ kv_out) {
    int w = blockIdx.x * 4 + (threadIdx.x >> 5);
    int lane = threadIdx.x & 31;
    int h = w % NH;
    int bt = w / NH;
    int b = bt / CACHE_T;
    int t = bt % CACHE_T;

    size_t src = ((((size_t)b * CACHE_T + t) * 2 + 0) * NH + h) * HD;
    float k1 = cached[src + lane], k2 = cached[src + lane + 32];
    float v1 = cached[src + NH * HD + lane], v2 = cached[src + NH * HD + lane + 32];

    size_t dst = ((((size_t)b * KVLEN + t) * 2 + 0) * NH + h) * HD;
    kv_out[dst + lane] = k1;
    kv_out[dst + lane + 32] = k2;
    kv_out[dst + NH * HD + lane] = v1;
    kv_out[dst + NH * HD + lane + 32] = v2;

    float inv = 1.0f / powf(10000.0f, (float)lane / 32.0f);
    float ang = (float)t * inv;
    float c = cosf(ang), s = sinf(ang);
    float ka = k1 * c - k2 * s;
    float kb2 = k2 * c + k1 * s;

    int bh = b * NH + h;
    size_t koff = ((size_t)bh * KVLEN + t) * HD;
    {
        __nv_bfloat16 h1 = __float2bfloat16(ka);
        __nv_bfloat16 h2 = __float2bfloat16(kb2);
        Kh[koff + lane] = h1;
        Kh[koff + lane + 32] = h2;
        Kl[koff + lane] = __float2bfloat16(ka - __bfloat162float(h1));
        Kl[koff + lane + 32] = __float2bfloat16(kb2 - __bfloat162float(h2));
    }
    size_t voff = ((size_t)bh * HD) * KVLEN + t;
    {
        __nv_bfloat16 h1 = __float2bfloat16(v1);
        __nv_bfloat16 h2 = __float2bfloat16(v2);
        Vth[voff + (size_t)lane * KVLEN] = h1;
        Vth[voff + (size_t)(lane + 32) * KVLEN] = h2;
        Vtl[voff + (size_t)lane * KVLEN] = __float2bfloat16(v1 - __bfloat162float(h1));
        Vtl[voff + (size_t)(lane + 32) * KVLEN] = __float2bfloat16(v2 - __bfloat162float(h2));
    }
}

// ---------------- attention: MMA flash, 64 q-rows/block, 64-key chunks ----------------
#define AT_STAGE 32768
__global__ __launch_bounds__(128)
void attn_mma(const __nv_bfloat16* __restrict__ Qh, const __nv_bfloat16* __restrict__ Ql,
              const __nv_bfloat16* __restrict__ Kh, const __nv_bfloat16* __restrict__ Kl,
              const __nv_bfloat16* __restrict__ Vth, const __nv_bfloat16* __restrict__ Vtl,
              __nv_bfloat16* __restrict__ OA2) {
    extern __shared__ __align__(16) unsigned char dsm[];
    uint32_t sbase = smem_u32(dsm);
    uint32_t qarea = sbase + 2 * AT_STAGE;

    int tid = threadIdx.x, lane = tid & 31, wid = tid >> 5;
    int bh = blockIdx.y;
    int b = bh / NH, h = bh % NH;
    int q0 = blockIdx.x * 64;

    size_t qoff = ((size_t)bh * SEQ + q0) * HD;
    size_t koff = (size_t)bh * KVLEN * HD;
    size_t voff = (size_t)bh * HD * KVLEN;

    int lr = tid >> 1;
    int lc4 = (tid & 1) * 4;

    {
        const __nv_bfloat16* qhg = Qh + qoff + lr * HD;
        const __nv_bfloat16* qlg = Ql + qoff + lr * HD;
        #pragma unroll
        for (int j = 0; j < 4; j++) {
            int ch = lc4 + j;
            uint32_t phys = (uint32_t)((ch ^ (lr & 7)) * 16);
            cpasync16(qarea + lr * 128 + phys, qhg + ch * 8);
            cpasync16(qarea + 8192 + lr * 128 + phys, qlg + ch * 8);
        }
        cpcommit();
    }

    auto issueKV = [&](int c, int buf) {
        uint32_t dst = sbase + buf * AT_STAGE + lr * 128;
        const __nv_bfloat16* khg = Kh + koff + (size_t)(c * 64 + lr) * HD;
        const __nv_bfloat16* klg = Kl + koff + (size_t)(c * 64 + lr) * HD;
        const __nv_bfloat16* vhg = Vth + voff + (size_t)lr * KVLEN + c * 64;
        const __nv_bfloat16* vlg = Vtl + voff + (size_t)lr * KVLEN + c * 64;
        #pragma unroll
        for (int j = 0; j < 4; j++) {
            int ch = lc4 + j;
            uint32_t phys = (uint32_t)((ch ^ (lr & 7)) * 16);
            cpasync16(dst + phys, khg + ch * 8);
            cpasync16(dst + 8192 + phys, klg + ch * 8);
            cpasync16(dst + 16384 + phys, vhg + ch * 8);
            cpasync16(dst + 24576 + phys, vlg + ch * 8);
        }
        cpcommit();
    };

    issueKV(0, 0);
    CP_WAIT(1);
    __syncthreads();

    int rA = lane & 15, kq = lane >> 4;
    int qrow = wid * 16 + rA;
    int qs = qrow & 7;
    uint32_t qfh[4][4], qfl[4][4];
    #pragma unroll
    for (int kt = 0; kt < 4; kt++) {
        uint32_t phys = (uint32_t)(((kt * 2 + kq) ^ qs) * 16);
        ldmx4(qfh[kt], qarea + qrow * 128 + phys);
        ldmx4(qfl[kt], qarea + 8192 + qrow * 128 + phys);
    }

    int gq = lane >> 2, tg = lane & 3;
    float m0 = -1e30f, m1 = -1e30f, l0 = 0.f, l1 = 0.f;
    float O[8][4];
    #pragma unroll
    for (int nt = 0; nt < 8; nt++)
        #pragma unroll
        for (int i = 0; i < 4; i++) O[nt][i] = 0.f;

    const int NCH = KVLEN / 64;
    for (int c = 0; c < NCH; c++) {
        if (c + 1 < NCH) { issueKV(c + 1, (c + 1) & 1); CP_WAIT(1); }
        else { CP_WAIT(0); }
        __syncthreads();

        uint32_t bufK = sbase + (c & 1) * AT_STAGE;
        uint32_t bufV = bufK + 16384;

        float S[8][4];
        #pragma unroll
        for (int nt = 0; nt < 8; nt++)
            #pragma unroll
            for (int i = 0; i < 4; i++) S[nt][i] = 0.f;

        #pragma unroll
        for (int kt = 0; kt < 4; kt++) {
            uint32_t kfh[4][4], kfl[4][4];
            #pragma unroll
            for (int g2 = 0; g2 < 4; g2++) {
                int krow = g2 * 16 + rA;
                uint32_t phys = (uint32_t)(((kt * 2 + kq) ^ (krow & 7)) * 16);
                ldmx4(kfh[g2], bufK + krow * 128 + phys);
                ldmx4(kfl[g2], bufK + 8192 + krow * 128 + phys);
            }
            #pragma unroll
            for (int g2 = 0; g2 < 4; g2++)
                #pragma unroll
                for (int hf = 0; hf < 2; hf++) {
                    int nt = 2 * g2 + hf;
                    mma16816(S[nt], qfh[kt], kfh[g2][hf], kfh[g2][hf + 2]);
                    mma16816(S[nt], qfh[kt], kfl[g2][hf], kfl[g2][hf + 2]);
                    mma16816(S[nt], qfl[kt], kfh[g2][hf], kfh[g2][hf + 2]);
                }
        }

        float mx0 = -1e30f, mx1 = -1e30f;
        #pragma unroll
        for (int nt = 0; nt < 8; nt++) {
            mx0 = fmaxf(mx0, fmaxf(S[nt][0], S[nt][1]));
            mx1 = fmaxf(mx1, fmaxf(S[nt][2], S[nt][3]));
        }
        mx0 = fmaxf(mx0, __shfl_xor_sync(0xffffffffu, mx0, 1));
        mx0 = fmaxf(mx0, __shfl_xor_sync(0xffffffffu, mx0, 2));
        mx1 = fmaxf(mx1, __shfl_xor_sync(0xffffffffu, mx1, 1));
        mx1 = fmaxf(mx1, __shfl_xor_sync(0xffffffffu, mx1, 2));
        float nm0 = fmaxf(m0, mx0), nm1 = fmaxf(m1, mx1);
        float a0 = __expf(m0 - nm0), a1 = __expf(m1 - nm1);

        float rs0 = 0.f, rs1 = 0.f;
        #pragma unroll
        for (int nt = 0; nt < 8; nt++) {
            S[nt][0] = __expf(S[nt][0] - nm0);
            S[nt][1] = __expf(S[nt][1] - nm0);
            S[nt][2] = __expf(S[nt][2] - nm1);
            S[nt][3] = __expf(S[nt][3] - nm1);
            rs0 += S[nt][0] + S[nt][1];
            rs1 += S[nt][2] + S[nt][3];
        }
        rs0 += __shfl_xor_sync(0xffffffffu, rs0, 1);
        rs0 += __shfl_xor_sync(0xffffffffu, rs0, 2);
        rs1 += __shfl_xor_sync(0xffffffffu, rs1, 1);
        rs1 += __shfl_xor_sync(0xffffffffu, rs1, 2);
        l0 = l0 * a0 + rs0;
        l1 = l1 * a1 + rs1;
        m0 = nm0; m1 = nm1;
        #pragma unroll
        for (int nt = 0; nt < 8; nt++) {
            O[nt][0] *= a0; O[nt][1] *= a0;
            O[nt][2] *= a1; O[nt][3] *= a1;
        }

        #pragma unroll
        for (int kt = 0; kt < 4; kt++) {
            uint32_t ah[4], al[4];
            splitpair(S[2 * kt][0], S[2 * kt][1], ah[0], al[0]);
            splitpair(S[2 * kt][2], S[2 * kt][3], ah[1], al[1]);
            splitpair(S[2 * kt + 1][0], S[2 * kt + 1][1], ah[2], al[2]);
            splitpair(S[2 * kt + 1][2], S[2 * kt + 1][3], ah[3], al[3]);
            uint32_t vfh[4][4], vfl[4][4];
            #pragma unroll
            for (int g2 = 0; g2 < 4; g2++) {
                int vrow = g2 * 16 + rA;
                uint32_t phys = (uint32_t)(((kt * 2 + kq) ^ (vrow & 7)) * 16);
                ldmx4(vfh[g2], bufV + vrow * 128 + phys);
                ldmx4(vfl[g2], bufV + 8192 + vrow * 128 + phys);
            }
            #pragma unroll
            for (int g2 = 0; g2 < 4; g2++)
                #pragma unroll
                for (int hf = 0; hf < 2; hf++) {
                    int nt = 2 * g2 + hf;
                    mma16816(O[nt], ah, vfh[g2][hf], vfh[g2][hf + 2]);
                    mma16816(O[nt], ah, vfl[g2][hf], vfl[g2][hf + 2]);
                    mma16816(O[nt], al, vfh[g2][hf], vfh[g2][hf + 2]);
                }
        }
        __syncthreads();
    }

    float inv0 = 1.0f / l0, inv1 = 1.0f / l1;
    int r0 = q0 + wid * 16 + gq;
    size_t tok0 = (size_t)(b * SEQ + r0);
    size_t tok1 = tok0 + 8;
    #pragma unroll
    for (int nt = 0; nt < 8; nt++) {
        int col = h * HD + nt * 8 + 2 * tg;
        uint32_t hi, lo;
        splitpair(O[nt][0] * inv0, O[nt][1] * inv0, hi, lo);
        *(uint32_t*)&OA2[tok0 * (2 * DM) + col] = hi;
        *(uint32_t*)&OA2[tok0 * (2 * DM) + DM + col] = lo;
        splitpair(O[nt][2] * inv1, O[nt][3] * inv1, hi, lo);
        *(uint32_t*)&OA2[tok1 * (2 * DM) + col] = hi;
        *(uint32_t*)&OA2[tok1 * (2 * DM) + DM + col] = lo;
    }
}

// ---------------- GLU ----------------
__global__ void glu_kernel(const float* __restrict__ in, float* __restrict__ out) {
    int i = blockIdx.x * blockDim.x + threadIdx.x;
    if (i >= NTOK * DM) return;
    int r = i / DM, c = i % DM;
    float a = in[(size_t)r * (2 * DM) + c];
    float bb = in[(size_t)r * (2 * DM) + DM + c];
    out[i] = a * sigmoidf_(bb);
}

// ---------------- depthwise conv ----------------
__global__ void dwconv_kernel(const float* __restrict__ in,
                              const float* __restrict__ w,
                              const float* __restrict__ bias,
                              float* __restrict__ out) {
    int i = blockIdx.x * blockDim.x + threadIdx.x;
    if (i >= NTOK * DM) return;
    int c = i % DM;
    int pos = i / DM;
    int n = pos % SEQ;
    int b = pos / SEQ;
    float acc = bias[c];
    #pragma unroll
    for (int k = 0; k < KSZ; k++) {
        int nn = n - (KSZ / 2) + k;
        if (nn >= 0 && nn < SEQ)
            acc = fmaf(in[((size_t)b * SEQ + nn) * DM + c], w[c * KSZ + k], acc);
    }
    out[i] = acc;
}

// ---------------- batchnorm stats ----------------
__global__ void bnstats_kernel(const float* __restrict__ in,
                               float* __restrict__ mean, float* __restrict__ var) {
    int c = blockIdx.x;
    float s = 0.f, ss = 0.f;
    for (int r = threadIdx.x; r < NTOK; r += blockDim.x) {
        float v = in[(size_t)r * DM + c];
        s += v;
        ss += v * v;
    }
    #pragma unroll
    for (int o = 16; o > 0; o >>= 1) {
        s += __shfl_xor_sync(0xffffffffu, s, o);
        ss += __shfl_xor_sync(0xffffffffu, ss, o);
    }
    __shared__ float rs[8], rss[8];
    if ((threadIdx.x & 31) == 0) {
        rs[threadIdx.x >> 5] = s;
        rss[threadIdx.x >> 5] = ss;
    }
    __syncthreads();
    if (threadIdx.x == 0) {
        float ts = 0.f, tss = 0.f;
        #pragma unroll
        for (int i = 0; i < 8; i++) { ts += rs[i]; tss += rss[i]; }
        float m = ts / (float)NTOK;
        mean[c] = m;
        var[c] = tss / (float)NTOK - m * m;
    }
}

// ---------------- bn apply + swish -> bf16 hi|lo ----------------
__global__ void bnapply_bf16_kernel(const float* __restrict__ in,
                                    const float* __restrict__ mean, const float* __restrict__ var,
                                    const float* __restrict__ g, const float* __restrict__ be,
                                    __nv_bfloat16* __restrict__ out) {
    int i = blockIdx.x * blockDim.x + threadIdx.x;
    if (i >= NTOK * DM) return;
    int r = i / DM, c = i % DM;
    float y = (in[i] - mean[c]) * rsqrtf(var[c] + EPSF) * g[c] + be[c];
    y = y * sigmoidf_(y);
    __nv_bfloat16 h = __float2bfloat16(y);
    out[(size_t)r * (2 * DM) + c] = h;
    out[(size_t)r * (2 * DM) + DM + c] = __float2bfloat16(y - __bfloat162float(h));
}

// ---------------- host-side helpers ----------------
static __nv_bfloat16* s_b2 = nullptr;

static void tc_gemm(const __nv_bfloat16* A2, const float* W, void* C,
                    int M, int N, int K,
                    const float* bias, const float* res, float scale, int act,
                    int out_bf16) {
    convB_kernel<<<dim3(K / 32, N / 32), dim3(32, 8)>>>(W, s_b2, K, N);
    hgemm_mma<<<dim3(N / 128, M / 128), 128, 98304>>>(A2, s_b2, C, M, N, K,
                                                      bias, res, scale, act, out_bf16);
}

extern "C" void kernel_launch(void* const* d_in, const int* in_sizes, int n_in,
                              void* d_out, int out_size) {
    (void)in_sizes; (void)n_in; (void)out_size;
    const float* x          = (const float*)d_in[0];
    const float* cached_kv  = (const float*)d_in[4];
    const float* ff1_norm_w = (const float*)d_in[5];
    const float* ff1_w1     = (const float*)d_in[6];
    const float* ff1_b1     = (const float*)d_in[7];
    const float* ff1_w2     = (const float*)d_in[8];
    const float* ff1_b2     = (const float*)d_in[9];
    const float* attn_norm_w= (const float*)d_in[10];
    const float* qkv_w      = (const float*)d_in[11];
    const float* out_w      = (const float*)d_in[12];
    const float* q_norm_w   = (const float*)d_in[13];
    const float* k_norm_w   = (const float*)d_in[14];
    const float* conv_norm_w= (const float*)d_in[15];
    const float* pw1_w      = (const float*)d_in[16];
    const float* pw1_b      = (const float*)d_in[17];
    const float* dw_w       = (const float*)d_in[18];
    const float* dw_b       = (const float*)d_in[19];
    const float* bn_g       = (const float*)d_in[20];
    const float* bn_b       = (const float*)d_in[21];
    const float* pw2_w      = (const float*)d_in[22];
    const float* pw2_b      = (const float*)d_in[23];
    const float* ff2_norm_w = (const float*)d_in[24];
    const float* ff2_w1     = (const float*)d_in[25];
    const float* ff2_b1     = (const float*)d_in[26];
    const float* ff2_w2     = (const float*)d_in[27];
    const float* ff2_b2     = (const float*)d_in[28];
    const float* out_norm_w = (const float*)d_in[29];

    float* out_x  = (float*)d_out;
    float* out_kv = out_x + (size_t)NTOK * DM;

    float *gH, *gX1, *gX2, *gQKV, *gT, *gC, *gM, *gV;
    __nv_bfloat16 *gA2, *gAH, *gQh, *gQl, *gKh, *gKl, *gVth, *gVtl;
    cudaGetSymbolAddress((void**)&gH,   g_h);
    cudaGetSymbolAddress((void**)&gX1,  g_x1);
    cudaGetSymbolAddress((void**)&gX2,  g_x2);
    cudaGetSymbolAddress((void**)&gQKV, g_qkv);
    cudaGetSymbolAddress((void**)&gT,   g_tmp);
    cudaGetSymbolAddress((void**)&gC,   g_conv);
    cudaGetSymbolAddress((void**)&gM,   g_mean);
    cudaGetSymbolAddress((void**)&gV,   g_var);
    cudaGetSymbolAddress((void**)&gA2,  g_a2);
    cudaGetSymbolAddress((void**)&gAH,  g_ah);
    cudaGetSymbolAddress((void**)&s_b2, g_b2);
    cudaGetSymbolAddress((void**)&gQh,  g_qh);
    cudaGetSymbolAddress((void**)&gQl,  g_ql);
    cudaGetSymbolAddress((void**)&gKh,  g_kh);
    cudaGetSymbolAddress((void**)&gKl,  g_kl);
    cudaGetSymbolAddress((void**)&gVth, g_vth);
    cudaGetSymbolAddress((void**)&gVtl, g_vtl);

    cudaFuncSetAttribute(hgemm_mma, cudaFuncAttributeMaxDynamicSharedMemorySize, 98304);
    cudaFuncSetAttribute(attn_mma, cudaFuncAttributeMaxDynamicSharedMemorySize, 81920);

    const int EW_BLOCKS = (NTOK * DM + 255) / 256;

    // ---- FF1 ----
    rmsnorm_bf16_kernel<<<NTOK, 256>>>(x, ff1_norm_w, gA2);
    tc_gemm(gA2, ff1_w1, gAH, NTOK, FFD, DM, ff1_b1, nullptr, 1.0f, 1, 1);
    tc_gemm(gAH, ff1_w2, gX1, NTOK, DM, FFD, ff1_b2, x, 0.5f, 0, 0);

    // ---- Attention ----
    rmsnorm_bf16_kernel<<<NTOK, 256>>>(gX1, attn_norm_w, gA2);
    tc_gemm(gA2, qkv_w, gQKV, NTOK, 3 * NH * HD, DM, nullptr, nullptr, 1.0f, 0, 0);
    qkv_post_kernel<<<NTOK * NH / 4, 128>>>(gQKV, q_norm_w, k_norm_w,
                                            gQh, gQl, gKh, gKl, gVth, gVtl, out_kv);
    cache_kernel<<<BSZ * CACHE_T * NH / 4, 128>>>(cached_kv, gKh, gKl, gVth, gVtl, out_kv);
    attn_mma<<<dim3(SEQ / 64, BSZ * NH), 128, 81920>>>(gQh, gQl, gKh, gKl, gVth, gVtl, gA2);
    tc_gemm(gA2, out_w, gX2, NTOK, DM, DM, nullptr, gX1, 1.0f, 0, 0);

    // ---- Conv module ----
    rmsnorm_bf16_kernel<<<NTOK, 256>>>(gX2, conv_norm_w, gA2);
    tc_gemm(gA2, pw1_w, gH, NTOK, 2 * DM, DM, pw1_b, nullptr, 1.0f, 0, 0);
    glu_kernel<<<EW_BLOCKS, 256>>>(gH, gT);
    dwconv_kernel<<<EW_BLOCKS, 256>>>(gT, dw_w, dw_b, gC);
    bnstats_kernel<<<DM, 256>>>(gC, gM, gV);
    bnapply_bf16_kernel<<<EW_BLOCKS, 256>>>(gC, gM, gV, bn_g, bn_b, gA2);
    tc_gemm(gA2, pw2_w, gX1, NTOK, DM, DM, pw2_b, nullptr, 1.0f, 0, 0);

    // ---- FF2 ----
    rmsnorm_bf16_kernel<<<NTOK, 256>>>(gX1, ff2_norm_w, gA2);
    tc_gemm(gA2, ff2_w1, gAH, NTOK, FFD, DM, ff2_b1, nullptr, 1.0f, 1, 1);
    tc_gemm(gAH, ff2_w2, gX2, NTOK, DM, FFD, ff2_b2, gX1, 0.5f, 0, 0);

    // ---- final norm ----
    rmsnorm_kernel<<<NTOK, 256>>>(gX2, out_norm_w, out_x);
}

// round 7
// speedup vs baseline: 2.0106x; 2.0106x over previous
#include <cuda_runtime.h>
#include <cuda_bf16.h>
#include <math.h>
#include <stdint.h>

// ---------------- problem constants ----------------
#define BSZ      2
#define SEQ      2048
#define NTOK     4096          // B*N
#define CACHE_T  512
#define KVLEN    2560
#define DM       768
#define NH       12
#define HD       64
#define FFD      3072
#define KSZ      31
#define EPSF     1e-5f

// ---------------- scratch (device globals; no allocation) ----------------
__device__ __align__(128) float g_h[NTOK * FFD];
__device__ __align__(128) float g_x1[NTOK * DM];
__device__ __align__(128) float g_x2[NTOK * DM];
__device__ __align__(128) float g_qkv[NTOK * 3 * NH * HD];
__device__ __align__(128) float g_tmp[NTOK * DM];
__device__ __align__(128) float g_conv[NTOK * DM];
__device__ float g_mean[DM];
__device__ float g_var[DM];
__device__ __align__(128) __nv_bfloat16 g_a2[NTOK * 2 * DM];             // (M,1536) hi|lo
__device__ __align__(128) __nv_bfloat16 g_ah[(size_t)NTOK * 2 * FFD];    // (M,6144) hi|lo
__device__ __align__(128) __nv_bfloat16 g_b2[(size_t)FFD * 2 * DM];      // weights (N,2K)
__device__ __align__(128) __nv_bfloat16 g_qh[BSZ * NH * SEQ * HD];
__device__ __align__(128) __nv_bfloat16 g_ql[BSZ * NH * SEQ * HD];
__device__ __align__(128) __nv_bfloat16 g_kh[BSZ * NH * KVLEN * HD];
__device__ __align__(128) __nv_bfloat16 g_kl[BSZ * NH * KVLEN * HD];
__device__ __align__(128) __nv_bfloat16 g_vth[BSZ * NH * HD * KVLEN];    // (b,h,d,t)
__device__ __align__(128) __nv_bfloat16 g_vtl[BSZ * NH * HD * KVLEN];

// ---------------- helpers ----------------
__device__ __forceinline__ float gelu_tanh(float x) {
    const float c = 0.7978845608028654f;
    float t = tanhf(c * (x + 0.044715f * x * x * x));
    return 0.5f * x * (1.0f + t);
}
__device__ __forceinline__ float sigmoidf_(float x) {
    return 1.0f / (1.0f + expf(-x));
}
__device__ __forceinline__ uint32_t smem_u32(const void* p) {
    uint32_t a;
    asm("{ .reg .u64 t; cvta.to.shared.u64 t, %1; cvt.u32.u64 %0, t; }"
        : "=r"(a) : "l"(p));
    return a;
}
__device__ __forceinline__ void cpasync16(uint32_t dst, const void* src) {
    asm volatile("cp.async.cg.shared.global [%0], [%1], 16;" :: "r"(dst), "l"(src));
}
__device__ __forceinline__ void cpcommit() {
    asm volatile("cp.async.commit_group;");
}
#define CP_WAIT(N) asm volatile("cp.async.wait_group %0;" :: "n"(N))
__device__ __forceinline__ void ldmx4(uint32_t r[4], uint32_t a) {
    asm volatile("ldmatrix.sync.aligned.m8n8.x4.shared.b16 {%0,%1,%2,%3}, [%4];"
                 : "=r"(r[0]), "=r"(r[1]), "=r"(r[2]), "=r"(r[3]) : "r"(a));
}
__device__ __forceinline__ void mma16816(float c[4], const uint32_t a[4],
                                         uint32_t b0, uint32_t b1) {
    asm volatile(
        "mma.sync.aligned.m16n8k16.row.col.f32.bf16.bf16.f32 "
        "{%0,%1,%2,%3}, {%4,%5,%6,%7}, {%8,%9}, {%0,%1,%2,%3};"
        : "+f"(c[0]), "+f"(c[1]), "+f"(c[2]), "+f"(c[3])
        : "r"(a[0]), "r"(a[1]), "r"(a[2]), "r"(a[3]), "r"(b0), "r"(b1));
}
__device__ __forceinline__ void splitpair(float x, float y,
                                          uint32_t& hi, uint32_t& lo) {
    __nv_bfloat16 hx = __float2bfloat16(x), hy = __float2bfloat16(y);
    __nv_bfloat162 H; H.x = hx; H.y = hy;
    __nv_bfloat162 L = __floats2bfloat162_rn(x - __bfloat162float(hx),
                                             y - __bfloat162float(hy));
    hi = *reinterpret_cast<uint32_t*>(&H);
    lo = *reinterpret_cast<uint32_t*>(&L);
}

// ---------------- weight conversion: W (K,N) fp32 -> (N,2K) bf16 hi|lo ----------------
__global__ void convB_kernel(const float* __restrict__ W,
                             __nv_bfloat16* __restrict__ out, int K, int N) {
    __shared__ float t[32][33];
    int k0 = blockIdx.x * 32, n0 = blockIdx.y * 32;
    int tx = threadIdx.x, ty = threadIdx.y;   // 32 x 8
    #pragma unroll
    for (int i = ty; i < 32; i += 8)
        t[i][tx] = W[(size_t)(k0 + i) * N + n0 + tx];
    __syncthreads();
    #pragma unroll
    for (int i = ty; i < 32; i += 8) {
        float v = t[tx][i];                   // W[k0+tx][n0+i]
        __nv_bfloat16 h = __float2bfloat16(v);
        float lo = v - __bfloat162float(h);
        size_t b = (size_t)(n0 + i) * (2 * K) + k0 + tx;
        out[b] = h;
        out[b + K] = __float2bfloat16(lo);
    }
}

// ---------------- warp-MMA bf16 GEMM, 3-pass split, 128x128x64 tile, 3-stage ----------------
// 256 threads, 8 warps (2m x 4n), warp tile 64x32.  (R4-proven config.)
// A2 (M,2K) K-major hi|lo, B2 (N,2K) K-major hi|lo.
// out_bf16=0: C fp32 (M,N) bias/act/scale/res.  out_bf16=1: C bf16 (M,2N) hi|lo.
__global__ __launch_bounds__(256)
void hgemm_mma(const __nv_bfloat16* __restrict__ A2,
               const __nv_bfloat16* __restrict__ B2,
               void* __restrict__ Cout, int M, int N, int K,
               const float* __restrict__ bias, const float* __restrict__ res,
               float scale, int act, int out_bf16) {
    extern __shared__ __align__(16) unsigned char dsm[];
    uint32_t sbase = smem_u32(dsm);

    int tid = threadIdx.x;
    int lane = tid & 31;
    int wid = tid >> 5;
    int wm = (wid >> 2) * 64;
    int wn = (wid & 3) * 32;
    int bm = blockIdx.y * 128;
    int bn = blockIdx.x * 128;

    int kpp = K >> 6;
    int nkb = 3 * kpp;

    int lr = tid >> 1;
    int lc = (tid & 1) * 4;
    int sw_r = lr & 7;

    float acc[4][4][4];
    #pragma unroll
    for (int a = 0; a < 4; a++)
        #pragma unroll
        for (int b = 0; b < 4; b++)
            #pragma unroll
            for (int c = 0; c < 4; c++) acc[a][b][c] = 0.f;

    auto issue = [&](int kb, int buf) {
        int p = kb / kpp;
        int off = (kb - p * kpp) << 6;
        int aCol = ((p == 2) ? K : 0) + off;
        int bCol = ((p == 1) ? K : 0) + off;
        const __nv_bfloat16* ag = A2 + (size_t)(bm + lr) * (2 * K) + aCol + lc * 8;
        const __nv_bfloat16* bg = B2 + (size_t)(bn + lr) * (2 * K) + bCol + lc * 8;
        uint32_t abuf = sbase + buf * 32768 + lr * 128;
        uint32_t bbuf = abuf + 16384;
        #pragma unroll
        for (int j = 0; j < 4; j++) {
            uint32_t phys = (uint32_t)((lc + j) ^ sw_r) * 16;
            cpasync16(abuf + phys, ag + j * 8);
            cpasync16(bbuf + phys, bg + j * 8);
        }
        cpcommit();
    };

    issue(0, 0);
    issue(1, 1);

    int rA = lane & 15;
    int kq = lane >> 4;
    int swA = rA & 7;

    for (int kb = 0; kb < nkb; kb++) {
        if (kb + 1 < nkb) { CP_WAIT(1); } else { CP_WAIT(0); }
        __syncthreads();
        if (kb + 2 < nkb) issue(kb + 2, (kb + 2) % 3);

        uint32_t Ab = sbase + (kb % 3) * 32768;
        uint32_t Bb = Ab + 16384;

        #pragma unroll
        for (int ks = 0; ks < 4; ks++) {
            uint32_t phys = (uint32_t)(((ks * 2 + kq) ^ swA) * 16);
            uint32_t af[4][4];
            #pragma unroll
            for (int mt = 0; mt < 4; mt++)
                ldmx4(af[mt], Ab + (uint32_t)(wm + mt * 16 + rA) * 128 + phys);
            uint32_t bf[4][2];
            #pragma unroll
            for (int g = 0; g < 2; g++) {
                uint32_t r[4];
                ldmx4(r, Bb + (uint32_t)(wn + g * 16 + rA) * 128 + phys);
                bf[2 * g][0] = r[0]; bf[2 * g][1] = r[2];
                bf[2 * g + 1][0] = r[1]; bf[2 * g + 1][1] = r[3];
            }
            #pragma unroll
            for (int mt = 0; mt < 4; mt++)
                #pragma unroll
                for (int nt = 0; nt < 4; nt++)
                    mma16816(acc[mt][nt], af[mt], bf[nt][0], bf[nt][1]);
        }
        // no trailing sync: next iteration's top barrier guards buffer reuse
    }

    int gq = lane >> 2;
    int tg = lane & 3;
    #pragma unroll
    for (int mt = 0; mt < 4; mt++) {
        #pragma unroll
        for (int nt = 0; nt < 4; nt++) {
            int row0 = bm + wm + mt * 16 + gq;
            int col = bn + wn + nt * 8 + 2 * tg;
            float bv0 = bias ? bias[col] : 0.f;
            float bv1 = bias ? bias[col + 1] : 0.f;
            #pragma unroll
            for (int half = 0; half < 2; half++) {
                int row = row0 + half * 8;
                float v0 = acc[mt][nt][2 * half + 0] + bv0;
                float v1 = acc[mt][nt][2 * half + 1] + bv1;
                if (act == 1) { v0 = gelu_tanh(v0); v1 = gelu_tanh(v1); }
                v0 *= scale; v1 *= scale;
                if (!out_bf16) {
                    float* C = (float*)Cout;
                    if (res) {
                        v0 += res[(size_t)row * N + col];
                        v1 += res[(size_t)row * N + col + 1];
                    }
                    *(float2*)&C[(size_t)row * N + col] = make_float2(v0, v1);
                } else {
                    __nv_bfloat16* C2 = (__nv_bfloat16*)Cout;
                    uint32_t hi, lo;
                    splitpair(v0, v1, hi, lo);
                    *(uint32_t*)&C2[(size_t)row * 2 * N + col] = hi;
                    *(uint32_t*)&C2[(size_t)row * 2 * N + N + col] = lo;
                }
            }
        }
    }
}

// ---------------- rmsnorm fp32 out (final) ----------------
__global__ void rmsnorm_kernel(const float* __restrict__ x,
                               const float* __restrict__ w,
                               float* __restrict__ y) {
    int row = blockIdx.x;
    const float* xr = x + (size_t)row * DM;
    float ss = 0.f;
    for (int i = threadIdx.x; i < DM; i += blockDim.x) {
        float v = xr[i];
        ss += v * v;
    }
    #pragma unroll
    for (int o = 16; o > 0; o >>= 1) ss += __shfl_xor_sync(0xffffffffu, ss, o);
    __shared__ float red[8];
    if ((threadIdx.x & 31) == 0) red[threadIdx.x >> 5] = ss;
    __syncthreads();
    __shared__ float s_r;
    if (threadIdx.x == 0) {
        float t = 0.f;
        #pragma unroll
        for (int i = 0; i < 8; i++) t += red[i];
        s_r = rsqrtf(t / (float)DM + EPSF);
    }
    __syncthreads();
    float r = s_r;
    float* yr = y + (size_t)row * DM;
    for (int i = threadIdx.x; i < DM; i += blockDim.x)
        yr[i] = xr[i] * r * w[i];
}

// ---------------- rmsnorm -> bf16 hi|lo A2 format ----------------
__global__ void rmsnorm_bf16_kernel(const float* __restrict__ x,
                                    const float* __restrict__ w,
                                    __nv_bfloat16* __restrict__ y) {
    int row = blockIdx.x;
    const float* xr = x + (size_t)row * DM;
    float ss = 0.f;
    for (int i = threadIdx.x; i < DM; i += blockDim.x) {
        float v = xr[i];
        ss += v * v;
    }
    #pragma unroll
    for (int o = 16; o > 0; o >>= 1) ss += __shfl_xor_sync(0xffffffffu, ss, o);
    __shared__ float red[8];
    if ((threadIdx.x & 31) == 0) red[threadIdx.x >> 5] = ss;
    __syncthreads();
    __shared__ float s_r;
    if (threadIdx.x == 0) {
        float t = 0.f;
        #pragma unroll
        for (int i = 0; i < 8; i++) t += red[i];
        s_r = rsqrtf(t / (float)DM + EPSF);
    }
    __syncthreads();
    float r = s_r;
    __nv_bfloat16* yr = y + (size_t)row * (2 * DM);
    for (int i = threadIdx.x; i < DM; i += blockDim.x) {
        float v = xr[i] * r * w[i];
        __nv_bfloat16 h = __float2bfloat16(v);
        yr[i] = h;
        yr[DM + i] = __float2bfloat16(v - __bfloat162float(h));
    }
}

// ---------------- qkv postproc: head rmsnorm + rope + split outputs ----------------
__global__ __launch_bounds__(128)
void qkv_post_kernel(const float* __restrict__ qkv,
                     const float* __restrict__ qnw, const float* __restrict__ knw,
                     __nv_bfloat16* __restrict__ Qh, __nv_bfloat16* __restrict__ Ql,
                     __nv_bfloat16* __restrict__ Kh, __nv_bfloat16* __restrict__ Kl,
                     __nv_bfloat16* __restrict__ Vth, __nv_bfloat16* __restrict__ Vtl,
                     float* __restrict__ kv_out) {
    int w = blockIdx.x * 4 + (threadIdx.x >> 5);
    int lane = threadIdx.x & 31;
    int h = w % NH;
    int tok = w / NH;
    int b = tok / SEQ;
    int n = tok % SEQ;

    const float* base = qkv + (size_t)tok * (3 * NH * HD) + h * (HD * 3);
    float q1 = base[lane * 3 + 0], q2 = base[(lane + 32) * 3 + 0];
    float k1 = base[lane * 3 + 1], k2 = base[(lane + 32) * 3 + 1];
    float v1 = base[lane * 3 + 2], v2 = base[(lane + 32) * 3 + 2];

    float sq = q1 * q1 + q2 * q2;
    #pragma unroll
    for (int o = 16; o > 0; o >>= 1) sq += __shfl_xor_sync(0xffffffffu, sq, o);
    float rq = rsqrtf(sq / 64.f + EPSF);
    q1 *= rq * qnw[lane]; q2 *= rq * qnw[lane + 32];

    float sk = k1 * k1 + k2 * k2;
    #pragma unroll
    for (int o = 16; o > 0; o >>= 1) sk += __shfl_xor_sync(0xffffffffu, sk, o);
    float rk = rsqrtf(sk / 64.f + EPSF);
    k1 *= rk * knw[lane]; k2 *= rk * knw[lane + 32];

    int t = CACHE_T + n;
    size_t kb = ((((size_t)b * KVLEN + t) * 2 + 0) * NH + h) * HD;
    kv_out[kb + lane] = k1;
    kv_out[kb + lane + 32] = k2;
    kv_out[kb + NH * HD + lane] = v1;
    kv_out[kb + NH * HD + lane + 32] = v2;

    float inv = 1.0f / powf(10000.0f, (float)lane / 32.0f);
    float ang = (float)t * inv;
    float c = cosf(ang), s = sinf(ang);

    int bh = b * NH + h;
    float qa = (q1 * c - q2 * s) * 0.125f;
    float qb2 = (q2 * c + q1 * s) * 0.125f;
    size_t qoff = ((size_t)bh * SEQ + n) * HD;
    {
        __nv_bfloat16 h1 = __float2bfloat16(qa);
        __nv_bfloat16 h2 = __float2bfloat16(qb2);
        Qh[qoff + lane] = h1;
        Qh[qoff + lane + 32] = h2;
        Ql[qoff + lane] = __float2bfloat16(qa - __bfloat162float(h1));
        Ql[qoff + lane + 32] = __float2bfloat16(qb2 - __bfloat162float(h2));
    }
    float ka = k1 * c - k2 * s;
    float kb2 = k2 * c + k1 * s;
    size_t koff = ((size_t)bh * KVLEN + t) * HD;
    {
        __nv_bfloat16 h1 = __float2bfloat16(ka);
        __nv_bfloat16 h2 = __float2bfloat16(kb2);
        Kh[koff + lane] = h1;
        Kh[koff + lane + 32] = h2;
        Kl[koff + lane] = __float2bfloat16(ka - __bfloat162float(h1));
        Kl[koff + lane + 32] = __float2bfloat16(kb2 - __bfloat162float(h2));
    }
    size_t voff = ((size_t)bh * HD) * KVLEN + t;
    {
        __nv_bfloat16 h1 = __float2bfloat16(v1);
        __nv_bfloat16 h2 = __float2bfloat16(v2);
        Vth[voff + (size_t)lane * KVLEN] = h1;
        Vth[voff + (size_t)(lane + 32) * KVLEN] = h2;
        Vtl[voff + (size_t)lane * KVLEN] = __float2bfloat16(v1 - __bfloat162float(h1));
        Vtl[voff + (size_t)(lane + 32) * KVLEN] = __float2bfloat16(v2 - __bfloat162float(h2));
    }
}

// ---------------- cached tokens: copy + rope + split ----------------
__global__ __launch_bounds__(128)
void cache_kernel(const float* __restrict__ cached,
                  __nv_bfloat16* __restrict__ Kh, __nv_bfloat16* __restrict__ Kl,
                  __nv_bfloat16* __restrict__ Vth, __nv_bfloat16* __restrict__ Vtl,
                  float* __restrict__ kv_out) {
    int w = blockIdx.x * 4 + (threadIdx.x >> 5);
    int lane = threadIdx.x & 31;
    int h = w % NH;
    int bt = w / NH;
    int b = bt / CACHE_T;
    int t = bt % CACHE_T;

    size_t src = ((((size_t)b * CACHE_T + t) * 2 + 0) * NH + h) * HD;
    float k1 = cached[src + lane], k2 = cached[src + lane + 32];
    float v1 = cached[src + NH * HD + lane], v2 = cached[src + NH * HD + lane + 32];

    size_t dst = ((((size_t)b * KVLEN + t) * 2 + 0) * NH + h) * HD;
    kv_out[dst + lane] = k1;
    kv_out[dst + lane + 32] = k2;
    kv_out[dst + NH * HD + lane] = v1;
    kv_out[dst + NH * HD + lane + 32] = v2;

    float inv = 1.0f / powf(10000.0f, (float)lane / 32.0f);
    float ang = (float)t * inv;
    float c = cosf(ang), s = sinf(ang);
    float ka = k1 * c - k2 * s;
    float kb2 = k2 * c + k1 * s;

    int bh = b * NH + h;
    size_t koff = ((size_t)bh * KVLEN + t) * HD;
    {
        __nv_bfloat16 h1 = __float2bfloat16(ka);
        __nv_bfloat16 h2 = __float2bfloat16(kb2);
        Kh[koff + lane] = h1;
        Kh[koff + lane + 32] = h2;
        Kl[koff + lane] = __float2bfloat16(ka - __bfloat162float(h1));
        Kl[koff + lane + 32] = __float2bfloat16(kb2 - __bfloat162float(h2));
    }
    size_t voff = ((size_t)bh * HD) * KVLEN + t;
    {
        __nv_bfloat16 h1 = __float2bfloat16(v1);
        __nv_bfloat16 h2 = __float2bfloat16(v2);
        Vth[voff + (size_t)lane * KVLEN] = h1;
        Vth[voff + (size_t)(lane + 32) * KVLEN] = h2;
        Vtl[voff + (size_t)lane * KVLEN] = __float2bfloat16(v1 - __bfloat162float(h1));
        Vtl[voff + (size_t)(lane + 32) * KVLEN] = __float2bfloat16(v2 - __bfloat162float(h2));
    }
}

// ---------------- attention: MMA flash, 64 q-rows/block, 64-key chunks ----------------
#define AT_STAGE 32768
__global__ __launch_bounds__(128)
void attn_mma(const __nv_bfloat16* __restrict__ Qh, const __nv_bfloat16* __restrict__ Ql,
              const __nv_bfloat16* __restrict__ Kh, const __nv_bfloat16* __restrict__ Kl,
              const __nv_bfloat16* __restrict__ Vth, const __nv_bfloat16* __restrict__ Vtl,
              __nv_bfloat16* __restrict__ OA2) {
    extern __shared__ __align__(16) unsigned char dsm[];
    uint32_t sbase = smem_u32(dsm);
    uint32_t qarea = sbase + 2 * AT_STAGE;

    int tid = threadIdx.x, lane = tid & 31, wid = tid >> 5;
    int bh = blockIdx.y;
    int b = bh / NH, h = bh % NH;
    int q0 = blockIdx.x * 64;

    size_t qoff = ((size_t)bh * SEQ + q0) * HD;
    size_t koff = (size_t)bh * KVLEN * HD;
    size_t voff = (size_t)bh * HD * KVLEN;

    int lr = tid >> 1;
    int lc4 = (tid & 1) * 4;

    {
        const __nv_bfloat16* qhg = Qh + qoff + lr * HD;
        const __nv_bfloat16* qlg = Ql + qoff + lr * HD;
        #pragma unroll
        for (int j = 0; j < 4; j++) {
            int ch = lc4 + j;
            uint32_t phys = (uint32_t)((ch ^ (lr & 7)) * 16);
            cpasync16(qarea + lr * 128 + phys, qhg + ch * 8);
            cpasync16(qarea + 8192 + lr * 128 + phys, qlg + ch * 8);
        }
        cpcommit();
    }

    auto issueKV = [&](int c, int buf) {
        uint32_t dst = sbase + buf * AT_STAGE + lr * 128;
        const __nv_bfloat16* khg = Kh + koff + (size_t)(c * 64 + lr) * HD;
        const __nv_bfloat16* klg = Kl + koff + (size_t)(c * 64 + lr) * HD;
        const __nv_bfloat16* vhg = Vth + voff + (size_t)lr * KVLEN + c * 64;
        const __nv_bfloat16* vlg = Vtl + voff + (size_t)lr * KVLEN + c * 64;
        #pragma unroll
        for (int j = 0; j < 4; j++) {
            int ch = lc4 + j;
            uint32_t phys = (uint32_t)((ch ^ (lr & 7)) * 16);
            cpasync16(dst + phys, khg + ch * 8);
            cpasync16(dst + 8192 + phys, klg + ch * 8);
            cpasync16(dst + 16384 + phys, vhg + ch * 8);
            cpasync16(dst + 24576 + phys, vlg + ch * 8);
        }
        cpcommit();
    };

    issueKV(0, 0);
    CP_WAIT(1);
    __syncthreads();

    int rA = lane & 15, kq = lane >> 4;
    int qrow = wid * 16 + rA;
    int qs = qrow & 7;
    uint32_t qfh[4][4], qfl[4][4];
    #pragma unroll
    for (int kt = 0; kt < 4; kt++) {
        uint32_t phys = (uint32_t)(((kt * 2 + kq) ^ qs) * 16);
        ldmx4(qfh[kt], qarea + qrow * 128 + phys);
        ldmx4(qfl[kt], qarea + 8192 + qrow * 128 + phys);
    }

    int gq = lane >> 2, tg = lane & 3;
    float m0 = -1e30f, m1 = -1e30f, l0 = 0.f, l1 = 0.f;
    float O[8][4];
    #pragma unroll
    for (int nt = 0; nt < 8; nt++)
        #pragma unroll
        for (int i = 0; i < 4; i++) O[nt][i] = 0.f;

    const int NCH = KVLEN / 64;
    for (int c = 0; c < NCH; c++) {
        if (c + 1 < NCH) { issueKV(c + 1, (c + 1) & 1); CP_WAIT(1); }
        else { CP_WAIT(0); }
        __syncthreads();

        uint32_t bufK = sbase + (c & 1) * AT_STAGE;
        uint32_t bufV = bufK + 16384;

        float S[8][4];
        #pragma unroll
        for (int nt = 0; nt < 8; nt++)
            #pragma unroll
            for (int i = 0; i < 4; i++) S[nt][i] = 0.f;

        #pragma unroll
        for (int kt = 0; kt < 4; kt++) {
            uint32_t kfh[4][4], kfl[4][4];
            #pragma unroll
            for (int g2 = 0; g2 < 4; g2++) {
                int krow = g2 * 16 + rA;
                uint32_t phys = (uint32_t)(((kt * 2 + kq) ^ (krow & 7)) * 16);
                ldmx4(kfh[g2], bufK + krow * 128 + phys);
                ldmx4(kfl[g2], bufK + 8192 + krow * 128 + phys);
            }
            #pragma unroll
            for (int g2 = 0; g2 < 4; g2++)
                #pragma unroll
                for (int hf = 0; hf < 2; hf++) {
                    int nt = 2 * g2 + hf;
                    mma16816(S[nt], qfh[kt], kfh[g2][hf], kfh[g2][hf + 2]);
                    mma16816(S[nt], qfh[kt], kfl[g2][hf], kfl[g2][hf + 2]);
                    mma16816(S[nt], qfl[kt], kfh[g2][hf], kfh[g2][hf + 2]);
                }
        }

        float mx0 = -1e30f, mx1 = -1e30f;
        #pragma unroll
        for (int nt = 0; nt < 8; nt++) {
            mx0 = fmaxf(mx0, fmaxf(S[nt][0], S[nt][1]));
            mx1 = fmaxf(mx1, fmaxf(S[nt][2], S[nt][3]));
        }
        mx0 = fmaxf(mx0, __shfl_xor_sync(0xffffffffu, mx0, 1));
        mx0 = fmaxf(mx0, __shfl_xor_sync(0xffffffffu, mx0, 2));
        mx1 = fmaxf(mx1, __shfl_xor_sync(0xffffffffu, mx1, 1));
        mx1 = fmaxf(mx1, __shfl_xor_sync(0xffffffffu, mx1, 2));
        float nm0 = fmaxf(m0, mx0), nm1 = fmaxf(m1, mx1);
        float a0 = __expf(m0 - nm0), a1 = __expf(m1 - nm1);

        float rs0 = 0.f, rs1 = 0.f;
        #pragma unroll
        for (int nt = 0; nt < 8; nt++) {
            S[nt][0] = __expf(S[nt][0] - nm0);
            S[nt][1] = __expf(S[nt][1] - nm0);
            S[nt][2] = __expf(S[nt][2] - nm1);
            S[nt][3] = __expf(S[nt][3] - nm1);
            rs0 += S[nt][0] + S[nt][1];
            rs1 += S[nt][2] + S[nt][3];
        }
        rs0 += __shfl_xor_sync(0xffffffffu, rs0, 1);
        rs0 += __shfl_xor_sync(0xffffffffu, rs0, 2);
        rs1 += __shfl_xor_sync(0xffffffffu, rs1, 1);
        rs1 += __shfl_xor_sync(0xffffffffu, rs1, 2);
        l0 = l0 * a0 + rs0;
        l1 = l1 * a1 + rs1;
        m0 = nm0; m1 = nm1;
        #pragma unroll
        for (int nt = 0; nt < 8; nt++) {
            O[nt][0] *= a0; O[nt][1] *= a0;
            O[nt][2] *= a1; O[nt][3] *= a1;
        }

        #pragma unroll
        for (int kt = 0; kt < 4; kt++) {
            uint32_t ah[4], al[4];
            splitpair(S[2 * kt][0], S[2 * kt][1], ah[0], al[0]);
            splitpair(S[2 * kt][2], S[2 * kt][3], ah[1], al[1]);
            splitpair(S[2 * kt + 1][0], S[2 * kt + 1][1], ah[2], al[2]);
            splitpair(S[2 * kt + 1][2], S[2 * kt + 1][3], ah[3], al[3]);
            uint32_t vfh[4][4], vfl[4][4];
            #pragma unroll
            for (int g2 = 0; g2 < 4; g2++) {
                int vrow = g2 * 16 + rA;
                uint32_t phys = (uint32_t)(((kt * 2 + kq) ^ (vrow & 7)) * 16);
                ldmx4(vfh[g2], bufV + vrow * 128 + phys);
                ldmx4(vfl[g2], bufV + 8192 + vrow * 128 + phys);
            }
            #pragma unroll
            for (int g2 = 0; g2 < 4; g2++)
                #pragma unroll
                for (int hf = 0; hf < 2; hf++) {
                    int nt = 2 * g2 + hf;
                    mma16816(O[nt], ah, vfh[g2][hf], vfh[g2][hf + 2]);
                    mma16816(O[nt], ah, vfl[g2][hf], vfl[g2][hf + 2]);
                    mma16816(O[nt], al, vfh[g2][hf], vfh[g2][hf + 2]);
                }
        }
        __syncthreads();
    }

    float inv0 = 1.0f / l0, inv1 = 1.0f / l1;
    int r0 = q0 + wid * 16 + gq;
    size_t tok0 = (size_t)(b * SEQ + r0);
    size_t tok1 = tok0 + 8;
    #pragma unroll
    for (int nt = 0; nt < 8; nt++) {
        int col = h * HD + nt * 8 + 2 * tg;
        uint32_t hi, lo;
        splitpair(O[nt][0] * inv0, O[nt][1] * inv0, hi, lo);
        *(uint32_t*)&OA2[tok0 * (2 * DM) + col] = hi;
        *(uint32_t*)&OA2[tok0 * (2 * DM) + DM + col] = lo;
        splitpair(O[nt][2] * inv1, O[nt][3] * inv1, hi, lo);
        *(uint32_t*)&OA2[tok1 * (2 * DM) + col] = hi;
        *(uint32_t*)&OA2[tok1 * (2 * DM) + DM + col] = lo;
    }
}

// ---------------- GLU ----------------
__global__ void glu_kernel(const float* __restrict__ in, float* __restrict__ out) {
    int i = blockIdx.x * blockDim.x + threadIdx.x;
    if (i >= NTOK * DM) return;
    int r = i / DM, c = i % DM;
    float a = in[(size_t)r * (2 * DM) + c];
    float bb = in[(size_t)r * (2 * DM) + DM + c];
    out[i] = a * sigmoidf_(bb);
}

// ---------------- depthwise conv ----------------
__global__ void dwconv_kernel(const float* __restrict__ in,
                              const float* __restrict__ w,
                              const float* __restrict__ bias,
                              float* __restrict__ out) {
    int i = blockIdx.x * blockDim.x + threadIdx.x;
    if (i >= NTOK * DM) return;
    int c = i % DM;
    int pos = i / DM;
    int n = pos % SEQ;
    int b = pos / SEQ;
    float acc = bias[c];
    #pragma unroll
    for (int k = 0; k < KSZ; k++) {
        int nn = n - (KSZ / 2) + k;
        if (nn >= 0 && nn < SEQ)
            acc = fmaf(in[((size_t)b * SEQ + nn) * DM + c], w[c * KSZ + k], acc);
    }
    out[i] = acc;
}

// ---------------- batchnorm stats ----------------
__global__ void bnstats_kernel(const float* __restrict__ in,
                               float* __restrict__ mean, float* __restrict__ var) {
    int c = blockIdx.x;
    float s = 0.f, ss = 0.f;
    for (int r = threadIdx.x; r < NTOK; r += blockDim.x) {
        float v = in[(size_t)r * DM + c];
        s += v;
        ss += v * v;
    }
    #pragma unroll
    for (int o = 16; o > 0; o >>= 1) {
        s += __shfl_xor_sync(0xffffffffu, s, o);
        ss += __shfl_xor_sync(0xffffffffu, ss, o);
    }
    __shared__ float rs[8], rss[8];
    if ((threadIdx.x & 31) == 0) {
        rs[threadIdx.x >> 5] = s;
        rss[threadIdx.x >> 5] = ss;
    }
    __syncthreads();
    if (threadIdx.x == 0) {
        float ts = 0.f, tss = 0.f;
        #pragma unroll
        for (int i = 0; i < 8; i++) { ts += rs[i]; tss += rss[i]; }
        float m = ts / (float)NTOK;
        mean[c] = m;
        var[c] = tss / (float)NTOK - m * m;
    }
}

// ---------------- bn apply + swish -> bf16 hi|lo ----------------
__global__ void bnapply_bf16_kernel(const float* __restrict__ in,
                                    const float* __restrict__ mean, const float* __restrict__ var,
                                    const float* __restrict__ g, const float* __restrict__ be,
                                    __nv_bfloat16* __restrict__ out) {
    int i = blockIdx.x * blockDim.x + threadIdx.x;
    if (i >= NTOK * DM) return;
    int r = i / DM, c = i % DM;
    float y = (in[i] - mean[c]) * rsqrtf(var[c] + EPSF) * g[c] + be[c];
    y = y * sigmoidf_(y);
    __nv_bfloat16 h = __float2bfloat16(y);
    out[(size_t)r * (2 * DM) + c] = h;
    out[(size_t)r * (2 * DM) + DM + c] = __float2bfloat16(y - __bfloat162float(h));
}

// ---------------- host-side helpers ----------------
static __nv_bfloat16* s_b2 = nullptr;

static void tc_gemm(const __nv_bfloat16* A2, const float* W, void* C,
                    int M, int N, int K,
                    const float* bias, const float* res, float scale, int act,
                    int out_bf16) {
    convB_kernel<<<dim3(K / 32, N / 32), dim3(32, 8)>>>(W, s_b2, K, N);
    hgemm_mma<<<dim3(N / 128, M / 128), 256, 98304>>>(A2, s_b2, C, M, N, K,
                                                      bias, res, scale, act, out_bf16);
}

extern "C" void kernel_launch(void* const* d_in, const int* in_sizes, int n_in,
                              void* d_out, int out_size) {
    (void)in_sizes; (void)n_in; (void)out_size;
    const float* x          = (const float*)d_in[0];
    const float* cached_kv  = (const float*)d_in[4];
    const float* ff1_norm_w = (const float*)d_in[5];
    const float* ff1_w1     = (const float*)d_in[6];
    const float* ff1_b1     = (const float*)d_in[7];
    const float* ff1_w2     = (const float*)d_in[8];
    const float* ff1_b2     = (const float*)d_in[9];
    const float* attn_norm_w= (const float*)d_in[10];
    const float* qkv_w      = (const float*)d_in[11];
    const float* out_w      = (const float*)d_in[12];
    const float* q_norm_w   = (const float*)d_in[13];
    const float* k_norm_w   = (const float*)d_in[14];
    const float* conv_norm_w= (const float*)d_in[15];
    const float* pw1_w      = (const float*)d_in[16];
    const float* pw1_b      = (const float*)d_in[17];
    const float* dw_w       = (const float*)d_in[18];
    const float* dw_b       = (const float*)d_in[19];
    const float* bn_g       = (const float*)d_in[20];
    const float* bn_b       = (const float*)d_in[21];
    const float* pw2_w      = (const float*)d_in[22];
    const float* pw2_b      = (const float*)d_in[23];
    const float* ff2_norm_w = (const float*)d_in[24];
    const float* ff2_w1     = (const float*)d_in[25];
    const float* ff2_b1     = (const float*)d_in[26];
    const float* ff2_w2     = (const float*)d_in[27];
    const float* ff2_b2     = (const float*)d_in[28];
    const float* out_norm_w = (const float*)d_in[29];

    float* out_x  = (float*)d_out;
    float* out_kv = out_x + (size_t)NTOK * DM;

    float *gH, *gX1, *gX2, *gQKV, *gT, *gC, *gM, *gV;
    __nv_bfloat16 *gA2, *gAH, *gQh, *gQl, *gKh, *gKl, *gVth, *gVtl;
    cudaGetSymbolAddress((void**)&gH,   g_h);
    cudaGetSymbolAddress((void**)&gX1,  g_x1);
    cudaGetSymbolAddress((void**)&gX2,  g_x2);
    cudaGetSymbolAddress((void**)&gQKV, g_qkv);
    cudaGetSymbolAddress((void**)&gT,   g_tmp);
    cudaGetSymbolAddress((void**)&gC,   g_conv);
    cudaGetSymbolAddress((void**)&gM,   g_mean);
    cudaGetSymbolAddress((void**)&gV,   g_var);
    cudaGetSymbolAddress((void**)&gA2,  g_a2);
    cudaGetSymbolAddress((void**)&gAH,  g_ah);
    cudaGetSymbolAddress((void**)&s_b2, g_b2);
    cudaGetSymbolAddress((void**)&gQh,  g_qh);
    cudaGetSymbolAddress((void**)&gQl,  g_ql);
    cudaGetSymbolAddress((void**)&gKh,  g_kh);
    cudaGetSymbolAddress((void**)&gKl,  g_kl);
    cudaGetSymbolAddress((void**)&gVth, g_vth);
    cudaGetSymbolAddress((void**)&gVtl, g_vtl);

    cudaFuncSetAttribute(hgemm_mma, cudaFuncAttributeMaxDynamicSharedMemorySize, 98304);
    cudaFuncSetAttribute(attn_mma, cudaFuncAttributeMaxDynamicSharedMemorySize, 81920);

    const int EW_BLOCKS = (NTOK * DM + 255) / 256;

    // ---- FF1 ----
    rmsnorm_bf16_kernel<<<NTOK, 256>>>(x, ff1_norm_w, gA2);
    tc_gemm(gA2, ff1_w1, gAH, NTOK, FFD, DM, ff1_b1, nullptr, 1.0f, 1, 1);
    tc_gemm(gAH, ff1_w2, gX1, NTOK, DM, FFD, ff1_b2, x, 0.5f, 0, 0);

    // ---- Attention ----
    rmsnorm_bf16_kernel<<<NTOK, 256>>>(gX1, attn_norm_w, gA2);
    tc_gemm(gA2, qkv_w, gQKV, NTOK, 3 * NH * HD, DM, nullptr, nullptr, 1.0f, 0, 0);
    qkv_post_kernel<<<NTOK * NH / 4, 128>>>(gQKV, q_norm_w, k_norm_w,
                                            gQh, gQl, gKh, gKl, gVth, gVtl, out_kv);
    cache_kernel<<<BSZ * CACHE_T * NH / 4, 128>>>(cached_kv, gKh, gKl, gVth, gVtl, out_kv);
    attn_mma<<<dim3(SEQ / 64, BSZ * NH), 128, 81920>>>(gQh, gQl, gKh, gKl, gVth, gVtl, gA2);
    tc_gemm(gA2, out_w, gX2, NTOK, DM, DM, nullptr, gX1, 1.0f, 0, 0);

    // ---- Conv module ----
    rmsnorm_bf16_kernel<<<NTOK, 256>>>(gX2, conv_norm_w, gA2);
    tc_gemm(gA2, pw1_w, gH, NTOK, 2 * DM, DM, pw1_b, nullptr, 1.0f, 0, 0);
    glu_kernel<<<EW_BLOCKS, 256>>>(gH, gT);
    dwconv_kernel<<<EW_BLOCKS, 256>>>(gT, dw_w, dw_b, gC);
    bnstats_kernel<<<DM, 256>>>(gC, gM, gV);
    bnapply_bf16_kernel<<<EW_BLOCKS, 256>>>(gC, gM, gV, bn_g, bn_b, gA2);
    tc_gemm(gA2, pw2_w, gX1, NTOK, DM, DM, pw2_b, nullptr, 1.0f, 0, 0);

    // ---- FF2 ----
    rmsnorm_bf16_kernel<<<NTOK, 256>>>(gX1, ff2_norm_w, gA2);
    tc_gemm(gA2, ff2_w1, gAH, NTOK, FFD, DM, ff2_b1, nullptr, 1.0f, 1, 1);
    tc_gemm(gAH, ff2_w2, gX2, NTOK, DM, FFD, ff2_b2, gX1, 0.5f, 0, 0);

    // ---- final norm ----
    rmsnorm_kernel<<<NTOK, 256>>>(gX2, out_norm_w, out_x);
}

// round 8
// speedup vs baseline: 2.3923x; 1.1899x over previous
#include <cuda_runtime.h>
#include <cuda_bf16.h>
#include <cuda_fp16.h>
#include <math.h>
#include <stdint.h>

// ---------------- problem constants ----------------
#define BSZ      2
#define SEQ      2048
#define NTOK     4096          // B*N
#define CACHE_T  512
#define KVLEN    2560
#define DM       768
#define NH       12
#define HD       64
#define FFD      3072
#define KSZ      31
#define EPSF     1e-5f

// ---------------- scratch (device globals; no allocation) ----------------
__device__ __align__(128) float g_h[NTOK * FFD];
__device__ __align__(128) float g_x1[NTOK * DM];
__device__ __align__(128) float g_x2[NTOK * DM];
__device__ __align__(128) float g_qkv[NTOK * 3 * NH * HD];
__device__ __align__(128) float g_tmp[NTOK * DM];
__device__ __align__(128) float g_conv[NTOK * DM];
__device__ float g_mean[DM];
__device__ float g_var[DM];
__device__ __align__(128) __nv_bfloat16 g_a2[NTOK * 2 * DM];             // (M,1536) hi|lo / fp16 reuse
__device__ __align__(128) __nv_bfloat16 g_ah[(size_t)NTOK * 2 * FFD];    // FF intermediate (fp16 reuse)
__device__ __align__(128) __nv_bfloat16 g_b2[(size_t)FFD * 2 * DM];      // weights (N,2K)
__device__ __align__(128) __nv_bfloat16 g_qh[BSZ * NH * SEQ * HD];
__device__ __align__(128) __nv_bfloat16 g_ql[BSZ * NH * SEQ * HD];
__device__ __align__(128) __nv_bfloat16 g_kh[BSZ * NH * KVLEN * HD];
__device__ __align__(128) __nv_bfloat16 g_kl[BSZ * NH * KVLEN * HD];
__device__ __align__(128) __nv_bfloat16 g_vth[BSZ * NH * HD * KVLEN];    // (b,h,d,t)
__device__ __align__(128) __nv_bfloat16 g_vtl[BSZ * NH * HD * KVLEN];

// ---------------- helpers ----------------
__device__ __forceinline__ float gelu_tanh(float x) {
    const float c = 0.7978845608028654f;
    float t = tanhf(c * (x + 0.044715f * x * x * x));
    return 0.5f * x * (1.0f + t);
}
__device__ __forceinline__ float sigmoidf_(float x) {
    return 1.0f / (1.0f + expf(-x));
}
__device__ __forceinline__ uint32_t smem_u32(const void* p) {
    uint32_t a;
    asm("{ .reg .u64 t; cvta.to.shared.u64 t, %1; cvt.u32.u64 %0, t; }"
        : "=r"(a) : "l"(p));
    return a;
}
__device__ __forceinline__ void cpasync16(uint32_t dst, const void* src) {
    asm volatile("cp.async.cg.shared.global [%0], [%1], 16;" :: "r"(dst), "l"(src));
}
__device__ __forceinline__ void cpcommit() {
    asm volatile("cp.async.commit_group;");
}
#define CP_WAIT(N) asm volatile("cp.async.wait_group %0;" :: "n"(N))
__device__ __forceinline__ void ldmx4(uint32_t r[4], uint32_t a) {
    asm volatile("ldmatrix.sync.aligned.m8n8.x4.shared.b16 {%0,%1,%2,%3}, [%4];"
                 : "=r"(r[0]), "=r"(r[1]), "=r"(r[2]), "=r"(r[3]) : "r"(a));
}
__device__ __forceinline__ void mma16816(float c[4], const uint32_t a[4],
                                         uint32_t b0, uint32_t b1) {
    asm volatile(
        "mma.sync.aligned.m16n8k16.row.col.f32.bf16.bf16.f32 "
        "{%0,%1,%2,%3}, {%4,%5,%6,%7}, {%8,%9}, {%0,%1,%2,%3};"
        : "+f"(c[0]), "+f"(c[1]), "+f"(c[2]), "+f"(c[3])
        : "r"(a[0]), "r"(a[1]), "r"(a[2]), "r"(a[3]), "r"(b0), "r"(b1));
}
__device__ __forceinline__ void mma16816h(float c[4], const uint32_t a[4],
                                          uint32_t b0, uint32_t b1) {
    asm volatile(
        "mma.sync.aligned.m16n8k16.row.col.f32.f16.f16.f32 "
        "{%0,%1,%2,%3}, {%4,%5,%6,%7}, {%8,%9}, {%0,%1,%2,%3};"
        : "+f"(c[0]), "+f"(c[1]), "+f"(c[2]), "+f"(c[3])
        : "r"(a[0]), "r"(a[1]), "r"(a[2]), "r"(a[3]), "r"(b0), "r"(b1));
}
__device__ __forceinline__ void splitpair(float x, float y,
                                          uint32_t& hi, uint32_t& lo) {
    __nv_bfloat16 hx = __float2bfloat16(x), hy = __float2bfloat16(y);
    __nv_bfloat162 H; H.x = hx; H.y = hy;
    __nv_bfloat162 L = __floats2bfloat162_rn(x - __bfloat162float(hx),
                                             y - __bfloat162float(hy));
    hi = *reinterpret_cast<uint32_t*>(&H);
    lo = *reinterpret_cast<uint32_t*>(&L);
}

// ---------------- weight conversion: W (K,N) fp32 -> (N,2K) bf16 hi|lo ----------------
__global__ void convB_kernel(const float* __restrict__ W,
                             __nv_bfloat16* __restrict__ out, int K, int N) {
    __shared__ float t[32][33];
    int k0 = blockIdx.x * 32, n0 = blockIdx.y * 32;
    int tx = threadIdx.x, ty = threadIdx.y;   // 32 x 8
    #pragma unroll
    for (int i = ty; i < 32; i += 8)
        t[i][tx] = W[(size_t)(k0 + i) * N + n0 + tx];
    __syncthreads();
    #pragma unroll
    for (int i = ty; i < 32; i += 8) {
        float v = t[tx][i];                   // W[k0+tx][n0+i]
        __nv_bfloat16 h = __float2bfloat16(v);
        float lo = v - __bfloat162float(h);
        size_t b = (size_t)(n0 + i) * (2 * K) + k0 + tx;
        out[b] = h;
        out[b + K] = __float2bfloat16(lo);
    }
}

// ---------------- weight conversion: W (K,N) fp32 -> (N,2K) fp16 hi|lo ----------------
__global__ void convB_fp16_kernel(const float* __restrict__ W,
                                  __half* __restrict__ out, int K, int N) {
    __shared__ float t[32][33];
    int k0 = blockIdx.x * 32, n0 = blockIdx.y * 32;
    int tx = threadIdx.x, ty = threadIdx.y;   // 32 x 8
    #pragma unroll
    for (int i = ty; i < 32; i += 8)
        t[i][tx] = W[(size_t)(k0 + i) * N + n0 + tx];
    __syncthreads();
    #pragma unroll
    for (int i = ty; i < 32; i += 8) {
        float v = t[tx][i];                   // W[k0+tx][n0+i]
        __half h = __float2half(v);
        float lo = v - __half2float(h);
        size_t b = (size_t)(n0 + i) * (2 * K) + k0 + tx;
        out[b] = h;
        out[b + K] = __float2half(lo);
    }
}

// ---------------- warp-MMA GEMM, 128x128x64 tile, 3-stage pipeline ----------------
// 256 threads, 8 warps (2m x 4n), warp tile 64x32.  (R4/R7-proven config.)
// DT=0: bf16 3-pass split, A2 (M,2K) hi|lo.   DT=1: fp16 2-pass, A2 (M,K) single.
// B2 (N,2K) K-major hi|lo (bf16 or fp16 per DT).
// outmode 0: C fp32 (M,N) bias/act/scale/res.
// outmode 1: C bf16 (M,2N) hi|lo.   outmode 2: C fp16 (M,N).
template<int DT>
__global__ __launch_bounds__(256)
void hgemm_mma_t(const uint16_t* __restrict__ A2,
                 const uint16_t* __restrict__ B2,
                 void* __restrict__ Cout, int M, int N, int K,
                 const float* __restrict__ bias, const float* __restrict__ res,
                 float scale, int act, int outmode) {
    extern __shared__ __align__(16) unsigned char dsm[];
    uint32_t sbase = smem_u32(dsm);

    int tid = threadIdx.x;
    int lane = tid & 31;
    int wid = tid >> 5;
    int wm = (wid >> 2) * 64;
    int wn = (wid & 3) * 32;
    int bm = blockIdx.y * 128;
    int bn = blockIdx.x * 128;

    int kpp = K >> 6;
    int nkb = (DT ? 2 : 3) * kpp;

    int lr = tid >> 1;
    int lc = (tid & 1) * 4;
    int sw_r = lr & 7;

    float acc[4][4][4];
    #pragma unroll
    for (int a = 0; a < 4; a++)
        #pragma unroll
        for (int b = 0; b < 4; b++)
            #pragma unroll
            for (int c = 0; c < 4; c++) acc[a][b][c] = 0.f;

    auto issue = [&](int kb, int buf) {
        int p = kb / kpp;
        int off = (kb - p * kpp) << 6;
        int aCol = DT ? off : (((p == 2) ? K : 0) + off);
        int bCol = DT ? (p * K + off) : (((p == 1) ? K : 0) + off);
        size_t astr = DT ? (size_t)K : (size_t)(2 * K);
        const uint16_t* ag = A2 + (size_t)(bm + lr) * astr + aCol + lc * 8;
        const uint16_t* bg = B2 + (size_t)(bn + lr) * (2 * K) + bCol + lc * 8;
        uint32_t abuf = sbase + buf * 32768 + lr * 128;
        uint32_t bbuf = abuf + 16384;
        #pragma unroll
        for (int j = 0; j < 4; j++) {
            uint32_t phys = (uint32_t)((lc + j) ^ sw_r) * 16;
            cpasync16(abuf + phys, ag + j * 8);
            cpasync16(bbuf + phys, bg + j * 8);
        }
        cpcommit();
    };

    issue(0, 0);
    issue(1, 1);

    int rA = lane & 15;
    int kq = lane >> 4;
    int swA = rA & 7;

    for (int kb = 0; kb < nkb; kb++) {
        if (kb + 1 < nkb) { CP_WAIT(1); } else { CP_WAIT(0); }
        __syncthreads();
        if (kb + 2 < nkb) issue(kb + 2, (kb + 2) % 3);

        uint32_t Ab = sbase + (kb % 3) * 32768;
        uint32_t Bb = Ab + 16384;

        #pragma unroll
        for (int ks = 0; ks < 4; ks++) {
            uint32_t phys = (uint32_t)(((ks * 2 + kq) ^ swA) * 16);
            uint32_t af[4][4];
            #pragma unroll
            for (int mt = 0; mt < 4; mt++)
                ldmx4(af[mt], Ab + (uint32_t)(wm + mt * 16 + rA) * 128 + phys);
            uint32_t bf[4][2];
            #pragma unroll
            for (int g = 0; g < 2; g++) {
                uint32_t r[4];
                ldmx4(r, Bb + (uint32_t)(wn + g * 16 + rA) * 128 + phys);
                bf[2 * g][0] = r[0]; bf[2 * g][1] = r[2];
                bf[2 * g + 1][0] = r[1]; bf[2 * g + 1][1] = r[3];
            }
            #pragma unroll
            for (int mt = 0; mt < 4; mt++)
                #pragma unroll
                for (int nt = 0; nt < 4; nt++) {
                    if (DT) mma16816h(acc[mt][nt], af[mt], bf[nt][0], bf[nt][1]);
                    else    mma16816 (acc[mt][nt], af[mt], bf[nt][0], bf[nt][1]);
                }
        }
        // no trailing sync: next iteration's top barrier guards buffer reuse
    }

    int gq = lane >> 2;
    int tg = lane & 3;
    #pragma unroll
    for (int mt = 0; mt < 4; mt++) {
        #pragma unroll
        for (int nt = 0; nt < 4; nt++) {
            int row0 = bm + wm + mt * 16 + gq;
            int col = bn + wn + nt * 8 + 2 * tg;
            float bv0 = bias ? bias[col] : 0.f;
            float bv1 = bias ? bias[col + 1] : 0.f;
            #pragma unroll
            for (int half = 0; half < 2; half++) {
                int row = row0 + half * 8;
                float v0 = acc[mt][nt][2 * half + 0] + bv0;
                float v1 = acc[mt][nt][2 * half + 1] + bv1;
                if (act == 1) { v0 = gelu_tanh(v0); v1 = gelu_tanh(v1); }
                v0 *= scale; v1 *= scale;
                if (outmode == 0) {
                    float* C = (float*)Cout;
                    if (res) {
                        v0 += res[(size_t)row * N + col];
                        v1 += res[(size_t)row * N + col + 1];
                    }
                    *(float2*)&C[(size_t)row * N + col] = make_float2(v0, v1);
                } else if (outmode == 1) {
                    __nv_bfloat16* C2 = (__nv_bfloat16*)Cout;
                    uint32_t hi, lo;
                    splitpair(v0, v1, hi, lo);
                    *(uint32_t*)&C2[(size_t)row * 2 * N + col] = hi;
                    *(uint32_t*)&C2[(size_t)row * 2 * N + N + col] = lo;
                } else {
                    __half* C3 = (__half*)Cout;
                    __half2 hv = __floats2half2_rn(v0, v1);
                    *(uint32_t*)&C3[(size_t)row * N + col] =
                        *reinterpret_cast<uint32_t*>(&hv);
                }
            }
        }
    }
}

// ---------------- rmsnorm fp32 out (final) ----------------
__global__ void rmsnorm_kernel(const float* __restrict__ x,
                               const float* __restrict__ w,
                               float* __restrict__ y) {
    int row = blockIdx.x;
    const float* xr = x + (size_t)row * DM;
    float ss = 0.f;
    for (int i = threadIdx.x; i < DM; i += blockDim.x) {
        float v = xr[i];
        ss += v * v;
    }
    #pragma unroll
    for (int o = 16; o > 0; o >>= 1) ss += __shfl_xor_sync(0xffffffffu, ss, o);
    __shared__ float red[8];
    if ((threadIdx.x & 31) == 0) red[threadIdx.x >> 5] = ss;
    __syncthreads();
    __shared__ float s_r;
    if (threadIdx.x == 0) {
        float t = 0.f;
        #pragma unroll
        for (int i = 0; i < 8; i++) t += red[i];
        s_r = rsqrtf(t / (float)DM + EPSF);
    }
    __syncthreads();
    float r = s_r;
    float* yr = y + (size_t)row * DM;
    for (int i = threadIdx.x; i < DM; i += blockDim.x)
        yr[i] = xr[i] * r * w[i];
}

// ---------------- rmsnorm -> bf16 hi|lo A2 format ----------------
__global__ void rmsnorm_bf16_kernel(const float* __restrict__ x,
                                    const float* __restrict__ w,
                                    __nv_bfloat16* __restrict__ y) {
    int row = blockIdx.x;
    const float* xr = x + (size_t)row * DM;
    float ss = 0.f;
    for (int i = threadIdx.x; i < DM; i += blockDim.x) {
        float v = xr[i];
        ss += v * v;
    }
    #pragma unroll
    for (int o = 16; o > 0; o >>= 1) ss += __shfl_xor_sync(0xffffffffu, ss, o);
    __shared__ float red[8];
    if ((threadIdx.x & 31) == 0) red[threadIdx.x >> 5] = ss;
    __syncthreads();
    __shared__ float s_r;
    if (threadIdx.x == 0) {
        float t = 0.f;
        #pragma unroll
        for (int i = 0; i < 8; i++) t += red[i];
        s_r = rsqrtf(t / (float)DM + EPSF);
    }
    __syncthreads();
    float r = s_r;
    __nv_bfloat16* yr = y + (size_t)row * (2 * DM);
    for (int i = threadIdx.x; i < DM; i += blockDim.x) {
        float v = xr[i] * r * w[i];
        __nv_bfloat16 h = __float2bfloat16(v);
        yr[i] = h;
        yr[DM + i] = __float2bfloat16(v - __bfloat162float(h));
    }
}

// ---------------- rmsnorm -> fp16 single (FF inputs) ----------------
__global__ void rmsnorm_fp16_kernel(const float* __restrict__ x,
                                    const float* __restrict__ w,
                                    __half* __restrict__ y) {
    int row = blockIdx.x;
    const float* xr = x + (size_t)row * DM;
    float ss = 0.f;
    for (int i = threadIdx.x; i < DM; i += blockDim.x) {
        float v = xr[i];
        ss += v * v;
    }
    #pragma unroll
    for (int o = 16; o > 0; o >>= 1) ss += __shfl_xor_sync(0xffffffffu, ss, o);
    __shared__ float red[8];
    if ((threadIdx.x & 31) == 0) red[threadIdx.x >> 5] = ss;
    __syncthreads();
    __shared__ float s_r;
    if (threadIdx.x == 0) {
        float t = 0.f;
        #pragma unroll
        for (int i = 0; i < 8; i++) t += red[i];
        s_r = rsqrtf(t / (float)DM + EPSF);
    }
    __syncthreads();
    float r = s_r;
    __half* yr = y + (size_t)row * DM;
    for (int i = threadIdx.x; i < DM; i += blockDim.x)
        yr[i] = __float2half(xr[i] * r * w[i]);
}

// ---------------- qkv postproc: head rmsnorm + rope + split outputs ----------------
__global__ __launch_bounds__(128)
void qkv_post_kernel(const float* __restrict__ qkv,
                     const float* __restrict__ qnw, const float* __restrict__ knw,
                     __nv_bfloat16* __restrict__ Qh, __nv_bfloat16* __restrict__ Ql,
                     __nv_bfloat16* __restrict__ Kh, __nv_bfloat16* __restrict__ Kl,
                     __nv_bfloat16* __restrict__ Vth, __nv_bfloat16* __restrict__ Vtl,
                     float* __restrict__ kv_out) {
    int w = blockIdx.x * 4 + (threadIdx.x >> 5);
    int lane = threadIdx.x & 31;
    int h = w % NH;
    int tok = w / NH;
    int b = tok / SEQ;
    int n = tok % SEQ;

    const float* base = qkv + (size_t)tok * (3 * NH * HD) + h * (HD * 3);
    float q1 = base[lane * 3 + 0], q2 = base[(lane + 32) * 3 + 0];
    float k1 = base[lane * 3 + 1], k2 = base[(lane + 32) * 3 + 1];
    float v1 = base[lane * 3 + 2], v2 = base[(lane + 32) * 3 + 2];

    float sq = q1 * q1 + q2 * q2;
    #pragma unroll
    for (int o = 16; o > 0; o >>= 1) sq += __shfl_xor_sync(0xffffffffu, sq, o);
    float rq = rsqrtf(sq / 64.f + EPSF);
    q1 *= rq * qnw[lane]; q2 *= rq * qnw[lane + 32];

    float sk = k1 * k1 + k2 * k2;
    #pragma unroll
    for (int o = 16; o > 0; o >>= 1) sk += __shfl_xor_sync(0xffffffffu, sk, o);
    float rk = rsqrtf(sk / 64.f + EPSF);
    k1 *= rk * knw[lane]; k2 *= rk * knw[lane + 32];

    int t = CACHE_T + n;
    size_t kb = ((((size_t)b * KVLEN + t) * 2 + 0) * NH + h) * HD;
    kv_out[kb + lane] = k1;
    kv_out[kb + lane + 32] = k2;
    kv_out[kb + NH * HD + lane] = v1;
    kv_out[kb + NH * HD + lane + 32] = v2;

    float inv = 1.0f / powf(10000.0f, (float)lane / 32.0f);
    float ang = (float)t * inv;
    float c = cosf(ang), s = sinf(ang);

    int bh = b * NH + h;
    float qa = (q1 * c - q2 * s) * 0.125f;
    float qb2 = (q2 * c + q1 * s) * 0.125f;
    size_t qoff = ((size_t)bh * SEQ + n) * HD;
    {
        __nv_bfloat16 h1 = __float2bfloat16(qa);
        __nv_bfloat16 h2 = __float2bfloat16(qb2);
        Qh[qoff + lane] = h1;
        Qh[qoff + lane + 32] = h2;
        Ql[qoff + lane] = __float2bfloat16(qa - __bfloat162float(h1));
        Ql[qoff + lane + 32] = __float2bfloat16(qb2 - __bfloat162float(h2));
    }
    float ka = k1 * c - k2 * s;
    float kb2 = k2 * c + k1 * s;
    size_t koff = ((size_t)bh * KVLEN + t) * HD;
    {
        __nv_bfloat16 h1 = __float2bfloat16(ka);
        __nv_bfloat16 h2 = __float2bfloat16(kb2);
        Kh[koff + lane] = h1;
        Kh[koff + lane + 32] = h2;
        Kl[koff + lane] = __float2bfloat16(ka - __bfloat162float(h1));
        Kl[koff + lane + 32] = __float2bfloat16(kb2 - __bfloat162float(h2));
    }
    size_t voff = ((size_t)bh * HD) * KVLEN + t;
    {
        __nv_bfloat16 h1 = __float2bfloat16(v1);
        __nv_bfloat16 h2 = __float2bfloat16(v2);
        Vth[voff + (size_t)lane * KVLEN] = h1;
        Vth[voff + (size_t)(lane + 32) * KVLEN] = h2;
        Vtl[voff + (size_t)lane * KVLEN] = __float2bfloat16(v1 - __bfloat162float(h1));
        Vtl[voff + (size_t)(lane + 32) * KVLEN] = __float2bfloat16(v2 - __bfloat162float(h2));
    }
}

// ---------------- cached tokens: copy + rope + split ----------------
__global__ __launch_bounds__(128)
void cache_kernel(const float* __restrict__ cached,
                  __nv_bfloat16* __restrict__ Kh, __nv_bfloat16* __restrict__ Kl,
                  __nv_bfloat16* __restrict__ Vth, __nv_bfloat16* __restrict__ Vtl,
                  float* __restrict__ kv_out) {
    int w = blockIdx.x * 4 + (threadIdx.x >> 5);
    int lane = threadIdx.x & 31;
    int h = w % NH;
    int bt = w / NH;
    int b = bt / CACHE_T;
    int t = bt % CACHE_T;

    size_t src = ((((size_t)b * CACHE_T + t) * 2 + 0) * NH + h) * HD;
    float k1 = cached[src + lane], k2 = cached[src + lane + 32];
    float v1 = cached[src + NH * HD + lane], v2 = cached[src + NH * HD + lane + 32];

    size_t dst = ((((size_t)b * KVLEN + t) * 2 + 0) * NH + h) * HD;
    kv_out[dst + lane] = k1;
    kv_out[dst + lane + 32] = k2;
    kv_out[dst + NH * HD + lane] = v1;
    kv_out[dst + NH * HD + lane + 32] = v2;

    float inv = 1.0f / powf(10000.0f, (float)lane / 32.0f);
    float ang = (float)t * inv;
    float c = cosf(ang), s = sinf(ang);
    float ka = k1 * c - k2 * s;
    float kb2 = k2 * c + k1 * s;

    int bh = b * NH + h;
    size_t koff = ((size_t)bh * KVLEN + t) * HD;
    {
        __nv_bfloat16 h1 = __float2bfloat16(ka);
        __nv_bfloat16 h2 = __float2bfloat16(kb2);
        Kh[koff + lane] = h1;
        Kh[koff + lane + 32] = h2;
        Kl[koff + lane] = __float2bfloat16(ka - __bfloat162float(h1));
        Kl[koff + lane + 32] = __float2bfloat16(kb2 - __bfloat162float(h2));
    }
    size_t voff = ((size_t)bh * HD) * KVLEN + t;
    {
        __nv_bfloat16 h1 = __float2bfloat16(v1);
        __nv_bfloat16 h2 = __float2bfloat16(v2);
        Vth[voff + (size_t)lane * KVLEN] = h1;
        Vth[voff + (size_t)(lane + 32) * KVLEN] = h2;
        Vtl[voff + (size_t)lane * KVLEN] = __float2bfloat16(v1 - __bfloat162float(h1));
        Vtl[voff + (size_t)(lane + 32) * KVLEN] = __float2bfloat16(v2 - __bfloat162float(h2));
    }
}

// ---------------- attention: MMA flash, 64 q-rows/block, 64-key chunks ----------------
#define AT_STAGE 32768
__global__ __launch_bounds__(128)
void attn_mma(const __nv_bfloat16* __restrict__ Qh, const __nv_bfloat16* __restrict__ Ql,
              const __nv_bfloat16* __restrict__ Kh, const __nv_bfloat16* __restrict__ Kl,
              const __nv_bfloat16* __restrict__ Vth, const __nv_bfloat16* __restrict__ Vtl,
              __nv_bfloat16* __restrict__ OA2) {
    extern __shared__ __align__(16) unsigned char dsm[];
    uint32_t sbase = smem_u32(dsm);
    uint32_t qarea = sbase + 2 * AT_STAGE;

    int tid = threadIdx.x, lane = tid & 31, wid = tid >> 5;
    int bh = blockIdx.y;
    int b = bh / NH, h = bh % NH;
    int q0 = blockIdx.x * 64;

    size_t qoff = ((size_t)bh * SEQ + q0) * HD;
    size_t koff = (size_t)bh * KVLEN * HD;
    size_t voff = (size_t)bh * HD * KVLEN;

    int lr = tid >> 1;
    int lc4 = (tid & 1) * 4;

    {
        const __nv_bfloat16* qhg = Qh + qoff + lr * HD;
        const __nv_bfloat16* qlg = Ql + qoff + lr * HD;
        #pragma unroll
        for (int j = 0; j < 4; j++) {
            int ch = lc4 + j;
            uint32_t phys = (uint32_t)((ch ^ (lr & 7)) * 16);
            cpasync16(qarea + lr * 128 + phys, qhg + ch * 8);
            cpasync16(qarea + 8192 + lr * 128 + phys, qlg + ch * 8);
        }
        cpcommit();
    }

    auto issueKV = [&](int c, int buf) {
        uint32_t dst = sbase + buf * AT_STAGE + lr * 128;
        const __nv_bfloat16* khg = Kh + koff + (size_t)(c * 64 + lr) * HD;
        const __nv_bfloat16* klg = Kl + koff + (size_t)(c * 64 + lr) * HD;
        const __nv_bfloat16* vhg = Vth + voff + (size_t)lr * KVLEN + c * 64;
        const __nv_bfloat16* vlg = Vtl + voff + (size_t)lr * KVLEN + c * 64;
        #pragma unroll
        for (int j = 0; j < 4; j++) {
            int ch = lc4 + j;
            uint32_t phys = (uint32_t)((ch ^ (lr & 7)) * 16);
            cpasync16(dst + phys, khg + ch * 8);
            cpasync16(dst + 8192 + phys, klg + ch * 8);
            cpasync16(dst + 16384 + phys, vhg + ch * 8);
            cpasync16(dst + 24576 + phys, vlg + ch * 8);
        }
        cpcommit();
    };

    issueKV(0, 0);
    CP_WAIT(1);
    __syncthreads();

    int rA = lane & 15, kq = lane >> 4;
    int qrow = wid * 16 + rA;
    int qs = qrow & 7;
    uint32_t qfh[4][4], qfl[4][4];
    #pragma unroll
    for (int kt = 0; kt < 4; kt++) {
        uint32_t phys = (uint32_t)(((kt * 2 + kq) ^ qs) * 16);
        ldmx4(qfh[kt], qarea + qrow * 128 + phys);
        ldmx4(qfl[kt], qarea + 8192 + qrow * 128 + phys);
    }

    int gq = lane >> 2, tg = lane & 3;
    float m0 = -1e30f, m1 = -1e30f, l0 = 0.f, l1 = 0.f;
    float O[8][4];
    #pragma unroll
    for (int nt = 0; nt < 8; nt++)
        #pragma unroll
        for (int i = 0; i < 4; i++) O[nt][i] = 0.f;

    const int NCH = KVLEN / 64;
    for (int c = 0; c < NCH; c++) {
        if (c + 1 < NCH) { issueKV(c + 1, (c + 1) & 1); CP_WAIT(1); }
        else { CP_WAIT(0); }
        __syncthreads();

        uint32_t bufK = sbase + (c & 1) * AT_STAGE;
        uint32_t bufV = bufK + 16384;

        float S[8][4];
        #pragma unroll
        for (int nt = 0; nt < 8; nt++)
            #pragma unroll
            for (int i = 0; i < 4; i++) S[nt][i] = 0.f;

        #pragma unroll
        for (int kt = 0; kt < 4; kt++) {
            uint32_t kfh[4][4], kfl[4][4];
            #pragma unroll
            for (int g2 = 0; g2 < 4; g2++) {
                int krow = g2 * 16 + rA;
                uint32_t phys = (uint32_t)(((kt * 2 + kq) ^ (krow & 7)) * 16);
                ldmx4(kfh[g2], bufK + krow * 128 + phys);
                ldmx4(kfl[g2], bufK + 8192 + krow * 128 + phys);
            }
            #pragma unroll
            for (int g2 = 0; g2 < 4; g2++)
                #pragma unroll
                for (int hf = 0; hf < 2; hf++) {
                    int nt = 2 * g2 + hf;
                    mma16816(S[nt], qfh[kt], kfh[g2][hf], kfh[g2][hf + 2]);
                    mma16816(S[nt], qfh[kt], kfl[g2][hf], kfl[g2][hf + 2]);
                    mma16816(S[nt], qfl[kt], kfh[g2][hf], kfh[g2][hf + 2]);
                }
        }

        float mx0 = -1e30f, mx1 = -1e30f;
        #pragma unroll
        for (int nt = 0; nt < 8; nt++) {
            mx0 = fmaxf(mx0, fmaxf(S[nt][0], S[nt][1]));
            mx1 = fmaxf(mx1, fmaxf(S[nt][2], S[nt][3]));
        }
        mx0 = fmaxf(mx0, __shfl_xor_sync(0xffffffffu, mx0, 1));
        mx0 = fmaxf(mx0, __shfl_xor_sync(0xffffffffu, mx0, 2));
        mx1 = fmaxf(mx1, __shfl_xor_sync(0xffffffffu, mx1, 1));
        mx1 = fmaxf(mx1, __shfl_xor_sync(0xffffffffu, mx1, 2));
        float nm0 = fmaxf(m0, mx0), nm1 = fmaxf(m1, mx1);
        float a0 = __expf(m0 - nm0), a1 = __expf(m1 - nm1);

        float rs0 = 0.f, rs1 = 0.f;
        #pragma unroll
        for (int nt = 0; nt < 8; nt++) {
            S[nt][0] = __expf(S[nt][0] - nm0);
            S[nt][1] = __expf(S[nt][1] - nm0);
            S[nt][2] = __expf(S[nt][2] - nm1);
            S[nt][3] = __expf(S[nt][3] - nm1);
            rs0 += S[nt][0] + S[nt][1];
            rs1 += S[nt][2] + S[nt][3];
        }
        rs0 += __shfl_xor_sync(0xffffffffu, rs0, 1);
        rs0 += __shfl_xor_sync(0xffffffffu, rs0, 2);
        rs1 += __shfl_xor_sync(0xffffffffu, rs1, 1);
        rs1 += __shfl_xor_sync(0xffffffffu, rs1, 2);
        l0 = l0 * a0 + rs0;
        l1 = l1 * a1 + rs1;
        m0 = nm0; m1 = nm1;
        #pragma unroll
        for (int nt = 0; nt < 8; nt++) {
            O[nt][0] *= a0; O[nt][1] *= a0;
            O[nt][2] *= a1; O[nt][3] *= a1;
        }

        #pragma unroll
        for (int kt = 0; kt < 4; kt++) {
            uint32_t ah[4], al[4];
            splitpair(S[2 * kt][0], S[2 * kt][1], ah[0], al[0]);
            splitpair(S[2 * kt][2], S[2 * kt][3], ah[1], al[1]);
            splitpair(S[2 * kt + 1][0], S[2 * kt + 1][1], ah[2], al[2]);
            splitpair(S[2 * kt + 1][2], S[2 * kt + 1][3], ah[3], al[3]);
            uint32_t vfh[4][4], vfl[4][4];
            #pragma unroll
            for (int g2 = 0; g2 < 4; g2++) {
                int vrow = g2 * 16 + rA;
                uint32_t phys = (uint32_t)(((kt * 2 + kq) ^ (vrow & 7)) * 16);
                ldmx4(vfh[g2], bufV + vrow * 128 + phys);
                ldmx4(vfl[g2], bufV + 8192 + vrow * 128 + phys);
            }
            #pragma unroll
            for (int g2 = 0; g2 < 4; g2++)
                #pragma unroll
                for (int hf = 0; hf < 2; hf++) {
                    int nt = 2 * g2 + hf;
                    mma16816(O[nt], ah, vfh[g2][hf], vfh[g2][hf + 2]);
                    mma16816(O[nt], ah, vfl[g2][hf], vfl[g2][hf + 2]);
                    mma16816(O[nt], al, vfh[g2][hf], vfh[g2][hf + 2]);
                }
        }
        __syncthreads();
    }

    float inv0 = 1.0f / l0, inv1 = 1.0f / l1;
    int r0 = q0 + wid * 16 + gq;
    size_t tok0 = (size_t)(b * SEQ + r0);
    size_t tok1 = tok0 + 8;
    #pragma unroll
    for (int nt = 0; nt < 8; nt++) {
        int col = h * HD + nt * 8 + 2 * tg;
        uint32_t hi, lo;
        splitpair(O[nt][0] * inv0, O[nt][1] * inv0, hi, lo);
        *(uint32_t*)&OA2[tok0 * (2 * DM) + col] = hi;
        *(uint32_t*)&OA2[tok0 * (2 * DM) + DM + col] = lo;
        splitpair(O[nt][2] * inv1, O[nt][3] * inv1, hi, lo);
        *(uint32_t*)&OA2[tok1 * (2 * DM) + col] = hi;
        *(uint32_t*)&OA2[tok1 * (2 * DM) + DM + col] = lo;
    }
}

// ---------------- GLU ----------------
__global__ void glu_kernel(const float* __restrict__ in, float* __restrict__ out) {
    int i = blockIdx.x * blockDim.x + threadIdx.x;
    if (i >= NTOK * DM) return;
    int r = i / DM, c = i % DM;
    float a = in[(size_t)r * (2 * DM) + c];
    float bb = in[(size_t)r * (2 * DM) + DM + c];
    out[i] = a * sigmoidf_(bb);
}

// ---------------- depthwise conv ----------------
__global__ void dwconv_kernel(const float* __restrict__ in,
                              const float* __restrict__ w,
                              const float* __restrict__ bias,
                              float* __restrict__ out) {
    int i = blockIdx.x * blockDim.x + threadIdx.x;
    if (i >= NTOK * DM) return;
    int c = i % DM;
    int pos = i / DM;
    int n = pos % SEQ;
    int b = pos / SEQ;
    float acc = bias[c];
    #pragma unroll
    for (int k = 0; k < KSZ; k++) {
        int nn = n - (KSZ / 2) + k;
        if (nn >= 0 && nn < SEQ)
            acc = fmaf(in[((size_t)b * SEQ + nn) * DM + c], w[c * KSZ + k], acc);
    }
    out[i] = acc;
}

// ---------------- batchnorm stats ----------------
__global__ void bnstats_kernel(const float* __restrict__ in,
                               float* __restrict__ mean, float* __restrict__ var) {
    int c = blockIdx.x;
    float s = 0.f, ss = 0.f;
    for (int r = threadIdx.x; r < NTOK; r += blockDim.x) {
        float v = in[(size_t)r * DM + c];
        s += v;
        ss += v * v;
    }
    #pragma unroll
    for (int o = 16; o > 0; o >>= 1) {
        s += __shfl_xor_sync(0xffffffffu, s, o);
        ss += __shfl_xor_sync(0xffffffffu, ss, o);
    }
    __shared__ float rs[8], rss[8];
    if ((threadIdx.x & 31) == 0) {
        rs[threadIdx.x >> 5] = s;
        rss[threadIdx.x >> 5] = ss;
    }
    __syncthreads();
    if (threadIdx.x == 0) {
        float ts = 0.f, tss = 0.f;
        #pragma unroll
        for (int i = 0; i < 8; i++) { ts += rs[i]; tss += rss[i]; }
        float m = ts / (float)NTOK;
        mean[c] = m;
        var[c] = tss / (float)NTOK - m * m;
    }
}

// ---------------- bn apply + swish -> bf16 hi|lo ----------------
__global__ void bnapply_bf16_kernel(const float* __restrict__ in,
                                    const float* __restrict__ mean, const float* __restrict__ var,
                                    const float* __restrict__ g, const float* __restrict__ be,
                                    __nv_bfloat16* __restrict__ out) {
    int i = blockIdx.x * blockDim.x + threadIdx.x;
    if (i >= NTOK * DM) return;
    int r = i / DM, c = i % DM;
    float y = (in[i] - mean[c]) * rsqrtf(var[c] + EPSF) * g[c] + be[c];
    y = y * sigmoidf_(y);
    __nv_bfloat16 h = __float2bfloat16(y);
    out[(size_t)r * (2 * DM) + c] = h;
    out[(size_t)r * (2 * DM) + DM + c] = __float2bfloat16(y - __bfloat162float(h));
}

// ---------------- host-side helpers ----------------
static __nv_bfloat16* s_b2 = nullptr;

static void tc_gemm(const __nv_bfloat16* A2, const float* W, void* C,
                    int M, int N, int K,
                    const float* bias, const float* res, float scale, int act,
                    int outmode) {
    convB_kernel<<<dim3(K / 32, N / 32), dim3(32, 8)>>>(W, s_b2, K, N);
    hgemm_mma_t<0><<<dim3(N / 128, M / 128), 256, 98304>>>(
        (const uint16_t*)A2, (const uint16_t*)s_b2, C, M, N, K,
        bias, res, scale, act, outmode);
}

static void tc_gemm_fp16(const __half* A1, const float* W, void* C,
                         int M, int N, int K,
                         const float* bias, const float* res, float scale, int act,
                         int outmode) {
    convB_fp16_kernel<<<dim3(K / 32, N / 32), dim3(32, 8)>>>(W, (__half*)s_b2, K, N);
    hgemm_mma_t<1><<<dim3(N / 128, M / 128), 256, 98304>>>(
        (const uint16_t*)A1, (const uint16_t*)s_b2, C, M, N, K,
        bias, res, scale, act, outmode);
}

extern "C" void kernel_launch(void* const* d_in, const int* in_sizes, int n_in,
                              void* d_out, int out_size) {
    (void)in_sizes; (void)n_in; (void)out_size;
    const float* x          = (const float*)d_in[0];
    const float* cached_kv  = (const float*)d_in[4];
    const float* ff1_norm_w = (const float*)d_in[5];
    const float* ff1_w1     = (const float*)d_in[6];
    const float* ff1_b1     = (const float*)d_in[7];
    const float* ff1_w2     = (const float*)d_in[8];
    const float* ff1_b2     = (const float*)d_in[9];
    const float* attn_norm_w= (const float*)d_in[10];
    const float* qkv_w      = (const float*)d_in[11];
    const float* out_w      = (const float*)d_in[12];
    const float* q_norm_w   = (const float*)d_in[13];
    const float* k_norm_w   = (const float*)d_in[14];
    const float* conv_norm_w= (const float*)d_in[15];
    const float* pw1_w      = (const float*)d_in[16];
    const float* pw1_b      = (const float*)d_in[17];
    const float* dw_w       = (const float*)d_in[18];
    const float* dw_b       = (const float*)d_in[19];
    const float* bn_g       = (const float*)d_in[20];
    const float* bn_b       = (const float*)d_in[21];
    const float* pw2_w      = (const float*)d_in[22];
    const float* pw2_b      = (const float*)d_in[23];
    const float* ff2_norm_w = (const float*)d_in[24];
    const float* ff2_w1     = (const float*)d_in[25];
    const float* ff2_b1     = (const float*)d_in[26];
    const float* ff2_w2     = (const float*)d_in[27];
    const float* ff2_b2     = (const float*)d_in[28];
    const float* out_norm_w = (const float*)d_in[29];

    float* out_x  = (float*)d_out;
    float* out_kv = out_x + (size_t)NTOK * DM;

    float *gH, *gX1, *gX2, *gQKV, *gT, *gC, *gM, *gV;
    __nv_bfloat16 *gA2, *gAH, *gQh, *gQl, *gKh, *gKl, *gVth, *gVtl;
    cudaGetSymbolAddress((void**)&gH,   g_h);
    cudaGetSymbolAddress((void**)&gX1,  g_x1);
    cudaGetSymbolAddress((void**)&gX2,  g_x2);
    cudaGetSymbolAddress((void**)&gQKV, g_qkv);
    cudaGetSymbolAddress((void**)&gT,   g_tmp);
    cudaGetSymbolAddress((void**)&gC,   g_conv);
    cudaGetSymbolAddress((void**)&gM,   g_mean);
    cudaGetSymbolAddress((void**)&gV,   g_var);
    cudaGetSymbolAddress((void**)&gA2,  g_a2);
    cudaGetSymbolAddress((void**)&gAH,  g_ah);
    cudaGetSymbolAddress((void**)&s_b2, g_b2);
    cudaGetSymbolAddress((void**)&gQh,  g_qh);
    cudaGetSymbolAddress((void**)&gQl,  g_ql);
    cudaGetSymbolAddress((void**)&gKh,  g_kh);
    cudaGetSymbolAddress((void**)&gKl,  g_kl);
    cudaGetSymbolAddress((void**)&gVth, g_vth);
    cudaGetSymbolAddress((void**)&gVtl, g_vtl);

    __half* gF16 = (__half*)gA2;     // fp16 FF input (M, DM)
    __half* gH16 = (__half*)gAH;     // fp16 FF intermediate (M, FFD)

    cudaFuncSetAttribute(hgemm_mma_t<0>, cudaFuncAttributeMaxDynamicSharedMemorySize, 98304);
    cudaFuncSetAttribute(hgemm_mma_t<1>, cudaFuncAttributeMaxDynamicSharedMemorySize, 98304);
    cudaFuncSetAttribute(attn_mma, cudaFuncAttributeMaxDynamicSharedMemorySize, 81920);

    const int EW_BLOCKS = (NTOK * DM + 255) / 256;

    // ---- FF1 (fp16 2-term path) ----
    rmsnorm_fp16_kernel<<<NTOK, 256>>>(x, ff1_norm_w, gF16);
    tc_gemm_fp16(gF16, ff1_w1, gH16, NTOK, FFD, DM, ff1_b1, nullptr, 1.0f, 1, 2);
    tc_gemm_fp16(gH16, ff1_w2, gX1, NTOK, DM, FFD, ff1_b2, x, 0.5f, 0, 0);

    // ---- Attention (bf16 3-term path) ----
    rmsnorm_bf16_kernel<<<NTOK, 256>>>(gX1, attn_norm_w, gA2);
    tc_gemm(gA2, qkv_w, gQKV, NTOK, 3 * NH * HD, DM, nullptr, nullptr, 1.0f, 0, 0);
    qkv_post_kernel<<<NTOK * NH / 4, 128>>>(gQKV, q_norm_w, k_norm_w,
                                            gQh, gQl, gKh, gKl, gVth, gVtl, out_kv);
    cache_kernel<<<BSZ * CACHE_T * NH / 4, 128>>>(cached_kv, gKh, gKl, gVth, gVtl, out_kv);
    attn_mma<<<dim3(SEQ / 64, BSZ * NH), 128, 81920>>>(gQh, gQl, gKh, gKl, gVth, gVtl, gA2);
    tc_gemm(gA2, out_w, gX2, NTOK, DM, DM, nullptr, gX1, 1.0f, 0, 0);

    // ---- Conv module (bf16 path) ----
    rmsnorm_bf16_kernel<<<NTOK, 256>>>(gX2, conv_norm_w, gA2);
    tc_gemm(gA2, pw1_w, gH, NTOK, 2 * DM, DM, pw1_b, nullptr, 1.0f, 0, 0);
    glu_kernel<<<EW_BLOCKS, 256>>>(gH, gT);
    dwconv_kernel<<<EW_BLOCKS, 256>>>(gT, dw_w, dw_b, gC);
    bnstats_kernel<<<DM, 256>>>(gC, gM, gV);
    bnapply_bf16_kernel<<<EW_BLOCKS, 256>>>(gC, gM, gV, bn_g, bn_b, gA2);
    tc_gemm(gA2, pw2_w, gX1, NTOK, DM, DM, pw2_b, nullptr, 1.0f, 0, 0);

    // ---- FF2 (fp16 2-term path) ----
    rmsnorm_fp16_kernel<<<NTOK, 256>>>(gX1, ff2_norm_w, gF16);
    tc_gemm_fp16(gF16, ff2_w1, gH16, NTOK, FFD, DM, ff2_b1, nullptr, 1.0f, 1, 2);
    tc_gemm_fp16(gH16, ff2_w2, gX2, NTOK, DM, FFD, ff2_b2, gX1, 0.5f, 0, 0);

    // ---- final norm ----
    rmsnorm_kernel<<<NTOK, 256>>>(gX2, out_norm_w, out_x);
}

// round 9
// speedup vs baseline: 2.5152x; 1.0514x over previous
#include <cuda_runtime.h>
#include <cuda_bf16.h>
#include <cuda_fp16.h>
#include <math.h>
#include <stdint.h>

// ---------------- problem constants ----------------
#define BSZ      2
#define SEQ      2048
#define NTOK     4096          // B*N
#define CACHE_T  512
#define KVLEN    2560
#define DM       768
#define NH       12
#define HD       64
#define FFD      3072
#define KSZ      31
#define EPSF     1e-5f

// ---------------- scratch (device globals; no allocation) ----------------
__device__ __align__(128) float g_h[NTOK * FFD];
__device__ __align__(128) float g_x1[NTOK * DM];
__device__ __align__(128) float g_x2[NTOK * DM];
__device__ __align__(128) float g_qkv[NTOK * 3 * NH * HD];
__device__ __align__(128) float g_tmp[NTOK * DM];
__device__ __align__(128) float g_conv[NTOK * DM];
__device__ float g_mean[DM];
__device__ float g_var[DM];
__device__ __align__(128) __nv_bfloat16 g_a2[NTOK * 2 * DM];             // bf16 hi|lo / fp16 reuse
__device__ __align__(128) __nv_bfloat16 g_ah[(size_t)NTOK * 2 * FFD];    // FF intermediate (fp16 reuse)
__device__ __align__(128) __nv_bfloat16 g_b2[(size_t)FFD * 2 * DM];      // weights (N,2K)
__device__ __align__(128) __nv_bfloat16 g_qh[BSZ * NH * SEQ * HD];
__device__ __align__(128) __nv_bfloat16 g_ql[BSZ * NH * SEQ * HD];
__device__ __align__(128) __nv_bfloat16 g_kh[BSZ * NH * KVLEN * HD];
__device__ __align__(128) __nv_bfloat16 g_kl[BSZ * NH * KVLEN * HD];
__device__ __align__(128) __nv_bfloat16 g_vth[BSZ * NH * HD * KVLEN];    // (b,h,d,t)
__device__ __align__(128) __nv_bfloat16 g_vtl[BSZ * NH * HD * KVLEN];

// ---------------- helpers ----------------
__device__ __forceinline__ float gelu_tanh(float x) {
    const float c = 0.7978845608028654f;
    float t = tanhf(c * (x + 0.044715f * x * x * x));
    return 0.5f * x * (1.0f + t);
}
__device__ __forceinline__ float sigmoidf_(float x) {
    return 1.0f / (1.0f + expf(-x));
}
__device__ __forceinline__ uint32_t smem_u32(const void* p) {
    uint32_t a;
    asm("{ .reg .u64 t; cvta.to.shared.u64 t, %1; cvt.u32.u64 %0, t; }"
        : "=r"(a) : "l"(p));
    return a;
}
__device__ __forceinline__ void cpasync16(uint32_t dst, const void* src) {
    asm volatile("cp.async.cg.shared.global [%0], [%1], 16;" :: "r"(dst), "l"(src));
}
__device__ __forceinline__ void cpcommit() {
    asm volatile("cp.async.commit_group;");
}
#define CP_WAIT(N) asm volatile("cp.async.wait_group %0;" :: "n"(N))
__device__ __forceinline__ void ldmx4(uint32_t r[4], uint32_t a) {
    asm volatile("ldmatrix.sync.aligned.m8n8.x4.shared.b16 {%0,%1,%2,%3}, [%4];"
                 : "=r"(r[0]), "=r"(r[1]), "=r"(r[2]), "=r"(r[3]) : "r"(a));
}
__device__ __forceinline__ void mma16816(float c[4], const uint32_t a[4],
                                         uint32_t b0, uint32_t b1) {
    asm volatile(
        "mma.sync.aligned.m16n8k16.row.col.f32.bf16.bf16.f32 "
        "{%0,%1,%2,%3}, {%4,%5,%6,%7}, {%8,%9}, {%0,%1,%2,%3};"
        : "+f"(c[0]), "+f"(c[1]), "+f"(c[2]), "+f"(c[3])
        : "r"(a[0]), "r"(a[1]), "r"(a[2]), "r"(a[3]), "r"(b0), "r"(b1));
}
__device__ __forceinline__ void mma16816h(float c[4], const uint32_t a[4],
                                          uint32_t b0, uint32_t b1) {
    asm volatile(
        "mma.sync.aligned.m16n8k16.row.col.f32.f16.f16.f32 "
        "{%0,%1,%2,%3}, {%4,%5,%6,%7}, {%8,%9}, {%0,%1,%2,%3};"
        : "+f"(c[0]), "+f"(c[1]), "+f"(c[2]), "+f"(c[3])
        : "r"(a[0]), "r"(a[1]), "r"(a[2]), "r"(a[3]), "r"(b0), "r"(b1));
}
__device__ __forceinline__ void splitpair(float x, float y,
                                          uint32_t& hi, uint32_t& lo) {
    __nv_bfloat16 hx = __float2bfloat16(x), hy = __float2bfloat16(y);
    __nv_bfloat162 H; H.x = hx; H.y = hy;
    __nv_bfloat162 L = __floats2bfloat162_rn(x - __bfloat162float(hx),
                                             y - __bfloat162float(hy));
    hi = *reinterpret_cast<uint32_t*>(&H);
    lo = *reinterpret_cast<uint32_t*>(&L);
}

// ---------------- weight conversion: W (K,N) fp32 -> (N,2K) bf16 hi|lo ----------------
__global__ void convB_kernel(const float* __restrict__ W,
                             __nv_bfloat16* __restrict__ out, int K, int N) {
    __shared__ float t[32][33];
    int k0 = blockIdx.x * 32, n0 = blockIdx.y * 32;
    int tx = threadIdx.x, ty = threadIdx.y;   // 32 x 8
    #pragma unroll
    for (int i = ty; i < 32; i += 8)
        t[i][tx] = W[(size_t)(k0 + i) * N + n0 + tx];
    __syncthreads();
    #pragma unroll
    for (int i = ty; i < 32; i += 8) {
        float v = t[tx][i];                   // W[k0+tx][n0+i]
        __nv_bfloat16 h = __float2bfloat16(v);
        float lo = v - __bfloat162float(h);
        size_t b = (size_t)(n0 + i) * (2 * K) + k0 + tx;
        out[b] = h;
        out[b + K] = __float2bfloat16(lo);
    }
}

// ---------------- weight conversion: W (K,N) fp32 -> (N,2K) fp16 hi|lo ----------------
__global__ void convB_fp16_kernel(const float* __restrict__ W,
                                  __half* __restrict__ out, int K, int N) {
    __shared__ float t[32][33];
    int k0 = blockIdx.x * 32, n0 = blockIdx.y * 32;
    int tx = threadIdx.x, ty = threadIdx.y;   // 32 x 8
    #pragma unroll
    for (int i = ty; i < 32; i += 8)
        t[i][tx] = W[(size_t)(k0 + i) * N + n0 + tx];
    __syncthreads();
    #pragma unroll
    for (int i = ty; i < 32; i += 8) {
        float v = t[tx][i];                   // W[k0+tx][n0+i]
        __half h = __float2half(v);
        float lo = v - __half2float(h);
        size_t b = (size_t)(n0 + i) * (2 * K) + k0 + tx;
        out[b] = h;
        out[b + K] = __float2half(lo);
    }
}

// ---------------- warp-MMA GEMM, 128x128x64 tile, 3-stage pipeline ----------------
// 256 threads, 8 warps (2m x 4n), warp tile 64x32.  (R4/R7-proven config.)
// DT=0: bf16 3-pass split, A2 (M,2K) hi|lo.   DT=1: fp16 2-pass, A2 (M,K) single.
// B2 (N,2K) K-major hi|lo (bf16 or fp16 per DT).
// outmode 0: C fp32 (M,N) bias/act/scale/res.
// outmode 1: C bf16 (M,2N) hi|lo.   outmode 2: C fp16 (M,N).
template<int DT>
__global__ __launch_bounds__(256)
void hgemm_mma_t(const uint16_t* __restrict__ A2,
                 const uint16_t* __restrict__ B2,
                 void* __restrict__ Cout, int M, int N, int K,
                 const float* __restrict__ bias, const float* __restrict__ res,
                 float scale, int act, int outmode) {
    extern __shared__ __align__(16) unsigned char dsm[];
    uint32_t sbase = smem_u32(dsm);

    int tid = threadIdx.x;
    int lane = tid & 31;
    int wid = tid >> 5;
    int wm = (wid >> 2) * 64;
    int wn = (wid & 3) * 32;
    int bm = blockIdx.y * 128;
    int bn = blockIdx.x * 128;

    int kpp = K >> 6;
    int nkb = (DT ? 2 : 3) * kpp;

    int lr = tid >> 1;
    int lc = (tid & 1) * 4;
    int sw_r = lr & 7;

    float acc[4][4][4];
    #pragma unroll
    for (int a = 0; a < 4; a++)
        #pragma unroll
        for (int b = 0; b < 4; b++)
            #pragma unroll
            for (int c = 0; c < 4; c++) acc[a][b][c] = 0.f;

    auto issue = [&](int kb, int buf) {
        int p = kb / kpp;
        int off = (kb - p * kpp) << 6;
        int aCol = DT ? off : (((p == 2) ? K : 0) + off);
        int bCol = DT ? (p * K + off) : (((p == 1) ? K : 0) + off);
        size_t astr = DT ? (size_t)K : (size_t)(2 * K);
        const uint16_t* ag = A2 + (size_t)(bm + lr) * astr + aCol + lc * 8;
        const uint16_t* bg = B2 + (size_t)(bn + lr) * (2 * K) + bCol + lc * 8;
        uint32_t abuf = sbase + buf * 32768 + lr * 128;
        uint32_t bbuf = abuf + 16384;
        #pragma unroll
        for (int j = 0; j < 4; j++) {
            uint32_t phys = (uint32_t)((lc + j) ^ sw_r) * 16;
            cpasync16(abuf + phys, ag + j * 8);
            cpasync16(bbuf + phys, bg + j * 8);
        }
        cpcommit();
    };

    issue(0, 0);
    issue(1, 1);

    int rA = lane & 15;
    int kq = lane >> 4;
    int swA = rA & 7;

    for (int kb = 0; kb < nkb; kb++) {
        if (kb + 1 < nkb) { CP_WAIT(1); } else { CP_WAIT(0); }
        __syncthreads();
        if (kb + 2 < nkb) issue(kb + 2, (kb + 2) % 3);

        uint32_t Ab = sbase + (kb % 3) * 32768;
        uint32_t Bb = Ab + 16384;

        #pragma unroll
        for (int ks = 0; ks < 4; ks++) {
            uint32_t phys = (uint32_t)(((ks * 2 + kq) ^ swA) * 16);
            uint32_t af[4][4];
            #pragma unroll
            for (int mt = 0; mt < 4; mt++)
                ldmx4(af[mt], Ab + (uint32_t)(wm + mt * 16 + rA) * 128 + phys);
            uint32_t bf[4][2];
            #pragma unroll
            for (int g = 0; g < 2; g++) {
                uint32_t r[4];
                ldmx4(r, Bb + (uint32_t)(wn + g * 16 + rA) * 128 + phys);
                bf[2 * g][0] = r[0]; bf[2 * g][1] = r[2];
                bf[2 * g + 1][0] = r[1]; bf[2 * g + 1][1] = r[3];
            }
            #pragma unroll
            for (int mt = 0; mt < 4; mt++)
                #pragma unroll
                for (int nt = 0; nt < 4; nt++) {
                    if (DT) mma16816h(acc[mt][nt], af[mt], bf[nt][0], bf[nt][1]);
                    else    mma16816 (acc[mt][nt], af[mt], bf[nt][0], bf[nt][1]);
                }
        }
        // no trailing sync: next iteration's top barrier guards buffer reuse
    }

    int gq = lane >> 2;
    int tg = lane & 3;
    #pragma unroll
    for (int mt = 0; mt < 4; mt++) {
        #pragma unroll
        for (int nt = 0; nt < 4; nt++) {
            int row0 = bm + wm + mt * 16 + gq;
            int col = bn + wn + nt * 8 + 2 * tg;
            float bv0 = bias ? bias[col] : 0.f;
            float bv1 = bias ? bias[col + 1] : 0.f;
            #pragma unroll
            for (int half = 0; half < 2; half++) {
                int row = row0 + half * 8;
                float v0 = acc[mt][nt][2 * half + 0] + bv0;
                float v1 = acc[mt][nt][2 * half + 1] + bv1;
                if (act == 1) { v0 = gelu_tanh(v0); v1 = gelu_tanh(v1); }
                v0 *= scale; v1 *= scale;
                if (outmode == 0) {
                    float* C = (float*)Cout;
                    if (res) {
                        v0 += res[(size_t)row * N + col];
                        v1 += res[(size_t)row * N + col + 1];
                    }
                    *(float2*)&C[(size_t)row * N + col] = make_float2(v0, v1);
                } else if (outmode == 1) {
                    __nv_bfloat16* C2 = (__nv_bfloat16*)Cout;
                    uint32_t hi, lo;
                    splitpair(v0, v1, hi, lo);
                    *(uint32_t*)&C2[(size_t)row * 2 * N + col] = hi;
                    *(uint32_t*)&C2[(size_t)row * 2 * N + N + col] = lo;
                } else {
                    __half* C3 = (__half*)Cout;
                    __half2 hv = __floats2half2_rn(v0, v1);
                    *(uint32_t*)&C3[(size_t)row * N + col] =
                        *reinterpret_cast<uint32_t*>(&hv);
                }
            }
        }
    }
}

// ---------------- rmsnorm fp32 out (final) ----------------
__global__ void rmsnorm_kernel(const float* __restrict__ x,
                               const float* __restrict__ w,
                               float* __restrict__ y) {
    int row = blockIdx.x;
    const float* xr = x + (size_t)row * DM;
    float ss = 0.f;
    for (int i = threadIdx.x; i < DM; i += blockDim.x) {
        float v = xr[i];
        ss += v * v;
    }
    #pragma unroll
    for (int o = 16; o > 0; o >>= 1) ss += __shfl_xor_sync(0xffffffffu, ss, o);
    __shared__ float red[8];
    if ((threadIdx.x & 31) == 0) red[threadIdx.x >> 5] = ss;
    __syncthreads();
    __shared__ float s_r;
    if (threadIdx.x == 0) {
        float t = 0.f;
        #pragma unroll
        for (int i = 0; i < 8; i++) t += red[i];
        s_r = rsqrtf(t / (float)DM + EPSF);
    }
    __syncthreads();
    float r = s_r;
    float* yr = y + (size_t)row * DM;
    for (int i = threadIdx.x; i < DM; i += blockDim.x)
        yr[i] = xr[i] * r * w[i];
}

// ---------------- rmsnorm -> bf16 hi|lo A2 format ----------------
__global__ void rmsnorm_bf16_kernel(const float* __restrict__ x,
                                    const float* __restrict__ w,
                                    __nv_bfloat16* __restrict__ y) {
    int row = blockIdx.x;
    const float* xr = x + (size_t)row * DM;
    float ss = 0.f;
    for (int i = threadIdx.x; i < DM; i += blockDim.x) {
        float v = xr[i];
        ss += v * v;
    }
    #pragma unroll
    for (int o = 16; o > 0; o >>= 1) ss += __shfl_xor_sync(0xffffffffu, ss, o);
    __shared__ float red[8];
    if ((threadIdx.x & 31) == 0) red[threadIdx.x >> 5] = ss;
    __syncthreads();
    __shared__ float s_r;
    if (threadIdx.x == 0) {
        float t = 0.f;
        #pragma unroll
        for (int i = 0; i < 8; i++) t += red[i];
        s_r = rsqrtf(t / (float)DM + EPSF);
    }
    __syncthreads();
    float r = s_r;
    __nv_bfloat16* yr = y + (size_t)row * (2 * DM);
    for (int i = threadIdx.x; i < DM; i += blockDim.x) {
        float v = xr[i] * r * w[i];
        __nv_bfloat16 h = __float2bfloat16(v);
        yr[i] = h;
        yr[DM + i] = __float2bfloat16(v - __bfloat162float(h));
    }
}

// ---------------- rmsnorm -> fp16 single ----------------
__global__ void rmsnorm_fp16_kernel(const float* __restrict__ x,
                                    const float* __restrict__ w,
                                    __half* __restrict__ y) {
    int row = blockIdx.x;
    const float* xr = x + (size_t)row * DM;
    float ss = 0.f;
    for (int i = threadIdx.x; i < DM; i += blockDim.x) {
        float v = xr[i];
        ss += v * v;
    }
    #pragma unroll
    for (int o = 16; o > 0; o >>= 1) ss += __shfl_xor_sync(0xffffffffu, ss, o);
    __shared__ float red[8];
    if ((threadIdx.x & 31) == 0) red[threadIdx.x >> 5] = ss;
    __syncthreads();
    __shared__ float s_r;
    if (threadIdx.x == 0) {
        float t = 0.f;
        #pragma unroll
        for (int i = 0; i < 8; i++) t += red[i];
        s_r = rsqrtf(t / (float)DM + EPSF);
    }
    __syncthreads();
    float r = s_r;
    __half* yr = y + (size_t)row * DM;
    for (int i = threadIdx.x; i < DM; i += blockDim.x)
        yr[i] = __float2half(xr[i] * r * w[i]);
}

// ---------------- qkv postproc: head rmsnorm + rope + split outputs ----------------
__global__ __launch_bounds__(128)
void qkv_post_kernel(const float* __restrict__ qkv,
                     const float* __restrict__ qnw, const float* __restrict__ knw,
                     __nv_bfloat16* __restrict__ Qh, __nv_bfloat16* __restrict__ Ql,
                     __nv_bfloat16* __restrict__ Kh, __nv_bfloat16* __restrict__ Kl,
                     __nv_bfloat16* __restrict__ Vth, __nv_bfloat16* __restrict__ Vtl,
                     float* __restrict__ kv_out) {
    int w = blockIdx.x * 4 + (threadIdx.x >> 5);
    int lane = threadIdx.x & 31;
    int h = w % NH;
    int tok = w / NH;
    int b = tok / SEQ;
    int n = tok % SEQ;

    const float* base = qkv + (size_t)tok * (3 * NH * HD) + h * (HD * 3);
    float q1 = base[lane * 3 + 0], q2 = base[(lane + 32) * 3 + 0];
    float k1 = base[lane * 3 + 1], k2 = base[(lane + 32) * 3 + 1];
    float v1 = base[lane * 3 + 2], v2 = base[(lane + 32) * 3 + 2];

    float sq = q1 * q1 + q2 * q2;
    #pragma unroll
    for (int o = 16; o > 0; o >>= 1) sq += __shfl_xor_sync(0xffffffffu, sq, o);
    float rq = rsqrtf(sq / 64.f + EPSF);
    q1 *= rq * qnw[lane]; q2 *= rq * qnw[lane + 32];

    float sk = k1 * k1 + k2 * k2;
    #pragma unroll
    for (int o = 16; o > 0; o >>= 1) sk += __shfl_xor_sync(0xffffffffu, sk, o);
    float rk = rsqrtf(sk / 64.f + EPSF);
    k1 *= rk * knw[lane]; k2 *= rk * knw[lane + 32];

    int t = CACHE_T + n;
    size_t kb = ((((size_t)b * KVLEN + t) * 2 + 0) * NH + h) * HD;
    kv_out[kb + lane] = k1;
    kv_out[kb + lane + 32] = k2;
    kv_out[kb + NH * HD + lane] = v1;
    kv_out[kb + NH * HD + lane + 32] = v2;

    float inv = 1.0f / powf(10000.0f, (float)lane / 32.0f);
    float ang = (float)t * inv;
    float c = cosf(ang), s = sinf(ang);

    int bh = b * NH + h;
    float qa = (q1 * c - q2 * s) * 0.125f;
    float qb2 = (q2 * c + q1 * s) * 0.125f;
    size_t qoff = ((size_t)bh * SEQ + n) * HD;
    {
        __nv_bfloat16 h1 = __float2bfloat16(qa);
        __nv_bfloat16 h2 = __float2bfloat16(qb2);
        Qh[qoff + lane] = h1;
        Qh[qoff + lane + 32] = h2;
        Ql[qoff + lane] = __float2bfloat16(qa - __bfloat162float(h1));
        Ql[qoff + lane + 32] = __float2bfloat16(qb2 - __bfloat162float(h2));
    }
    float ka = k1 * c - k2 * s;
    float kb2 = k2 * c + k1 * s;
    size_t koff = ((size_t)bh * KVLEN + t) * HD;
    {
        __nv_bfloat16 h1 = __float2bfloat16(ka);
        __nv_bfloat16 h2 = __float2bfloat16(kb2);
        Kh[koff + lane] = h1;
        Kh[koff + lane + 32] = h2;
        Kl[koff + lane] = __float2bfloat16(ka - __bfloat162float(h1));
        Kl[koff + lane + 32] = __float2bfloat16(kb2 - __bfloat162float(h2));
    }
    size_t voff = ((size_t)bh * HD) * KVLEN + t;
    {
        __nv_bfloat16 h1 = __float2bfloat16(v1);
        __nv_bfloat16 h2 = __float2bfloat16(v2);
        Vth[voff + (size_t)lane * KVLEN] = h1;
        Vth[voff + (size_t)(lane + 32) * KVLEN] = h2;
        Vtl[voff + (size_t)lane * KVLEN] = __float2bfloat16(v1 - __bfloat162float(h1));
        Vtl[voff + (size_t)(lane + 32) * KVLEN] = __float2bfloat16(v2 - __bfloat162float(h2));
    }
}

// ---------------- cached tokens: copy + rope + split ----------------
__global__ __launch_bounds__(128)
void cache_kernel(const float* __restrict__ cached,
                  __nv_bfloat16* __restrict__ Kh, __nv_bfloat16* __restrict__ Kl,
                  __nv_bfloat16* __restrict__ Vth, __nv_bfloat16* __restrict__ Vtl,
                  float* __restrict__ kv_out) {
    int w = blockIdx.x * 4 + (threadIdx.x >> 5);
    int lane = threadIdx.x & 31;
    int h = w % NH;
    int bt = w / NH;
    int b = bt / CACHE_T;
    int t = bt % CACHE_T;

    size_t src = ((((size_t)b * CACHE_T + t) * 2 + 0) * NH + h) * HD;
    float k1 = cached[src + lane], k2 = cached[src + lane + 32];
    float v1 = cached[src + NH * HD + lane], v2 = cached[src + NH * HD + lane + 32];

    size_t dst = ((((size_t)b * KVLEN + t) * 2 + 0) * NH + h) * HD;
    kv_out[dst + lane] = k1;
    kv_out[dst + lane + 32] = k2;
    kv_out[dst + NH * HD + lane] = v1;
    kv_out[dst + NH * HD + lane + 32] = v2;

    float inv = 1.0f / powf(10000.0f, (float)lane / 32.0f);
    float ang = (float)t * inv;
    float c = cosf(ang), s = sinf(ang);
    float ka = k1 * c - k2 * s;
    float kb2 = k2 * c + k1 * s;

    int bh = b * NH + h;
    size_t koff = ((size_t)bh * KVLEN + t) * HD;
    {
        __nv_bfloat16 h1 = __float2bfloat16(ka);
        __nv_bfloat16 h2 = __float2bfloat16(kb2);
        Kh[koff + lane] = h1;
        Kh[koff + lane + 32] = h2;
        Kl[koff + lane] = __float2bfloat16(ka - __bfloat162float(h1));
        Kl[koff + lane + 32] = __float2bfloat16(kb2 - __bfloat162float(h2));
    }
    size_t voff = ((size_t)bh * HD) * KVLEN + t;
    {
        __nv_bfloat16 h1 = __float2bfloat16(v1);
        __nv_bfloat16 h2 = __float2bfloat16(v2);
        Vth[voff + (size_t)lane * KVLEN] = h1;
        Vth[voff + (size_t)(lane + 32) * KVLEN] = h2;
        Vtl[voff + (size_t)lane * KVLEN] = __float2bfloat16(v1 - __bfloat162float(h1));
        Vtl[voff + (size_t)(lane + 32) * KVLEN] = __float2bfloat16(v2 - __bfloat162float(h2));
    }
}

// ---------------- attention: MMA flash, 64 q-rows/block, 64-key chunks ----------------
// epilogue writes single fp16 (M, DM) for the fp16 out-proj GEMM.
#define AT_STAGE 32768
__global__ __launch_bounds__(128)
void attn_mma(const __nv_bfloat16* __restrict__ Qh, const __nv_bfloat16* __restrict__ Ql,
              const __nv_bfloat16* __restrict__ Kh, const __nv_bfloat16* __restrict__ Kl,
              const __nv_bfloat16* __restrict__ Vth, const __nv_bfloat16* __restrict__ Vtl,
              __half* __restrict__ Oh) {
    extern __shared__ __align__(16) unsigned char dsm[];
    uint32_t sbase = smem_u32(dsm);
    uint32_t qarea = sbase + 2 * AT_STAGE;

    int tid = threadIdx.x, lane = tid & 31, wid = tid >> 5;
    int bh = blockIdx.y;
    int b = bh / NH, h = bh % NH;
    int q0 = blockIdx.x * 64;

    size_t qoff = ((size_t)bh * SEQ + q0) * HD;
    size_t koff = (size_t)bh * KVLEN * HD;
    size_t voff = (size_t)bh * HD * KVLEN;

    int lr = tid >> 1;
    int lc4 = (tid & 1) * 4;

    {
        const __nv_bfloat16* qhg = Qh + qoff + lr * HD;
        const __nv_bfloat16* qlg = Ql + qoff + lr * HD;
        #pragma unroll
        for (int j = 0; j < 4; j++) {
            int ch = lc4 + j;
            uint32_t phys = (uint32_t)((ch ^ (lr & 7)) * 16);
            cpasync16(qarea + lr * 128 + phys, qhg + ch * 8);
            cpasync16(qarea + 8192 + lr * 128 + phys, qlg + ch * 8);
        }
        cpcommit();
    }

    auto issueKV = [&](int c, int buf) {
        uint32_t dst = sbase + buf * AT_STAGE + lr * 128;
        const __nv_bfloat16* khg = Kh + koff + (size_t)(c * 64 + lr) * HD;
        const __nv_bfloat16* klg = Kl + koff + (size_t)(c * 64 + lr) * HD;
        const __nv_bfloat16* vhg = Vth + voff + (size_t)lr * KVLEN + c * 64;
        const __nv_bfloat16* vlg = Vtl + voff + (size_t)lr * KVLEN + c * 64;
        #pragma unroll
        for (int j = 0; j < 4; j++) {
            int ch = lc4 + j;
            uint32_t phys = (uint32_t)((ch ^ (lr & 7)) * 16);
            cpasync16(dst + phys, khg + ch * 8);
            cpasync16(dst + 8192 + phys, klg + ch * 8);
            cpasync16(dst + 16384 + phys, vhg + ch * 8);
            cpasync16(dst + 24576 + phys, vlg + ch * 8);
        }
        cpcommit();
    };

    issueKV(0, 0);
    CP_WAIT(1);
    __syncthreads();

    int rA = lane & 15, kq = lane >> 4;
    int qrow = wid * 16 + rA;
    int qs = qrow & 7;
    uint32_t qfh[4][4], qfl[4][4];
    #pragma unroll
    for (int kt = 0; kt < 4; kt++) {
        uint32_t phys = (uint32_t)(((kt * 2 + kq) ^ qs) * 16);
        ldmx4(qfh[kt], qarea + qrow * 128 + phys);
        ldmx4(qfl[kt], qarea + 8192 + qrow * 128 + phys);
    }

    int gq = lane >> 2, tg = lane & 3;
    float m0 = -1e30f, m1 = -1e30f, l0 = 0.f, l1 = 0.f;
    float O[8][4];
    #pragma unroll
    for (int nt = 0; nt < 8; nt++)
        #pragma unroll
        for (int i = 0; i < 4; i++) O[nt][i] = 0.f;

    const int NCH = KVLEN / 64;
    for (int c = 0; c < NCH; c++) {
        if (c + 1 < NCH) { issueKV(c + 1, (c + 1) & 1); CP_WAIT(1); }
        else { CP_WAIT(0); }
        __syncthreads();

        uint32_t bufK = sbase + (c & 1) * AT_STAGE;
        uint32_t bufV = bufK + 16384;

        float S[8][4];
        #pragma unroll
        for (int nt = 0; nt < 8; nt++)
            #pragma unroll
            for (int i = 0; i < 4; i++) S[nt][i] = 0.f;

        #pragma unroll
        for (int kt = 0; kt < 4; kt++) {
            uint32_t kfh[4][4], kfl[4][4];
            #pragma unroll
            for (int g2 = 0; g2 < 4; g2++) {
                int krow = g2 * 16 + rA;
                uint32_t phys = (uint32_t)(((kt * 2 + kq) ^ (krow & 7)) * 16);
                ldmx4(kfh[g2], bufK + krow * 128 + phys);
                ldmx4(kfl[g2], bufK + 8192 + krow * 128 + phys);
            }
            #pragma unroll
            for (int g2 = 0; g2 < 4; g2++)
                #pragma unroll
                for (int hf = 0; hf < 2; hf++) {
                    int nt = 2 * g2 + hf;
                    mma16816(S[nt], qfh[kt], kfh[g2][hf], kfh[g2][hf + 2]);
                    mma16816(S[nt], qfh[kt], kfl[g2][hf], kfl[g2][hf + 2]);
                    mma16816(S[nt], qfl[kt], kfh[g2][hf], kfh[g2][hf + 2]);
                }
        }

        float mx0 = -1e30f, mx1 = -1e30f;
        #pragma unroll
        for (int nt = 0; nt < 8; nt++) {
            mx0 = fmaxf(mx0, fmaxf(S[nt][0], S[nt][1]));
            mx1 = fmaxf(mx1, fmaxf(S[nt][2], S[nt][3]));
        }
        mx0 = fmaxf(mx0, __shfl_xor_sync(0xffffffffu, mx0, 1));
        mx0 = fmaxf(mx0, __shfl_xor_sync(0xffffffffu, mx0, 2));
        mx1 = fmaxf(mx1, __shfl_xor_sync(0xffffffffu, mx1, 1));
        mx1 = fmaxf(mx1, __shfl_xor_sync(0xffffffffu, mx1, 2));
        float nm0 = fmaxf(m0, mx0), nm1 = fmaxf(m1, mx1);
        float a0 = __expf(m0 - nm0), a1 = __expf(m1 - nm1);

        float rs0 = 0.f, rs1 = 0.f;
        #pragma unroll
        for (int nt = 0; nt < 8; nt++) {
            S[nt][0] = __expf(S[nt][0] - nm0);
            S[nt][1] = __expf(S[nt][1] - nm0);
            S[nt][2] = __expf(S[nt][2] - nm1);
            S[nt][3] = __expf(S[nt][3] - nm1);
            rs0 += S[nt][0] + S[nt][1];
            rs1 += S[nt][2] + S[nt][3];
        }
        rs0 += __shfl_xor_sync(0xffffffffu, rs0, 1);
        rs0 += __shfl_xor_sync(0xffffffffu, rs0, 2);
        rs1 += __shfl_xor_sync(0xffffffffu, rs1, 1);
        rs1 += __shfl_xor_sync(0xffffffffu, rs1, 2);
        l0 = l0 * a0 + rs0;
        l1 = l1 * a1 + rs1;
        m0 = nm0; m1 = nm1;
        #pragma unroll
        for (int nt = 0; nt < 8; nt++) {
            O[nt][0] *= a0; O[nt][1] *= a0;
            O[nt][2] *= a1; O[nt][3] *= a1;
        }

        #pragma unroll
        for (int kt = 0; kt < 4; kt++) {
            uint32_t ah[4], al[4];
            splitpair(S[2 * kt][0], S[2 * kt][1], ah[0], al[0]);
            splitpair(S[2 * kt][2], S[2 * kt][3], ah[1], al[1]);
            splitpair(S[2 * kt + 1][0], S[2 * kt + 1][1], ah[2], al[2]);
            splitpair(S[2 * kt + 1][2], S[2 * kt + 1][3], ah[3], al[3]);
            uint32_t vfh[4][4], vfl[4][4];
            #pragma unroll
            for (int g2 = 0; g2 < 4; g2++) {
                int vrow = g2 * 16 + rA;
                uint32_t phys = (uint32_t)(((kt * 2 + kq) ^ (vrow & 7)) * 16);
                ldmx4(vfh[g2], bufV + vrow * 128 + phys);
                ldmx4(vfl[g2], bufV + 8192 + vrow * 128 + phys);
            }
            #pragma unroll
            for (int g2 = 0; g2 < 4; g2++)
                #pragma unroll
                for (int hf = 0; hf < 2; hf++) {
                    int nt = 2 * g2 + hf;
                    mma16816(O[nt], ah, vfh[g2][hf], vfh[g2][hf + 2]);
                    mma16816(O[nt], ah, vfl[g2][hf], vfl[g2][hf + 2]);
                    mma16816(O[nt], al, vfh[g2][hf], vfh[g2][hf + 2]);
                }
        }
        __syncthreads();
    }

    float inv0 = 1.0f / l0, inv1 = 1.0f / l1;
    int r0 = q0 + wid * 16 + gq;
    size_t tok0 = (size_t)(b * SEQ + r0);
    size_t tok1 = tok0 + 8;
    #pragma unroll
    for (int nt = 0; nt < 8; nt++) {
        int col = h * HD + nt * 8 + 2 * tg;
        __half2 h0 = __floats2half2_rn(O[nt][0] * inv0, O[nt][1] * inv0);
        __half2 h1 = __floats2half2_rn(O[nt][2] * inv1, O[nt][3] * inv1);
        *(uint32_t*)&Oh[tok0 * DM + col] = *reinterpret_cast<uint32_t*>(&h0);
        *(uint32_t*)&Oh[tok1 * DM + col] = *reinterpret_cast<uint32_t*>(&h1);
    }
}

// ---------------- GLU ----------------
__global__ void glu_kernel(const float* __restrict__ in, float* __restrict__ out) {
    int i = blockIdx.x * blockDim.x + threadIdx.x;
    if (i >= NTOK * DM) return;
    int r = i / DM, c = i % DM;
    float a = in[(size_t)r * (2 * DM) + c];
    float bb = in[(size_t)r * (2 * DM) + DM + c];
    out[i] = a * sigmoidf_(bb);
}

// ---------------- depthwise conv ----------------
__global__ void dwconv_kernel(const float* __restrict__ in,
                              const float* __restrict__ w,
                              const float* __restrict__ bias,
                              float* __restrict__ out) {
    int i = blockIdx.x * blockDim.x + threadIdx.x;
    if (i >= NTOK * DM) return;
    int c = i % DM;
    int pos = i / DM;
    int n = pos % SEQ;
    int b = pos / SEQ;
    float acc = bias[c];
    #pragma unroll
    for (int k = 0; k < KSZ; k++) {
        int nn = n - (KSZ / 2) + k;
        if (nn >= 0 && nn < SEQ)
            acc = fmaf(in[((size_t)b * SEQ + nn) * DM + c], w[c * KSZ + k], acc);
    }
    out[i] = acc;
}

// ---------------- batchnorm stats ----------------
__global__ void bnstats_kernel(const float* __restrict__ in,
                               float* __restrict__ mean, float* __restrict__ var) {
    int c = blockIdx.x;
    float s = 0.f, ss = 0.f;
    for (int r = threadIdx.x; r < NTOK; r += blockDim.x) {
        float v = in[(size_t)r * DM + c];
        s += v;
        ss += v * v;
    }
    #pragma unroll
    for (int o = 16; o > 0; o >>= 1) {
        s += __shfl_xor_sync(0xffffffffu, s, o);
        ss += __shfl_xor_sync(0xffffffffu, ss, o);
    }
    __shared__ float rs[8], rss[8];
    if ((threadIdx.x & 31) == 0) {
        rs[threadIdx.x >> 5] = s;
        rss[threadIdx.x >> 5] = ss;
    }
    __syncthreads();
    if (threadIdx.x == 0) {
        float ts = 0.f, tss = 0.f;
        #pragma unroll
        for (int i = 0; i < 8; i++) { ts += rs[i]; tss += rss[i]; }
        float m = ts / (float)NTOK;
        mean[c] = m;
        var[c] = tss / (float)NTOK - m * m;
    }
}

// ---------------- bn apply + swish -> fp16 single ----------------
__global__ void bnapply_fp16_kernel(const float* __restrict__ in,
                                    const float* __restrict__ mean, const float* __restrict__ var,
                                    const float* __restrict__ g, const float* __restrict__ be,
                                    __half* __restrict__ out) {
    int i = blockIdx.x * blockDim.x + threadIdx.x;
    if (i >= NTOK * DM) return;
    int c = i % DM;
    float y = (in[i] - mean[c]) * rsqrtf(var[c] + EPSF) * g[c] + be[c];
    y = y * sigmoidf_(y);
    out[i] = __float2half(y);
}

// ---------------- host-side helpers ----------------
static __nv_bfloat16* s_b2 = nullptr;

static void tc_gemm(const __nv_bfloat16* A2, const float* W, void* C,
                    int M, int N, int K,
                    const float* bias, const float* res, float scale, int act,
                    int outmode) {
    convB_kernel<<<dim3(K / 32, N / 32), dim3(32, 8)>>>(W, s_b2, K, N);
    hgemm_mma_t<0><<<dim3(N / 128, M / 128), 256, 98304>>>(
        (const uint16_t*)A2, (const uint16_t*)s_b2, C, M, N, K,
        bias, res, scale, act, outmode);
}

static void tc_gemm_fp16(const __half* A1, const float* W, void* C,
                         int M, int N, int K,
                         const float* bias, const float* res, float scale, int act,
                         int outmode) {
    convB_fp16_kernel<<<dim3(K / 32, N / 32), dim3(32, 8)>>>(W, (__half*)s_b2, K, N);
    hgemm_mma_t<1><<<dim3(N / 128, M / 128), 256, 98304>>>(
        (const uint16_t*)A1, (const uint16_t*)s_b2, C, M, N, K,
        bias, res, scale, act, outmode);
}

extern "C" void kernel_launch(void* const* d_in, const int* in_sizes, int n_in,
                              void* d_out, int out_size) {
    (void)in_sizes; (void)n_in; (void)out_size;
    const float* x          = (const float*)d_in[0];
    const float* cached_kv  = (const float*)d_in[4];
    const float* ff1_norm_w = (const float*)d_in[5];
    const float* ff1_w1     = (const float*)d_in[6];
    const float* ff1_b1     = (const float*)d_in[7];
    const float* ff1_w2     = (const float*)d_in[8];
    const float* ff1_b2     = (const float*)d_in[9];
    const float* attn_norm_w= (const float*)d_in[10];
    const float* qkv_w      = (const float*)d_in[11];
    const float* out_w      = (const float*)d_in[12];
    const float* q_norm_w   = (const float*)d_in[13];
    const float* k_norm_w   = (const float*)d_in[14];
    const float* conv_norm_w= (const float*)d_in[15];
    const float* pw1_w      = (const float*)d_in[16];
    const float* pw1_b      = (const float*)d_in[17];
    const float* dw_w       = (const float*)d_in[18];
    const float* dw_b       = (const float*)d_in[19];
    const float* bn_g       = (const float*)d_in[20];
    const float* bn_b       = (const float*)d_in[21];
    const float* pw2_w      = (const float*)d_in[22];
    const float* pw2_b      = (const float*)d_in[23];
    const float* ff2_norm_w = (const float*)d_in[24];
    const float* ff2_w1     = (const float*)d_in[25];
    const float* ff2_b1     = (const float*)d_in[26];
    const float* ff2_w2     = (const float*)d_in[27];
    const float* ff2_b2     = (const float*)d_in[28];
    const float* out_norm_w = (const float*)d_in[29];

    float* out_x  = (float*)d_out;
    float* out_kv = out_x + (size_t)NTOK * DM;

    float *gH, *gX1, *gX2, *gQKV, *gT, *gC, *gM, *gV;
    __nv_bfloat16 *gA2, *gAH, *gQh, *gQl, *gKh, *gKl, *gVth, *gVtl;
    cudaGetSymbolAddress((void**)&gH,   g_h);
    cudaGetSymbolAddress((void**)&gX1,  g_x1);
    cudaGetSymbolAddress((void**)&gX2,  g_x2);
    cudaGetSymbolAddress((void**)&gQKV, g_qkv);
    cudaGetSymbolAddress((void**)&gT,   g_tmp);
    cudaGetSymbolAddress((void**)&gC,   g_conv);
    cudaGetSymbolAddress((void**)&gM,   g_mean);
    cudaGetSymbolAddress((void**)&gV,   g_var);
    cudaGetSymbolAddress((void**)&gA2,  g_a2);
    cudaGetSymbolAddress((void**)&gAH,  g_ah);
    cudaGetSymbolAddress((void**)&s_b2, g_b2);
    cudaGetSymbolAddress((void**)&gQh,  g_qh);
    cudaGetSymbolAddress((void**)&gQl,  g_ql);
    cudaGetSymbolAddress((void**)&gKh,  g_kh);
    cudaGetSymbolAddress((void**)&gKl,  g_kl);
    cudaGetSymbolAddress((void**)&gVth, g_vth);
    cudaGetSymbolAddress((void**)&gVtl, g_vtl);

    __half* gF16 = (__half*)gA2;     // fp16 GEMM input (M, DM)
    __half* gH16 = (__half*)gAH;     // fp16 FF intermediate (M, FFD)

    cudaFuncSetAttribute(hgemm_mma_t<0>, cudaFuncAttributeMaxDynamicSharedMemorySize, 98304);
    cudaFuncSetAttribute(hgemm_mma_t<1>, cudaFuncAttributeMaxDynamicSharedMemorySize, 98304);
    cudaFuncSetAttribute(attn_mma, cudaFuncAttributeMaxDynamicSharedMemorySize, 81920);

    const int EW_BLOCKS = (NTOK * DM + 255) / 256;

    // ---- FF1 (fp16 2-term path) ----
    rmsnorm_fp16_kernel<<<NTOK, 256>>>(x, ff1_norm_w, gF16);
    tc_gemm_fp16(gF16, ff1_w1, gH16, NTOK, FFD, DM, ff1_b1, nullptr, 1.0f, 1, 2);
    tc_gemm_fp16(gH16, ff1_w2, gX1, NTOK, DM, FFD, ff1_b2, x, 0.5f, 0, 0);

    // ---- Attention (qkv stays bf16 3-term to protect softmax; rest fp16) ----
    rmsnorm_bf16_kernel<<<NTOK, 256>>>(gX1, attn_norm_w, gA2);
    tc_gemm(gA2, qkv_w, gQKV, NTOK, 3 * NH * HD, DM, nullptr, nullptr, 1.0f, 0, 0);
    qkv_post_kernel<<<NTOK * NH / 4, 128>>>(gQKV, q_norm_w, k_norm_w,
                                            gQh, gQl, gKh, gKl, gVth, gVtl, out_kv);
    cache_kernel<<<BSZ * CACHE_T * NH / 4, 128>>>(cached_kv, gKh, gKl, gVth, gVtl, out_kv);
    attn_mma<<<dim3(SEQ / 64, BSZ * NH), 128, 81920>>>(gQh, gQl, gKh, gKl, gVth, gVtl, gF16);
    tc_gemm_fp16(gF16, out_w, gX2, NTOK, DM, DM, nullptr, gX1, 1.0f, 0, 0);

    // ---- Conv module (fp16 2-term path) ----
    rmsnorm_fp16_kernel<<<NTOK, 256>>>(gX2, conv_norm_w, gF16);
    tc_gemm_fp16(gF16, pw1_w, gH, NTOK, 2 * DM, DM, pw1_b, nullptr, 1.0f, 0, 0);
    glu_kernel<<<EW_BLOCKS, 256>>>(gH, gT);
    dwconv_kernel<<<EW_BLOCKS, 256>>>(gT, dw_w, dw_b, gC);
    bnstats_kernel<<<DM, 256>>>(gC, gM, gV);
    bnapply_fp16_kernel<<<EW_BLOCKS, 256>>>(gC, gM, gV, bn_g, bn_b, gF16);
    tc_gemm_fp16(gF16, pw2_w, gX1, NTOK, DM, DM, pw2_b, nullptr, 1.0f, 0, 0);

    // ---- FF2 (fp16 2-term path) ----
    rmsnorm_fp16_kernel<<<NTOK, 256>>>(gX1, ff2_norm_w, gF16);
    tc_gemm_fp16(gF16, ff2_w1, gH16, NTOK, FFD, DM, ff2_b1, nullptr, 1.0f, 1, 2);
    tc_gemm_fp16(gH16, ff2_w2, gX2, NTOK, DM, FFD, ff2_b2, gX1, 0.5f, 0, 0);

    // ---- final norm ----
    rmsnorm_kernel<<<NTOK, 256>>>(gX2, out_norm_w, out_x);
}

// round 11
// speedup vs baseline: 2.5761x; 1.0242x over previous
#include <cuda_runtime.h>
#include <cuda_bf16.h>
#include <cuda_fp16.h>
#include <math.h>
#include <stdint.h>

// ---------------- problem constants ----------------
#define BSZ      2
#define SEQ      2048
#define NTOK     4096          // B*N
#define CACHE_T  512
#define KVLEN    2560
#define DM       768
#define NH       12
#define HD       64
#define FFD      3072
#define KSZ      31
#define EPSF     1e-5f

// ---------------- scratch (device globals; no allocation) ----------------
__device__ __align__(128) float g_x1[NTOK * DM];
__device__ __align__(128) float g_x2[NTOK * DM];
__device__ __align__(128) float g_qkv[NTOK * 3 * NH * HD];
__device__ __align__(128) float g_tmp[NTOK * DM];            // also __half reuse
__device__ __align__(128) float g_conv[NTOK * DM];
__device__ float g_mean[DM];
__device__ float g_var[DM];
__device__ __align__(128) __nv_bfloat16 g_a2[NTOK * 2 * DM];             // fp16 GEMM input reuse
__device__ __align__(128) __nv_bfloat16 g_ah[(size_t)NTOK * 2 * FFD];    // FF intermediate (fp16 reuse)
__device__ __align__(128) __nv_bfloat16 g_b2[(size_t)FFD * 2 * DM];      // weights (N,2K)
__device__ __align__(128) __nv_bfloat16 g_qh[BSZ * NH * SEQ * HD];
__device__ __align__(128) __nv_bfloat16 g_ql[BSZ * NH * SEQ * HD];
__device__ __align__(128) __nv_bfloat16 g_kh[BSZ * NH * KVLEN * HD];
__device__ __align__(128) __nv_bfloat16 g_kl[BSZ * NH * KVLEN * HD];
__device__ __align__(128) __nv_bfloat16 g_vth[BSZ * NH * HD * KVLEN];    // (b,h,d,t)
__device__ __align__(128) __nv_bfloat16 g_vtl[BSZ * NH * HD * KVLEN];

// ---------------- helpers ----------------
__device__ __forceinline__ float gelu_tanh(float x) {
    const float c = 0.7978845608028654f;
    float t = tanhf(c * (x + 0.044715f * x * x * x));
    return 0.5f * x * (1.0f + t);
}
__device__ __forceinline__ float sigmoidf_(float x) {
    return 1.0f / (1.0f + expf(-x));
}
__device__ __forceinline__ uint32_t smem_u32(const void* p) {
    uint32_t a;
    asm("{ .reg .u64 t; cvta.to.shared.u64 t, %1; cvt.u32.u64 %0, t; }"
        : "=r"(a) : "l"(p));
    return a;
}
__device__ __forceinline__ void cpasync16(uint32_t dst, const void* src) {
    asm volatile("cp.async.cg.shared.global [%0], [%1], 16;" :: "r"(dst), "l"(src));
}
__device__ __forceinline__ void cpcommit() {
    asm volatile("cp.async.commit_group;");
}
#define CP_WAIT(N) asm volatile("cp.async.wait_group %0;" :: "n"(N))
__device__ __forceinline__ void ldmx4(uint32_t r[4], uint32_t a) {
    asm volatile("ldmatrix.sync.aligned.m8n8.x4.shared.b16 {%0,%1,%2,%3}, [%4];"
                 : "=r"(r[0]), "=r"(r[1]), "=r"(r[2]), "=r"(r[3]) : "r"(a));
}
__device__ __forceinline__ void mma16816(float c[4], const uint32_t a[4],
                                         uint32_t b0, uint32_t b1) {
    asm volatile(
        "mma.sync.aligned.m16n8k16.row.col.f32.bf16.bf16.f32 "
        "{%0,%1,%2,%3}, {%4,%5,%6,%7}, {%8,%9}, {%0,%1,%2,%3};"
        : "+f"(c[0]), "+f"(c[1]), "+f"(c[2]), "+f"(c[3])
        : "r"(a[0]), "r"(a[1]), "r"(a[2]), "r"(a[3]), "r"(b0), "r"(b1));
}
__device__ __forceinline__ void mma16816h(float c[4], const uint32_t a[4],
                                          uint32_t b0, uint32_t b1) {
    asm volatile(
        "mma.sync.aligned.m16n8k16.row.col.f32.f16.f16.f32 "
        "{%0,%1,%2,%3}, {%4,%5,%6,%7}, {%8,%9}, {%0,%1,%2,%3};"
        : "+f"(c[0]), "+f"(c[1]), "+f"(c[2]), "+f"(c[3])
        : "r"(a[0]), "r"(a[1]), "r"(a[2]), "r"(a[3]), "r"(b0), "r"(b1));
}
__device__ __forceinline__ void splitpair(float x, float y,
                                          uint32_t& hi, uint32_t& lo) {
    __nv_bfloat16 hx = __float2bfloat16(x), hy = __float2bfloat16(y);
    __nv_bfloat162 H; H.x = hx; H.y = hy;
    __nv_bfloat162 L = __floats2bfloat162_rn(x - __bfloat162float(hx),
                                             y - __bfloat162float(hy));
    hi = *reinterpret_cast<uint32_t*>(&H);
    lo = *reinterpret_cast<uint32_t*>(&L);
}

// ---------------- weight conversion: W (K,N) fp32 -> (N,2K) fp16 hi|lo ----------------
// glu_interleave=1: output row for orig col n is (n<N/2 ? 2n : 2(n-N/2)+1)
__global__ void convB_fp16_kernel(const float* __restrict__ W,
                                  __half* __restrict__ out, int K, int N,
                                  int glu_interleave) {
    __shared__ float t[32][33];
    int k0 = blockIdx.x * 32, n0 = blockIdx.y * 32;
    int tx = threadIdx.x, ty = threadIdx.y;   // 32 x 8
    #pragma unroll
    for (int i = ty; i < 32; i += 8)
        t[i][tx] = W[(size_t)(k0 + i) * N + n0 + tx];
    __syncthreads();
    int half_n = N >> 1;
    #pragma unroll
    for (int i = ty; i < 32; i += 8) {
        float v = t[tx][i];                   // W[k0+tx][n0+i]
        __half h = __float2half(v);
        float lo = v - __half2float(h);
        int n = n0 + i;
        int row = glu_interleave ? ((n < half_n) ? (2 * n) : (2 * (n - half_n) + 1))
                                 : n;
        size_t b = (size_t)row * (2 * K) + k0 + tx;
        out[b] = h;
        out[b + K] = __float2half(lo);
    }
}

// ---------------- warp-MMA fp16 GEMM, 2-pass split, 128x128x64 tile, 3-stage ----------------
// 256 threads, 8 warps (2m x 4n), warp tile 64x32.
// A1 (M,K) fp16 single, B2 (N,2K) fp16 hi|lo K-major.
// outmode 0: C fp32 (M,N) bias/act/scale/res.
// outmode 2: C fp16 (M,N) bias/act/scale.
// outmode 3: GLU — B cols interleaved (a,b pairs); C fp16 (M,N/2) = a*sigmoid(b),
//            bias indexed bias[col/2] (a) and bias[N/2+col/2] (b).
__global__ __launch_bounds__(256)
void hgemm_fp16(const uint16_t* __restrict__ A1,
                const uint16_t* __restrict__ B2,
                void* __restrict__ Cout, int M, int N, int K,
                const float* __restrict__ bias, const float* __restrict__ res,
                float scale, int act, int outmode) {
    extern __shared__ __align__(16) unsigned char dsm[];
    uint32_t sbase = smem_u32(dsm);

    int tid = threadIdx.x;
    int lane = tid & 31;
    int wid = tid >> 5;
    int wm = (wid >> 2) * 64;
    int wn = (wid & 3) * 32;
    int bm = blockIdx.y * 128;
    int bn = blockIdx.x * 128;

    int kpp = K >> 6;
    int nkb = 2 * kpp;

    int lr = tid >> 1;
    int lc = (tid & 1) * 4;
    int sw_r = lr & 7;

    float acc[4][4][4];
    #pragma unroll
    for (int a = 0; a < 4; a++)
        #pragma unroll
        for (int b = 0; b < 4; b++)
            #pragma unroll
            for (int c = 0; c < 4; c++) acc[a][b][c] = 0.f;

    auto issue = [&](int kb, int buf) {
        int p = kb / kpp;
        int off = (kb - p * kpp) << 6;
        const uint16_t* ag = A1 + (size_t)(bm + lr) * K + off + lc * 8;
        const uint16_t* bg = B2 + (size_t)(bn + lr) * (2 * K) + p * K + off + lc * 8;
        uint32_t abuf = sbase + buf * 32768 + lr * 128;
        uint32_t bbuf = abuf + 16384;
        #pragma unroll
        for (int j = 0; j < 4; j++) {
            uint32_t phys = (uint32_t)((lc + j) ^ sw_r) * 16;
            cpasync16(abuf + phys, ag + j * 8);
            cpasync16(bbuf + phys, bg + j * 8);
        }
        cpcommit();
    };

    issue(0, 0);
    issue(1, 1);

    int rA = lane & 15;
    int kq = lane >> 4;
    int swA = rA & 7;

    for (int kb = 0; kb < nkb; kb++) {
        if (kb + 1 < nkb) { CP_WAIT(1); } else { CP_WAIT(0); }
        __syncthreads();
        if (kb + 2 < nkb) issue(kb + 2, (kb + 2) % 3);

        uint32_t Ab = sbase + (kb % 3) * 32768;
        uint32_t Bb = Ab + 16384;

        #pragma unroll
        for (int ks = 0; ks < 4; ks++) {
            uint32_t phys = (uint32_t)(((ks * 2 + kq) ^ swA) * 16);
            uint32_t af[4][4];
            #pragma unroll
            for (int mt = 0; mt < 4; mt++)
                ldmx4(af[mt], Ab + (uint32_t)(wm + mt * 16 + rA) * 128 + phys);
            uint32_t bf[4][2];
            #pragma unroll
            for (int g = 0; g < 2; g++) {
                uint32_t r[4];
                ldmx4(r, Bb + (uint32_t)(wn + g * 16 + rA) * 128 + phys);
                bf[2 * g][0] = r[0]; bf[2 * g][1] = r[2];
                bf[2 * g + 1][0] = r[1]; bf[2 * g + 1][1] = r[3];
            }
            #pragma unroll
            for (int mt = 0; mt < 4; mt++)
                #pragma unroll
                for (int nt = 0; nt < 4; nt++)
                    mma16816h(acc[mt][nt], af[mt], bf[nt][0], bf[nt][1]);
        }
        // no trailing sync: next iteration's top barrier guards buffer reuse
    }

    int gq = lane >> 2;
    int tg = lane & 3;
    #pragma unroll
    for (int mt = 0; mt < 4; mt++) {
        #pragma unroll
        for (int nt = 0; nt < 4; nt++) {
            int row0 = bm + wm + mt * 16 + gq;
            int col = bn + wn + nt * 8 + 2 * tg;
            #pragma unroll
            for (int half = 0; half < 2; half++) {
                int row = row0 + half * 8;
                float v0 = acc[mt][nt][2 * half + 0];
                float v1 = acc[mt][nt][2 * half + 1];
                if (outmode == 3) {
                    int j = col >> 1;
                    float a = v0 + (bias ? bias[j] : 0.f);
                    float b = v1 + (bias ? bias[(N >> 1) + j] : 0.f);
                    float r = a * sigmoidf_(b);
                    ((__half*)Cout)[(size_t)row * (N >> 1) + j] = __float2half(r);
                    continue;
                }
                if (bias) { v0 += bias[col]; v1 += bias[col + 1]; }
                if (act == 1) { v0 = gelu_tanh(v0); v1 = gelu_tanh(v1); }
                v0 *= scale; v1 *= scale;
                if (outmode == 0) {
                    float* C = (float*)Cout;
                    if (res) {
                        v0 += res[(size_t)row * N + col];
                        v1 += res[(size_t)row * N + col + 1];
                    }
                    *(float2*)&C[(size_t)row * N + col] = make_float2(v0, v1);
                } else {
                    __half* C3 = (__half*)Cout;
                    __half2 hv = __floats2half2_rn(v0, v1);
                    *(uint32_t*)&C3[(size_t)row * N + col] =
                        *reinterpret_cast<uint32_t*>(&hv);
                }
            }
        }
    }
}

// ---------------- rmsnorm fp32 out (final) ----------------
__global__ void rmsnorm_kernel(const float* __restrict__ x,
                               const float* __restrict__ w,
                               float* __restrict__ y) {
    int row = blockIdx.x;
    const float* xr = x + (size_t)row * DM;
    float ss = 0.f;
    for (int i = threadIdx.x; i < DM; i += blockDim.x) {
        float v = xr[i];
        ss += v * v;
    }
    #pragma unroll
    for (int o = 16; o > 0; o >>= 1) ss += __shfl_xor_sync(0xffffffffu, ss, o);
    __shared__ float red[8];
    if ((threadIdx.x & 31) == 0) red[threadIdx.x >> 5] = ss;
    __syncthreads();
    __shared__ float s_r;
    if (threadIdx.x == 0) {
        float t = 0.f;
        #pragma unroll
        for (int i = 0; i < 8; i++) t += red[i];
        s_r = rsqrtf(t / (float)DM + EPSF);
    }
    __syncthreads();
    float r = s_r;
    float* yr = y + (size_t)row * DM;
    for (int i = threadIdx.x; i < DM; i += blockDim.x)
        yr[i] = xr[i] * r * w[i];
}

// ---------------- rmsnorm -> fp16 single ----------------
__global__ void rmsnorm_fp16_kernel(const float* __restrict__ x,
                                    const float* __restrict__ w,
                                    __half* __restrict__ y) {
    int row = blockIdx.x;
    const float* xr = x + (size_t)row * DM;
    float ss = 0.f;
    for (int i = threadIdx.x; i < DM; i += blockDim.x) {
        float v = xr[i];
        ss += v * v;
    }
    #pragma unroll
    for (int o = 16; o > 0; o >>= 1) ss += __shfl_xor_sync(0xffffffffu, ss, o);
    __shared__ float red[8];
    if ((threadIdx.x & 31) == 0) red[threadIdx.x >> 5] = ss;
    __syncthreads();
    __shared__ float s_r;
    if (threadIdx.x == 0) {
        float t = 0.f;
        #pragma unroll
        for (int i = 0; i < 8; i++) t += red[i];
        s_r = rsqrtf(t / (float)DM + EPSF);
    }
    __syncthreads();
    float r = s_r;
    __half* yr = y + (size_t)row * DM;
    for (int i = threadIdx.x; i < DM; i += blockDim.x)
        yr[i] = __float2half(xr[i] * r * w[i]);
}

// ---------------- qkv postproc: head rmsnorm + rope + split outputs ----------------
__global__ __launch_bounds__(128)
void qkv_post_kernel(const float* __restrict__ qkv,
                     const float* __restrict__ qnw, const float* __restrict__ knw,
                     __nv_bfloat16* __restrict__ Qh, __nv_bfloat16* __restrict__ Ql,
                     __nv_bfloat16* __restrict__ Kh, __nv_bfloat16* __restrict__ Kl,
                     __nv_bfloat16* __restrict__ Vth, __nv_bfloat16* __restrict__ Vtl,
                     float* __restrict__ kv_out) {
    int w = blockIdx.x * 4 + (threadIdx.x >> 5);
    int lane = threadIdx.x & 31;
    int h = w % NH;
    int tok = w / NH;
    int b = tok / SEQ;
    int n = tok % SEQ;

    const float* base = qkv + (size_t)tok * (3 * NH * HD) + h * (HD * 3);
    float q1 = base[lane * 3 + 0], q2 = base[(lane + 32) * 3 + 0];
    float k1 = base[lane * 3 + 1], k2 = base[(lane + 32) * 3 + 1];
    float v1 = base[lane * 3 + 2], v2 = base[(lane + 32) * 3 + 2];

    float sq = q1 * q1 + q2 * q2;
    #pragma unroll
    for (int o = 16; o > 0; o >>= 1) sq += __shfl_xor_sync(0xffffffffu, sq, o);
    float rq = rsqrtf(sq / 64.f + EPSF);
    q1 *= rq * qnw[lane]; q2 *= rq * qnw[lane + 32];

    float sk = k1 * k1 + k2 * k2;
    #pragma unroll
    for (int o = 16; o > 0; o >>= 1) sk += __shfl_xor_sync(0xffffffffu, sk, o);
    float rk = rsqrtf(sk / 64.f + EPSF);
    k1 *= rk * knw[lane]; k2 *= rk * knw[lane + 32];

    int t = CACHE_T + n;
    size_t kb = ((((size_t)b * KVLEN + t) * 2 + 0) * NH + h) * HD;
    kv_out[kb + lane] = k1;
    kv_out[kb + lane + 32] = k2;
    kv_out[kb + NH * HD + lane] = v1;
    kv_out[kb + NH * HD + lane + 32] = v2;

    float inv = 1.0f / powf(10000.0f, (float)lane / 32.0f);
    float ang = (float)t * inv;
    float c = cosf(ang), s = sinf(ang);

    int bh = b * NH + h;
    float qa = (q1 * c - q2 * s) * 0.125f;
    float qb2 = (q2 * c + q1 * s) * 0.125f;
    size_t qoff = ((size_t)bh * SEQ + n) * HD;
    {
        __nv_bfloat16 h1 = __float2bfloat16(qa);
        __nv_bfloat16 h2 = __float2bfloat16(qb2);
        Qh[qoff + lane] = h1;
        Qh[qoff + lane + 32] = h2;
        Ql[qoff + lane] = __float2bfloat16(qa - __bfloat162float(h1));
        Ql[qoff + lane + 32] = __float2bfloat16(qb2 - __bfloat162float(h2));
    }
    float ka = k1 * c - k2 * s;
    float kb2 = k2 * c + k1 * s;
    size_t koff = ((size_t)bh * KVLEN + t) * HD;
    {
        __nv_bfloat16 h1 = __float2bfloat16(ka);
        __nv_bfloat16 h2 = __float2bfloat16(kb2);
        Kh[koff + lane] = h1;
        Kh[koff + lane + 32] = h2;
        Kl[koff + lane] = __float2bfloat16(ka - __bfloat162float(h1));
        Kl[koff + lane + 32] = __float2bfloat16(kb2 - __bfloat162float(h2));
    }
    size_t voff = ((size_t)bh * HD) * KVLEN + t;
    {
        __nv_bfloat16 h1 = __float2bfloat16(v1);
        __nv_bfloat16 h2 = __float2bfloat16(v2);
        Vth[voff + (size_t)lane * KVLEN] = h1;
        Vth[voff + (size_t)(lane + 32) * KVLEN] = h2;
        Vtl[voff + (size_t)lane * KVLEN] = __float2bfloat16(v1 - __bfloat162float(h1));
        Vtl[voff + (size_t)(lane + 32) * KVLEN] = __float2bfloat16(v2 - __bfloat162float(h2));
    }
}

// ---------------- cached tokens: copy + rope + split ----------------
__global__ __launch_bounds__(128)
void cache_kernel(const float* __restrict__ cached,
                  __nv_bfloat16* __restrict__ Kh, __nv_bfloat16* __restrict__ Kl,
                  __nv_bfloat16* __restrict__ Vth, __nv_bfloat16* __restrict__ Vtl,
                  float* __restrict__ kv_out) {
    int w = blockIdx.x * 4 + (threadIdx.x >> 5);
    int lane = threadIdx.x & 31;
    int h = w % NH;
    int bt = w / NH;
    int b = bt / CACHE_T;
    int t = bt % CACHE_T;

    size_t src = ((((size_t)b * CACHE_T + t) * 2 + 0) * NH + h) * HD;
    float k1 = cached[src + lane], k2 = cached[src + lane + 32];
    float v1 = cached[src + NH * HD + lane], v2 = cached[src + NH * HD + lane + 32];

    size_t dst = ((((size_t)b * KVLEN + t) * 2 + 0) * NH + h) * HD;
    kv_out[dst + lane] = k1;
    kv_out[dst + lane + 32] = k2;
    kv_out[dst + NH * HD + lane] = v1;
    kv_out[dst + NH * HD + lane + 32] = v2;

    float inv = 1.0f / powf(10000.0f, (float)lane / 32.0f);
    float ang = (float)t * inv;
    float c = cosf(ang), s = sinf(ang);
    float ka = k1 * c - k2 * s;
    float kb2 = k2 * c + k1 * s;

    int bh = b * NH + h;
    size_t koff = ((size_t)bh * KVLEN + t) * HD;
    {
        __nv_bfloat16 h1 = __float2bfloat16(ka);
        __nv_bfloat16 h2 = __float2bfloat16(kb2);
        Kh[koff + lane] = h1;
        Kh[koff + lane + 32] = h2;
        Kl[koff + lane] = __float2bfloat16(ka - __bfloat162float(h1));
        Kl[koff + lane + 32] = __float2bfloat16(kb2 - __bfloat162float(h2));
    }
    size_t voff = ((size_t)bh * HD) * KVLEN + t;
    {
        __nv_bfloat16 h1 = __float2bfloat16(v1);
        __nv_bfloat16 h2 = __float2bfloat16(v2);
        Vth[voff + (size_t)lane * KVLEN] = h1;
        Vth[voff + (size_t)(lane + 32) * KVLEN] = h2;
        Vtl[voff + (size_t)lane * KVLEN] = __float2bfloat16(v1 - __bfloat162float(h1));
        Vtl[voff + (size_t)(lane + 32) * KVLEN] = __float2bfloat16(v2 - __bfloat162float(h2));
    }
}

// ---------------- attention: MMA flash, 64 q-rows/block, 64-key chunks ----------------
#define AT_STAGE 32768
__global__ __launch_bounds__(128)
void attn_mma(const __nv_bfloat16* __restrict__ Qh, const __nv_bfloat16* __restrict__ Ql,
              const __nv_bfloat16* __restrict__ Kh, const __nv_bfloat16* __restrict__ Kl,
              const __nv_bfloat16* __restrict__ Vth, const __nv_bfloat16* __restrict__ Vtl,
              __half* __restrict__ Oh) {
    extern __shared__ __align__(16) unsigned char dsm[];
    uint32_t sbase = smem_u32(dsm);
    uint32_t qarea = sbase + 2 * AT_STAGE;

    int tid = threadIdx.x, lane = tid & 31, wid = tid >> 5;
    int bh = blockIdx.y;
    int b = bh / NH, h = bh % NH;
    int q0 = blockIdx.x * 64;

    size_t qoff = ((size_t)bh * SEQ + q0) * HD;
    size_t koff = (size_t)bh * KVLEN * HD;
    size_t voff = (size_t)bh * HD * KVLEN;

    int lr = tid >> 1;
    int lc4 = (tid & 1) * 4;

    {
        const __nv_bfloat16* qhg = Qh + qoff + lr * HD;
        const __nv_bfloat16* qlg = Ql + qoff + lr * HD;
        #pragma unroll
        for (int j = 0; j < 4; j++) {
            int ch = lc4 + j;
            uint32_t phys = (uint32_t)((ch ^ (lr & 7)) * 16);
            cpasync16(qarea + lr * 128 + phys, qhg + ch * 8);
            cpasync16(qarea + 8192 + lr * 128 + phys, qlg + ch * 8);
        }
        cpcommit();
    }

    auto issueKV = [&](int c, int buf) {
        uint32_t dst = sbase + buf * AT_STAGE + lr * 128;
        const __nv_bfloat16* khg = Kh + koff + (size_t)(c * 64 + lr) * HD;
        const __nv_bfloat16* klg = Kl + koff + (size_t)(c * 64 + lr) * HD;
        const __nv_bfloat16* vhg = Vth + voff + (size_t)lr * KVLEN + c * 64;
        const __nv_bfloat16* vlg = Vtl + voff + (size_t)lr * KVLEN + c * 64;
        #pragma unroll
        for (int j = 0; j < 4; j++) {
            int ch = lc4 + j;
            uint32_t phys = (uint32_t)((ch ^ (lr & 7)) * 16);
            cpasync16(dst + phys, khg + ch * 8);
            cpasync16(dst + 8192 + phys, klg + ch * 8);
            cpasync16(dst + 16384 + phys, vhg + ch * 8);
            cpasync16(dst + 24576 + phys, vlg + ch * 8);
        }
        cpcommit();
    };

    issueKV(0, 0);
    CP_WAIT(1);
    __syncthreads();

    int rA = lane & 15, kq = lane >> 4;
    int qrow = wid * 16 + rA;
    int qs = qrow & 7;
    uint32_t qfh[4][4], qfl[4][4];
    #pragma unroll
    for (int kt = 0; kt < 4; kt++) {
        uint32_t phys = (uint32_t)(((kt * 2 + kq) ^ qs) * 16);
        ldmx4(qfh[kt], qarea + qrow * 128 + phys);
        ldmx4(qfl[kt], qarea + 8192 + qrow * 128 + phys);
    }

    int gq = lane >> 2, tg = lane & 3;
    float m0 = -1e30f, m1 = -1e30f, l0 = 0.f, l1 = 0.f;
    float O[8][4];
    #pragma unroll
    for (int nt = 0; nt < 8; nt++)
        #pragma unroll
        for (int i = 0; i < 4; i++) O[nt][i] = 0.f;

    const int NCH = KVLEN / 64;
    for (int c = 0; c < NCH; c++) {
        if (c + 1 < NCH) { issueKV(c + 1, (c + 1) & 1); CP_WAIT(1); }
        else { CP_WAIT(0); }
        __syncthreads();

        uint32_t bufK = sbase + (c & 1) * AT_STAGE;
        uint32_t bufV = bufK + 16384;

        float S[8][4];
        #pragma unroll
        for (int nt = 0; nt < 8; nt++)
            #pragma unroll
            for (int i = 0; i < 4; i++) S[nt][i] = 0.f;

        #pragma unroll
        for (int kt = 0; kt < 4; kt++) {
            uint32_t kfh[4][4], kfl[4][4];
            #pragma unroll
            for (int g2 = 0; g2 < 4; g2++) {
                int krow = g2 * 16 + rA;
                uint32_t phys = (uint32_t)(((kt * 2 + kq) ^ (krow & 7)) * 16);
                ldmx4(kfh[g2], bufK + krow * 128 + phys);
                ldmx4(kfl[g2], bufK + 8192 + krow * 128 + phys);
            }
            #pragma unroll
            for (int g2 = 0; g2 < 4; g2++)
                #pragma unroll
                for (int hf = 0; hf < 2; hf++) {
                    int nt = 2 * g2 + hf;
                    mma16816(S[nt], qfh[kt], kfh[g2][hf], kfh[g2][hf + 2]);
                    mma16816(S[nt], qfh[kt], kfl[g2][hf], kfl[g2][hf + 2]);
                    mma16816(S[nt], qfl[kt], kfh[g2][hf], kfh[g2][hf + 2]);
                }
        }

        float mx0 = -1e30f, mx1 = -1e30f;
        #pragma unroll
        for (int nt = 0; nt < 8; nt++) {
            mx0 = fmaxf(mx0, fmaxf(S[nt][0], S[nt][1]));
            mx1 = fmaxf(mx1, fmaxf(S[nt][2], S[nt][3]));
        }
        mx0 = fmaxf(mx0, __shfl_xor_sync(0xffffffffu, mx0, 1));
        mx0 = fmaxf(mx0, __shfl_xor_sync(0xffffffffu, mx0, 2));
        mx1 = fmaxf(mx1, __shfl_xor_sync(0xffffffffu, mx1, 1));
        mx1 = fmaxf(mx1, __shfl_xor_sync(0xffffffffu, mx1, 2));
        float nm0 = fmaxf(m0, mx0), nm1 = fmaxf(m1, mx1);
        float a0 = __expf(m0 - nm0), a1 = __expf(m1 - nm1);

        float rs0 = 0.f, rs1 = 0.f;
        #pragma unroll
        for (int nt = 0; nt < 8; nt++) {
            S[nt][0] = __expf(S[nt][0] - nm0);
            S[nt][1] = __expf(S[nt][1] - nm0);
            S[nt][2] = __expf(S[nt][2] - nm1);
            S[nt][3] = __expf(S[nt][3] - nm1);
            rs0 += S[nt][0] + S[nt][1];
            rs1 += S[nt][2] + S[nt][3];
        }
        rs0 += __shfl_xor_sync(0xffffffffu, rs0, 1);
        rs0 += __shfl_xor_sync(0xffffffffu, rs0, 2);
        rs1 += __shfl_xor_sync(0xffffffffu, rs1, 1);
        rs1 += __shfl_xor_sync(0xffffffffu, rs1, 2);
        l0 = l0 * a0 + rs0;
        l1 = l1 * a1 + rs1;
        m0 = nm0; m1 = nm1;
        #pragma unroll
        for (int nt = 0; nt < 8; nt++) {
            O[nt][0] *= a0; O[nt][1] *= a0;
            O[nt][2] *= a1; O[nt][3] *= a1;
        }

        #pragma unroll
        for (int kt = 0; kt < 4; kt++) {
            uint32_t ah[4], al[4];
            splitpair(S[2 * kt][0], S[2 * kt][1], ah[0], al[0]);
            splitpair(S[2 * kt][2], S[2 * kt][3], ah[1], al[1]);
            splitpair(S[2 * kt + 1][0], S[2 * kt + 1][1], ah[2], al[2]);
            splitpair(S[2 * kt + 1][2], S[2 * kt + 1][3], ah[3], al[3]);
            uint32_t vfh[4][4], vfl[4][4];
            #pragma unroll
            for (int g2 = 0; g2 < 4; g2++) {
                int vrow = g2 * 16 + rA;
                uint32_t phys = (uint32_t)(((kt * 2 + kq) ^ (vrow & 7)) * 16);
                ldmx4(vfh[g2], bufV + vrow * 128 + phys);
                ldmx4(vfl[g2], bufV + 8192 + vrow * 128 + phys);
            }
            #pragma unroll
            for (int g2 = 0; g2 < 4; g2++)
                #pragma unroll
                for (int hf = 0; hf < 2; hf++) {
                    int nt = 2 * g2 + hf;
                    mma16816(O[nt], ah, vfh[g2][hf], vfh[g2][hf + 2]);
                    mma16816(O[nt], ah, vfl[g2][hf], vfl[g2][hf + 2]);
                    mma16816(O[nt], al, vfh[g2][hf], vfh[g2][hf + 2]);
                }
        }
        __syncthreads();
    }

    float inv0 = 1.0f / l0, inv1 = 1.0f / l1;
    int r0 = q0 + wid * 16 + gq;
    size_t tok0 = (size_t)(b * SEQ + r0);
    size_t tok1 = tok0 + 8;
    #pragma unroll
    for (int nt = 0; nt < 8; nt++) {
        int col = h * HD + nt * 8 + 2 * tg;
        __half2 h0 = __floats2half2_rn(O[nt][0] * inv0, O[nt][1] * inv0);
        __half2 h1 = __floats2half2_rn(O[nt][2] * inv1, O[nt][3] * inv1);
        *(uint32_t*)&Oh[tok0 * DM + col] = *reinterpret_cast<uint32_t*>(&h0);
        *(uint32_t*)&Oh[tok1 * DM + col] = *reinterpret_cast<uint32_t*>(&h1);
    }
}

// ---------------- depthwise conv (fp16 input, fp32 out) ----------------
__global__ void dwconv_kernel(const __half* __restrict__ in,
                              const float* __restrict__ w,
                              const float* __restrict__ bias,
                              float* __restrict__ out) {
    int i = blockIdx.x * blockDim.x + threadIdx.x;
    if (i >= NTOK * DM) return;
    int c = i % DM;
    int pos = i / DM;
    int n = pos % SEQ;
    int b = pos / SEQ;
    float acc = bias[c];
    #pragma unroll
    for (int k = 0; k < KSZ; k++) {
        int nn = n - (KSZ / 2) + k;
        if (nn >= 0 && nn < SEQ)
            acc = fmaf(__half2float(in[((size_t)b * SEQ + nn) * DM + c]),
                       w[c * KSZ + k], acc);
    }
    out[i] = acc;
}

// ---------------- batchnorm stats ----------------
__global__ void bnstats_kernel(const float* __restrict__ in,
                               float* __restrict__ mean, float* __restrict__ var) {
    int c = blockIdx.x;
    float s = 0.f, ss = 0.f;
    for (int r = threadIdx.x; r < NTOK; r += blockDim.x) {
        float v = in[(size_t)r * DM + c];
        s += v;
        ss += v * v;
    }
    #pragma unroll
    for (int o = 16; o > 0; o >>= 1) {
        s += __shfl_xor_sync(0xffffffffu, s, o);
        ss += __shfl_xor_sync(0xffffffffu, ss, o);
    }
    __shared__ float rs[8], rss[8];
    if ((threadIdx.x & 31) == 0) {
        rs[threadIdx.x >> 5] = s;
        rss[threadIdx.x >> 5] = ss;
    }
    __syncthreads();
    if (threadIdx.x == 0) {
        float ts = 0.f, tss = 0.f;
        #pragma unroll
        for (int i = 0; i < 8; i++) { ts += rs[i]; tss += rss[i]; }
        float m = ts / (float)NTOK;
        mean[c] = m;
        var[c] = tss / (float)NTOK - m * m;
    }
}

// ---------------- bn apply + swish -> fp16 single ----------------
__global__ void bnapply_fp16_kernel(const float* __restrict__ in,
                                    const float* __restrict__ mean, const float* __restrict__ var,
                                    const float* __restrict__ g, const float* __restrict__ be,
                                    __half* __restrict__ out) {
    int i = blockIdx.x * blockDim.x + threadIdx.x;
    if (i >= NTOK * DM) return;
    int c = i % DM;
    float y = (in[i] - mean[c]) * rsqrtf(var[c] + EPSF) * g[c] + be[c];
    y = y * sigmoidf_(y);
    out[i] = __float2half(y);
}

// ---------------- host-side helpers ----------------
static __nv_bfloat16* s_b2 = nullptr;

static void tc_gemm_fp16(const __half* A1, const float* W, void* C,
                         int M, int N, int K,
                         const float* bias, const float* res, float scale, int act,
                         int outmode) {
    convB_fp16_kernel<<<dim3(K / 32, N / 32), dim3(32, 8)>>>(
        W, (__half*)s_b2, K, N, outmode == 3 ? 1 : 0);
    hgemm_fp16<<<dim3(N / 128, M / 128), 256, 98304>>>(
        (const uint16_t*)A1, (const uint16_t*)s_b2, C, M, N, K,
        bias, res, scale, act, outmode);
}

extern "C" void kernel_launch(void* const* d_in, const int* in_sizes, int n_in,
                              void* d_out, int out_size) {
    (void)in_sizes; (void)n_in; (void)out_size;
    const float* x          = (const float*)d_in[0];
    const float* cached_kv  = (const float*)d_in[4];
    const float* ff1_norm_w = (const float*)d_in[5];
    const float* ff1_w1     = (const float*)d_in[6];
    const float* ff1_b1     = (const float*)d_in[7];
    const float* ff1_w2     = (const float*)d_in[8];
    const float* ff1_b2     = (const float*)d_in[9];
    const float* attn_norm_w= (const float*)d_in[10];
    const float* qkv_w      = (const float*)d_in[11];
    const float* out_w      = (const float*)d_in[12];
    const float* q_norm_w   = (const float*)d_in[13];
    const float* k_norm_w   = (const float*)d_in[14];
    const float* conv_norm_w= (const float*)d_in[15];
    const float* pw1_w      = (const float*)d_in[16];
    const float* pw1_b      = (const float*)d_in[17];
    const float* dw_w       = (const float*)d_in[18];
    const float* dw_b       = (const float*)d_in[19];
    const float* bn_g       = (const float*)d_in[20];
    const float* bn_b       = (const float*)d_in[21];
    const float* pw2_w      = (const float*)d_in[22];
    const float* pw2_b      = (const float*)d_in[23];
    const float* ff2_norm_w = (const float*)d_in[24];
    const float* ff2_w1     = (const float*)d_in[25];
    const float* ff2_b1     = (const float*)d_in[26];
    const float* ff2_w2     = (const float*)d_in[27];
    const float* ff2_b2     = (const float*)d_in[28];
    const float* out_norm_w = (const float*)d_in[29];

    float* out_x  = (float*)d_out;
    float* out_kv = out_x + (size_t)NTOK * DM;

    float *gX1, *gX2, *gQKV, *gT, *gC, *gM, *gV;
    __nv_bfloat16 *gA2, *gAH, *gQh, *gQl, *gKh, *gKl, *gVth, *gVtl;
    cudaGetSymbolAddress((void**)&gX1,  g_x1);
    cudaGetSymbolAddress((void**)&gX2,  g_x2);
    cudaGetSymbolAddress((void**)&gQKV, g_qkv);
    cudaGetSymbolAddress((void**)&gT,   g_tmp);
    cudaGetSymbolAddress((void**)&gC,   g_conv);
    cudaGetSymbolAddress((void**)&gM,   g_mean);
    cudaGetSymbolAddress((void**)&gV,   g_var);
    cudaGetSymbolAddress((void**)&gA2,  g_a2);
    cudaGetSymbolAddress((void**)&gAH,  g_ah);
    cudaGetSymbolAddress((void**)&s_b2, g_b2);
    cudaGetSymbolAddress((void**)&gQh,  g_qh);
    cudaGetSymbolAddress((void**)&gQl,  g_ql);
    cudaGetSymbolAddress((void**)&gKh,  g_kh);
    cudaGetSymbolAddress((void**)&gKl,  g_kl);
    cudaGetSymbolAddress((void**)&gVth, g_vth);
    cudaGetSymbolAddress((void**)&gVtl, g_vtl);

    __half* gF16 = (__half*)gA2;     // fp16 GEMM input (M, DM)
    __half* gH16 = (__half*)gAH;     // fp16 FF intermediate (M, FFD)
    __half* gT16 = (__half*)gT;      // fp16 GLU output (M, DM)

    cudaFuncSetAttribute(hgemm_fp16, cudaFuncAttributeMaxDynamicSharedMemorySize, 98304);
    cudaFuncSetAttribute(attn_mma, cudaFuncAttributeMaxDynamicSharedMemorySize, 81920);

    const int EW_BLOCKS = (NTOK * DM + 255) / 256;

    // ---- FF1 ----
    rmsnorm_fp16_kernel<<<NTOK, 256>>>(x, ff1_norm_w, gF16);
    tc_gemm_fp16(gF16, ff1_w1, gH16, NTOK, FFD, DM, ff1_b1, nullptr, 1.0f, 1, 2);
    tc_gemm_fp16(gH16, ff1_w2, gX1, NTOK, DM, FFD, ff1_b2, x, 0.5f, 0, 0);

    // ---- Attention (fully fp16 2-term GEMMs; attn core stays bf16 split) ----
    rmsnorm_fp16_kernel<<<NTOK, 256>>>(gX1, attn_norm_w, gF16);
    tc_gemm_fp16(gF16, qkv_w, gQKV, NTOK, 3 * NH * HD, DM, nullptr, nullptr, 1.0f, 0, 0);
    qkv_post_kernel<<<NTOK * NH / 4, 128>>>(gQKV, q_norm_w, k_norm_w,
                                            gQh, gQl, gKh, gKl, gVth, gVtl, out_kv);
    cache_kernel<<<BSZ * CACHE_T * NH / 4, 128>>>(cached_kv, gKh, gKl, gVth, gVtl, out_kv);
    attn_mma<<<dim3(SEQ / 64, BSZ * NH), 128, 81920>>>(gQh, gQl, gKh, gKl, gVth, gVtl, gF16);
    tc_gemm_fp16(gF16, out_w, gX2, NTOK, DM, DM, nullptr, gX1, 1.0f, 0, 0);

    // ---- Conv module (GLU fused into pw1 epilogue) ----
    rmsnorm_fp16_kernel<<<NTOK, 256>>>(gX2, conv_norm_w, gF16);
    tc_gemm_fp16(gF16, pw1_w, gT16, NTOK, 2 * DM, DM, pw1_b, nullptr, 1.0f, 0, 3);
    dwconv_kernel<<<EW_BLOCKS, 256>>>(gT16, dw_w, dw_b, gC);
    bnstats_kernel<<<DM, 256>>>(gC, gM, gV);
    bnapply_fp16_kernel<<<EW_BLOCKS, 256>>>(gC, gM, gV, bn_g, bn_b, gF16);
    tc_gemm_fp16(gF16, pw2_w, gX1, NTOK, DM, DM, pw2_b, nullptr, 1.0f, 0, 0);

    // ---- FF2 ----
    rmsnorm_fp16_kernel<<<NTOK, 256>>>(gX1, ff2_norm_w, gF16);
    tc_gemm_fp16(gF16, ff2_w1, gH16, NTOK, FFD, DM, ff2_b1, nullptr, 1.0f, 1, 2);
    tc_gemm_fp16(gH16, ff2_w2, gX2, NTOK, DM, FFD, ff2_b2, gX1, 0.5f, 0, 0);

    // ---- final norm ----
    rmsnorm_kernel<<<NTOK, 256>>>(gX2, out_norm_w, out_x);
}

// round 12
// speedup vs baseline: 2.8213x; 1.0952x over previous
#include <cuda_runtime.h>
#include <cuda_bf16.h>
#include <cuda_fp16.h>
#include <math.h>
#include <stdint.h>

// ---------------- problem constants ----------------
#define BSZ      2
#define SEQ      2048
#define NTOK     4096          // B*N
#define CACHE_T  512
#define KVLEN    2560
#define DM       768
#define NH       12
#define HD       64
#define FFD      3072
#define KSZ      31
#define EPSF     1e-5f

// ---------------- scratch (device globals; no allocation) ----------------
__device__ __align__(128) float g_x1[NTOK * DM];
__device__ __align__(128) float g_x2[NTOK * DM];
__device__ __align__(128) float g_qkv[NTOK * 3 * NH * HD];
__device__ __align__(128) float g_tmp[NTOK * DM];            // also __half reuse
__device__ __align__(128) float g_conv[NTOK * DM];
__device__ float g_mean[DM];
__device__ float g_var[DM];
__device__ __align__(128) __nv_bfloat16 g_a2[NTOK * 2 * DM];             // fp16 GEMM input reuse
__device__ __align__(128) __nv_bfloat16 g_ah[(size_t)NTOK * 2 * FFD];    // FF intermediate (fp16 reuse)
__device__ __align__(128) __nv_bfloat16 g_b2[(size_t)FFD * 2 * DM];      // weights (N,2K)
__device__ __align__(128) __nv_bfloat16 g_qh[BSZ * NH * SEQ * HD];
__device__ __align__(128) __nv_bfloat16 g_ql[BSZ * NH * SEQ * HD];
__device__ __align__(128) __nv_bfloat16 g_kh[BSZ * NH * KVLEN * HD];
__device__ __align__(128) __nv_bfloat16 g_kl[BSZ * NH * KVLEN * HD];
__device__ __align__(128) __nv_bfloat16 g_vth[BSZ * NH * HD * KVLEN];    // (b,h,d,t)
__device__ __align__(128) __nv_bfloat16 g_vtl[BSZ * NH * HD * KVLEN];

// ---------------- helpers ----------------
__device__ __forceinline__ float gelu_tanh(float x) {
    const float c = 0.7978845608028654f;
    float t = tanhf(c * (x + 0.044715f * x * x * x));
    return 0.5f * x * (1.0f + t);
}
__device__ __forceinline__ float sigmoidf_(float x) {
    return 1.0f / (1.0f + expf(-x));
}
__device__ __forceinline__ uint32_t smem_u32(const void* p) {
    uint32_t a;
    asm("{ .reg .u64 t; cvta.to.shared.u64 t, %1; cvt.u32.u64 %0, t; }"
        : "=r"(a) : "l"(p));
    return a;
}
__device__ __forceinline__ void cpasync16(uint32_t dst, const void* src) {
    asm volatile("cp.async.cg.shared.global [%0], [%1], 16;" :: "r"(dst), "l"(src));
}
__device__ __forceinline__ void cpcommit() {
    asm volatile("cp.async.commit_group;");
}
#define CP_WAIT(N) asm volatile("cp.async.wait_group %0;" :: "n"(N))
__device__ __forceinline__ void ldmx4(uint32_t r[4], uint32_t a) {
    asm volatile("ldmatrix.sync.aligned.m8n8.x4.shared.b16 {%0,%1,%2,%3}, [%4];"
                 : "=r"(r[0]), "=r"(r[1]), "=r"(r[2]), "=r"(r[3]) : "r"(a));
}
__device__ __forceinline__ void mma16816(float c[4], const uint32_t a[4],
                                         uint32_t b0, uint32_t b1) {
    asm volatile(
        "mma.sync.aligned.m16n8k16.row.col.f32.bf16.bf16.f32 "
        "{%0,%1,%2,%3}, {%4,%5,%6,%7}, {%8,%9}, {%0,%1,%2,%3};"
        : "+f"(c[0]), "+f"(c[1]), "+f"(c[2]), "+f"(c[3])
        : "r"(a[0]), "r"(a[1]), "r"(a[2]), "r"(a[3]), "r"(b0), "r"(b1));
}
__device__ __forceinline__ void mma16816h(float c[4], const uint32_t a[4],
                                          uint32_t b0, uint32_t b1) {
    asm volatile(
        "mma.sync.aligned.m16n8k16.row.col.f32.f16.f16.f32 "
        "{%0,%1,%2,%3}, {%4,%5,%6,%7}, {%8,%9}, {%0,%1,%2,%3};"
        : "+f"(c[0]), "+f"(c[1]), "+f"(c[2]), "+f"(c[3])
        : "r"(a[0]), "r"(a[1]), "r"(a[2]), "r"(a[3]), "r"(b0), "r"(b1));
}
__device__ __forceinline__ void splitpair(float x, float y,
                                          uint32_t& hi, uint32_t& lo) {
    __nv_bfloat16 hx = __float2bfloat16(x), hy = __float2bfloat16(y);
    __nv_bfloat162 H; H.x = hx; H.y = hy;
    __nv_bfloat162 L = __floats2bfloat162_rn(x - __bfloat162float(hx),
                                             y - __bfloat162float(hy));
    hi = *reinterpret_cast<uint32_t*>(&H);
    lo = *reinterpret_cast<uint32_t*>(&L);
}

// ---------------- weight conversion: W (K,N) fp32 -> (N,2K) fp16 hi|lo ----------------
// glu_interleave=1: output row for orig col n is (n<N/2 ? 2n : 2(n-N/2)+1)
__global__ void convB_fp16_kernel(const float* __restrict__ W,
                                  __half* __restrict__ out, int K, int N,
                                  int glu_interleave) {
    __shared__ float t[32][33];
    int k0 = blockIdx.x * 32, n0 = blockIdx.y * 32;
    int tx = threadIdx.x, ty = threadIdx.y;   // 32 x 8
    #pragma unroll
    for (int i = ty; i < 32; i += 8)
        t[i][tx] = W[(size_t)(k0 + i) * N + n0 + tx];
    __syncthreads();
    int half_n = N >> 1;
    #pragma unroll
    for (int i = ty; i < 32; i += 8) {
        float v = t[tx][i];                   // W[k0+tx][n0+i]
        __half h = __float2half(v);
        float lo = v - __half2float(h);
        int n = n0 + i;
        int row = glu_interleave ? ((n < half_n) ? (2 * n) : (2 * (n - half_n) + 1))
                                 : n;
        size_t b = (size_t)row * (2 * K) + k0 + tx;
        out[b] = h;
        out[b + K] = __float2half(lo);
    }
}

// ---------------- warp-MMA fp16 GEMM, fused hi/lo, 128x128x64 tile, 2-stage ----------------
// 256 threads, 8 warps (2m x 4n), warp tile 64x32.
// A1 (M,K) fp16 single, B2 (N,2K) fp16 hi|lo K-major.
// Per physical k-block: stage [A | Bhi | Blo] (48KB); A fragments loaded ONCE and
// multiplied against both B tiles (saves 1/3 of ldmatrix + 25% of load traffic).
// outmode 0: C fp32 (M,N) bias/act/scale/res.
// outmode 2: C fp16 (M,N) bias/act/scale.
// outmode 3: GLU — B cols interleaved (a,b pairs); C fp16 (M,N/2) = a*sigmoid(b),
//            bias indexed bias[col/2] (a) and bias[N/2+col/2] (b).
__global__ __launch_bounds__(256)
void hgemm_fp16(const uint16_t* __restrict__ A1,
                const uint16_t* __restrict__ B2,
                void* __restrict__ Cout, int M, int N, int K,
                const float* __restrict__ bias, const float* __restrict__ res,
                float scale, int act, int outmode) {
    extern __shared__ __align__(16) unsigned char dsm[];
    uint32_t sbase = smem_u32(dsm);

    int tid = threadIdx.x;
    int lane = tid & 31;
    int wid = tid >> 5;
    int wm = (wid >> 2) * 64;
    int wn = (wid & 3) * 32;
    int bm = blockIdx.y * 128;
    int bn = blockIdx.x * 128;

    int nkb = K >> 6;             // physical 64-wide k-blocks

    int lr = tid >> 1;
    int lc = (tid & 1) * 4;
    int sw_r = lr & 7;

    float acc[4][4][4];
    #pragma unroll
    for (int a = 0; a < 4; a++)
        #pragma unroll
        for (int b = 0; b < 4; b++)
            #pragma unroll
            for (int c = 0; c < 4; c++) acc[a][b][c] = 0.f;

    // stage layout: [A 16KB | Bhi 16KB | Blo 16KB] x 2 stages = 96KB
    auto issue = [&](int kb, int buf) {
        int off = kb << 6;
        const uint16_t* ag  = A1 + (size_t)(bm + lr) * K + off + lc * 8;
        const uint16_t* bgh = B2 + (size_t)(bn + lr) * (2 * K) + off + lc * 8;
        const uint16_t* bgl = bgh + K;
        uint32_t abuf = sbase + buf * 49152 + lr * 128;
        uint32_t hbuf = abuf + 16384;
        uint32_t lbuf = abuf + 32768;
        #pragma unroll
        for (int j = 0; j < 4; j++) {
            uint32_t phys = (uint32_t)((lc + j) ^ sw_r) * 16;
            cpasync16(abuf + phys, ag + j * 8);
            cpasync16(hbuf + phys, bgh + j * 8);
            cpasync16(lbuf + phys, bgl + j * 8);
        }
        cpcommit();
    };

    issue(0, 0);

    int rA = lane & 15;
    int kq = lane >> 4;
    int swA = rA & 7;

    for (int kb = 0; kb < nkb; kb++) {
        if (kb + 1 < nkb) { issue(kb + 1, (kb + 1) & 1); CP_WAIT(1); }
        else { CP_WAIT(0); }
        __syncthreads();

        uint32_t Ab = sbase + (kb & 1) * 49152;
        uint32_t Bh = Ab + 16384;
        uint32_t Bl = Ab + 32768;

        #pragma unroll
        for (int ks = 0; ks < 4; ks++) {
            uint32_t phys = (uint32_t)(((ks * 2 + kq) ^ swA) * 16);
            uint32_t af[4][4];
            #pragma unroll
            for (int mt = 0; mt < 4; mt++)
                ldmx4(af[mt], Ab + (uint32_t)(wm + mt * 16 + rA) * 128 + phys);
            // hi B tile
            {
                uint32_t bf[4][2];
                #pragma unroll
                for (int g = 0; g < 2; g++) {
                    uint32_t r[4];
                    ldmx4(r, Bh + (uint32_t)(wn + g * 16 + rA) * 128 + phys);
                    bf[2 * g][0] = r[0]; bf[2 * g][1] = r[2];
                    bf[2 * g + 1][0] = r[1]; bf[2 * g + 1][1] = r[3];
                }
                #pragma unroll
                for (int mt = 0; mt < 4; mt++)
                    #pragma unroll
                    for (int nt = 0; nt < 4; nt++)
                        mma16816h(acc[mt][nt], af[mt], bf[nt][0], bf[nt][1]);
            }
            // lo B tile (reuses A fragments)
            {
                uint32_t bf[4][2];
                #pragma unroll
                for (int g = 0; g < 2; g++) {
                    uint32_t r[4];
                    ldmx4(r, Bl + (uint32_t)(wn + g * 16 + rA) * 128 + phys);
                    bf[2 * g][0] = r[0]; bf[2 * g][1] = r[2];
                    bf[2 * g + 1][0] = r[1]; bf[2 * g + 1][1] = r[3];
                }
                #pragma unroll
                for (int mt = 0; mt < 4; mt++)
                    #pragma unroll
                    for (int nt = 0; nt < 4; nt++)
                        mma16816h(acc[mt][nt], af[mt], bf[nt][0], bf[nt][1]);
            }
        }
        __syncthreads();   // 2-stage: protect buffer (kb&1) before issue(kb+2)
    }

    int gq = lane >> 2;
    int tg = lane & 3;
    #pragma unroll
    for (int mt = 0; mt < 4; mt++) {
        #pragma unroll
        for (int nt = 0; nt < 4; nt++) {
            int row0 = bm + wm + mt * 16 + gq;
            int col = bn + wn + nt * 8 + 2 * tg;
            #pragma unroll
            for (int half = 0; half < 2; half++) {
                int row = row0 + half * 8;
                float v0 = acc[mt][nt][2 * half + 0];
                float v1 = acc[mt][nt][2 * half + 1];
                if (outmode == 3) {
                    int j = col >> 1;
                    float a = v0 + (bias ? bias[j] : 0.f);
                    float b = v1 + (bias ? bias[(N >> 1) + j] : 0.f);
                    float r = a * sigmoidf_(b);
                    ((__half*)Cout)[(size_t)row * (N >> 1) + j] = __float2half(r);
                    continue;
                }
                if (bias) { v0 += bias[col]; v1 += bias[col + 1]; }
                if (act == 1) { v0 = gelu_tanh(v0); v1 = gelu_tanh(v1); }
                v0 *= scale; v1 *= scale;
                if (outmode == 0) {
                    float* C = (float*)Cout;
                    if (res) {
                        v0 += res[(size_t)row * N + col];
                        v1 += res[(size_t)row * N + col + 1];
                    }
                    *(float2*)&C[(size_t)row * N + col] = make_float2(v0, v1);
                } else {
                    __half* C3 = (__half*)Cout;
                    __half2 hv = __floats2half2_rn(v0, v1);
                    *(uint32_t*)&C3[(size_t)row * N + col] =
                        *reinterpret_cast<uint32_t*>(&hv);
                }
            }
        }
    }
}

// ---------------- rmsnorm (warp-per-row) fp32 out (final) ----------------
__global__ __launch_bounds__(256)
void rmsnorm_kernel(const float* __restrict__ x,
                    const float* __restrict__ w,
                    float* __restrict__ y) {
    int row = blockIdx.x * 8 + (threadIdx.x >> 5);
    int lane = threadIdx.x & 31;
    const float4* xr = (const float4*)(x + (size_t)row * DM);
    float4 v[6];
    float ss = 0.f;
    #pragma unroll
    for (int j = 0; j < 6; j++) {
        v[j] = xr[lane + 32 * j];
        ss += v[j].x * v[j].x + v[j].y * v[j].y + v[j].z * v[j].z + v[j].w * v[j].w;
    }
    #pragma unroll
    for (int o = 16; o > 0; o >>= 1) ss += __shfl_xor_sync(0xffffffffu, ss, o);
    float r = rsqrtf(ss / (float)DM + EPSF);
    const float4* wr = (const float4*)w;
    float4* yr = (float4*)(y + (size_t)row * DM);
    #pragma unroll
    for (int j = 0; j < 6; j++) {
        float4 wv = wr[lane + 32 * j];
        float4 o4;
        o4.x = v[j].x * r * wv.x;
        o4.y = v[j].y * r * wv.y;
        o4.z = v[j].z * r * wv.z;
        o4.w = v[j].w * r * wv.w;
        yr[lane + 32 * j] = o4;
    }
}

// ---------------- rmsnorm (warp-per-row) -> fp16 single ----------------
__global__ __launch_bounds__(256)
void rmsnorm_fp16_kernel(const float* __restrict__ x,
                         const float* __restrict__ w,
                         __half* __restrict__ y) {
    int row = blockIdx.x * 8 + (threadIdx.x >> 5);
    int lane = threadIdx.x & 31;
    const float4* xr = (const float4*)(x + (size_t)row * DM);
    float4 v[6];
    float ss = 0.f;
    #pragma unroll
    for (int j = 0; j < 6; j++) {
        v[j] = xr[lane + 32 * j];
        ss += v[j].x * v[j].x + v[j].y * v[j].y + v[j].z * v[j].z + v[j].w * v[j].w;
    }
    #pragma unroll
    for (int o = 16; o > 0; o >>= 1) ss += __shfl_xor_sync(0xffffffffu, ss, o);
    float r = rsqrtf(ss / (float)DM + EPSF);
    const float4* wr = (const float4*)w;
    __half* yr = y + (size_t)row * DM;
    #pragma unroll
    for (int j = 0; j < 6; j++) {
        float4 wv = wr[lane + 32 * j];
        __half2 h0 = __floats2half2_rn(v[j].x * r * wv.x, v[j].y * r * wv.y);
        __half2 h1 = __floats2half2_rn(v[j].z * r * wv.z, v[j].w * r * wv.w);
        uint2 st;
        st.x = *reinterpret_cast<uint32_t*>(&h0);
        st.y = *reinterpret_cast<uint32_t*>(&h1);
        *(uint2*)&yr[(lane + 32 * j) * 4] = st;
    }
}

// ---------------- qkv postproc: head rmsnorm + rope + split outputs ----------------
__global__ __launch_bounds__(128)
void qkv_post_kernel(const float* __restrict__ qkv,
                     const float* __restrict__ qnw, const float* __restrict__ knw,
                     __nv_bfloat16* __restrict__ Qh, __nv_bfloat16* __restrict__ Ql,
                     __nv_bfloat16* __restrict__ Kh, __nv_bfloat16* __restrict__ Kl,
                     __nv_bfloat16* __restrict__ Vth, __nv_bfloat16* __restrict__ Vtl,
                     float* __restrict__ kv_out) {
    int w = blockIdx.x * 4 + (threadIdx.x >> 5);
    int lane = threadIdx.x & 31;
    int h = w % NH;
    int tok = w / NH;
    int b = tok / SEQ;
    int n = tok % SEQ;

    const float* base = qkv + (size_t)tok * (3 * NH * HD) + h * (HD * 3);
    float q1 = base[lane * 3 + 0], q2 = base[(lane + 32) * 3 + 0];
    float k1 = base[lane * 3 + 1], k2 = base[(lane + 32) * 3 + 1];
    float v1 = base[lane * 3 + 2], v2 = base[(lane + 32) * 3 + 2];

    float sq = q1 * q1 + q2 * q2;
    #pragma unroll
    for (int o = 16; o > 0; o >>= 1) sq += __shfl_xor_sync(0xffffffffu, sq, o);
    float rq = rsqrtf(sq / 64.f + EPSF);
    q1 *= rq * qnw[lane]; q2 *= rq * qnw[lane + 32];

    float sk = k1 * k1 + k2 * k2;
    #pragma unroll
    for (int o = 16; o > 0; o >>= 1) sk += __shfl_xor_sync(0xffffffffu, sk, o);
    float rk = rsqrtf(sk / 64.f + EPSF);
    k1 *= rk * knw[lane]; k2 *= rk * knw[lane + 32];

    int t = CACHE_T + n;
    size_t kb = ((((size_t)b * KVLEN + t) * 2 + 0) * NH + h) * HD;
    kv_out[kb + lane] = k1;
    kv_out[kb + lane + 32] = k2;
    kv_out[kb + NH * HD + lane] = v1;
    kv_out[kb + NH * HD + lane + 32] = v2;

    float inv = 1.0f / powf(10000.0f, (float)lane / 32.0f);
    float ang = (float)t * inv;
    float c = cosf(ang), s = sinf(ang);

    int bh = b * NH + h;
    float qa = (q1 * c - q2 * s) * 0.125f;
    float qb2 = (q2 * c + q1 * s) * 0.125f;
    size_t qoff = ((size_t)bh * SEQ + n) * HD;
    {
        __nv_bfloat16 h1 = __float2bfloat16(qa);
        __nv_bfloat16 h2 = __float2bfloat16(qb2);
        Qh[qoff + lane] = h1;
        Qh[qoff + lane + 32] = h2;
        Ql[qoff + lane] = __float2bfloat16(qa - __bfloat162float(h1));
        Ql[qoff + lane + 32] = __float2bfloat16(qb2 - __bfloat162float(h2));
    }
    float ka = k1 * c - k2 * s;
    float kb2 = k2 * c + k1 * s;
    size_t koff = ((size_t)bh * KVLEN + t) * HD;
    {
        __nv_bfloat16 h1 = __float2bfloat16(ka);
        __nv_bfloat16 h2 = __float2bfloat16(kb2);
        Kh[koff + lane] = h1;
        Kh[koff + lane + 32] = h2;
        Kl[koff + lane] = __float2bfloat16(ka - __bfloat162float(h1));
        Kl[koff + lane + 32] = __float2bfloat16(kb2 - __bfloat162float(h2));
    }
    size_t voff = ((size_t)bh * HD) * KVLEN + t;
    {
        __nv_bfloat16 h1 = __float2bfloat16(v1);
        __nv_bfloat16 h2 = __float2bfloat16(v2);
        Vth[voff + (size_t)lane * KVLEN] = h1;
        Vth[voff + (size_t)(lane + 32) * KVLEN] = h2;
        Vtl[voff + (size_t)lane * KVLEN] = __float2bfloat16(v1 - __bfloat162float(h1));
        Vtl[voff + (size_t)(lane + 32) * KVLEN] = __float2bfloat16(v2 - __bfloat162float(h2));
    }
}

// ---------------- cached tokens: copy + rope + split ----------------
__global__ __launch_bounds__(128)
void cache_kernel(const float* __restrict__ cached,
                  __nv_bfloat16* __restrict__ Kh, __nv_bfloat16* __restrict__ Kl,
                  __nv_bfloat16* __restrict__ Vth, __nv_bfloat16* __restrict__ Vtl,
                  float* __restrict__ kv_out) {
    int w = blockIdx.x * 4 + (threadIdx.x >> 5);
    int lane = threadIdx.x & 31;
    int h = w % NH;
    int bt = w / NH;
    int b = bt / CACHE_T;
    int t = bt % CACHE_T;

    size_t src = ((((size_t)b * CACHE_T + t) * 2 + 0) * NH + h) * HD;
    float k1 = cached[src + lane], k2 = cached[src + lane + 32];
    float v1 = cached[src + NH * HD + lane], v2 = cached[src + NH * HD + lane + 32];

    size_t dst = ((((size_t)b * KVLEN + t) * 2 + 0) * NH + h) * HD;
    kv_out[dst + lane] = k1;
    kv_out[dst + lane + 32] = k2;
    kv_out[dst + NH * HD + lane] = v1;
    kv_out[dst + NH * HD + lane + 32] = v2;

    float inv = 1.0f / powf(10000.0f, (float)lane / 32.0f);
    float ang = (float)t * inv;
    float c = cosf(ang), s = sinf(ang);
    float ka = k1 * c - k2 * s;
    float kb2 = k2 * c + k1 * s;

    int bh = b * NH + h;
    size_t koff = ((size_t)bh * KVLEN + t) * HD;
    {
        __nv_bfloat16 h1 = __float2bfloat16(ka);
        __nv_bfloat16 h2 = __float2bfloat16(kb2);
        Kh[koff + lane] = h1;
        Kh[koff + lane + 32] = h2;
        Kl[koff + lane] = __float2bfloat16(ka - __bfloat162float(h1));
        Kl[koff + lane + 32] = __float2bfloat16(kb2 - __bfloat162float(h2));
    }
    size_t voff = ((size_t)bh * HD) * KVLEN + t;
    {
        __nv_bfloat16 h1 = __float2bfloat16(v1);
        __nv_bfloat16 h2 = __float2bfloat16(v2);
        Vth[voff + (size_t)lane * KVLEN] = h1;
        Vth[voff + (size_t)(lane + 32) * KVLEN] = h2;
        Vtl[voff + (size_t)lane * KVLEN] = __float2bfloat16(v1 - __bfloat162float(h1));
        Vtl[voff + (size_t)(lane + 32) * KVLEN] = __float2bfloat16(v2 - __bfloat162float(h2));
    }
}

// ---------------- attention: MMA flash, 64 q-rows/block, 64-key chunks ----------------
#define AT_STAGE 32768
__global__ __launch_bounds__(128)
void attn_mma(const __nv_bfloat16* __restrict__ Qh, const __nv_bfloat16* __restrict__ Ql,
              const __nv_bfloat16* __restrict__ Kh, const __nv_bfloat16* __restrict__ Kl,
              const __nv_bfloat16* __restrict__ Vth, const __nv_bfloat16* __restrict__ Vtl,
              __half* __restrict__ Oh) {
    extern __shared__ __align__(16) unsigned char dsm[];
    uint32_t sbase = smem_u32(dsm);
    uint32_t qarea = sbase + 2 * AT_STAGE;

    int tid = threadIdx.x, lane = tid & 31, wid = tid >> 5;
    int bh = blockIdx.y;
    int b = bh / NH, h = bh % NH;
    int q0 = blockIdx.x * 64;

    size_t qoff = ((size_t)bh * SEQ + q0) * HD;
    size_t koff = (size_t)bh * KVLEN * HD;
    size_t voff = (size_t)bh * HD * KVLEN;

    int lr = tid >> 1;
    int lc4 = (tid & 1) * 4;

    {
        const __nv_bfloat16* qhg = Qh + qoff + lr * HD;
        const __nv_bfloat16* qlg = Ql + qoff + lr * HD;
        #pragma unroll
        for (int j = 0; j < 4; j++) {
            int ch = lc4 + j;
            uint32_t phys = (uint32_t)((ch ^ (lr & 7)) * 16);
            cpasync16(qarea + lr * 128 + phys, qhg + ch * 8);
            cpasync16(qarea + 8192 + lr * 128 + phys, qlg + ch * 8);
        }
        cpcommit();
    }

    auto issueKV = [&](int c, int buf) {
        uint32_t dst = sbase + buf * AT_STAGE + lr * 128;
        const __nv_bfloat16* khg = Kh + koff + (size_t)(c * 64 + lr) * HD;
        const __nv_bfloat16* klg = Kl + koff + (size_t)(c * 64 + lr) * HD;
        const __nv_bfloat16* vhg = Vth + voff + (size_t)lr * KVLEN + c * 64;
        const __nv_bfloat16* vlg = Vtl + voff + (size_t)lr * KVLEN + c * 64;
        #pragma unroll
        for (int j = 0; j < 4; j++) {
            int ch = lc4 + j;
            uint32_t phys = (uint32_t)((ch ^ (lr & 7)) * 16);
            cpasync16(dst + phys, khg + ch * 8);
            cpasync16(dst + 8192 + phys, klg + ch * 8);
            cpasync16(dst + 16384 + phys, vhg + ch * 8);
            cpasync16(dst + 24576 + phys, vlg + ch * 8);
        }
        cpcommit();
    };

    issueKV(0, 0);
    CP_WAIT(1);
    __syncthreads();

    int rA = lane & 15, kq = lane >> 4;
    int qrow = wid * 16 + rA;
    int qs = qrow & 7;
    uint32_t qfh[4][4], qfl[4][4];
    #pragma unroll
    for (int kt = 0; kt < 4; kt++) {
        uint32_t phys = (uint32_t)(((kt * 2 + kq) ^ qs) * 16);
        ldmx4(qfh[kt], qarea + qrow * 128 + phys);
        ldmx4(qfl[kt], qarea + 8192 + qrow * 128 + phys);
    }

    int gq = lane >> 2, tg = lane & 3;
    float m0 = -1e30f, m1 = -1e30f, l0 = 0.f, l1 = 0.f;
    float O[8][4];
    #pragma unroll
    for (int nt = 0; nt < 8; nt++)
        #pragma unroll
        for (int i = 0; i < 4; i++) O[nt][i] = 0.f;

    const int NCH = KVLEN / 64;
    for (int c = 0; c < NCH; c++) {
        if (c + 1 < NCH) { issueKV(c + 1, (c + 1) & 1); CP_WAIT(1); }
        else { CP_WAIT(0); }
        __syncthreads();

        uint32_t bufK = sbase + (c & 1) * AT_STAGE;
        uint32_t bufV = bufK + 16384;

        float S[8][4];
        #pragma unroll
        for (int nt = 0; nt < 8; nt++)
            #pragma unroll
            for (int i = 0; i < 4; i++) S[nt][i] = 0.f;

        #pragma unroll
        for (int kt = 0; kt < 4; kt++) {
            uint32_t kfh[4][4], kfl[4][4];
            #pragma unroll
            for (int g2 = 0; g2 < 4; g2++) {
                int krow = g2 * 16 + rA;
                uint32_t phys = (uint32_t)(((kt * 2 + kq) ^ (krow & 7)) * 16);
                ldmx4(kfh[g2], bufK + krow * 128 + phys);
                ldmx4(kfl[g2], bufK + 8192 + krow * 128 + phys);
            }
            #pragma unroll
            for (int g2 = 0; g2 < 4; g2++)
                #pragma unroll
                for (int hf = 0; hf < 2; hf++) {
                    int nt = 2 * g2 + hf;
                    mma16816(S[nt], qfh[kt], kfh[g2][hf], kfh[g2][hf + 2]);
                    mma16816(S[nt], qfh[kt], kfl[g2][hf], kfl[g2][hf + 2]);
                    mma16816(S[nt], qfl[kt], kfh[g2][hf], kfh[g2][hf + 2]);
                }
        }

        float mx0 = -1e30f, mx1 = -1e30f;
        #pragma unroll
        for (int nt = 0; nt < 8; nt++) {
            mx0 = fmaxf(mx0, fmaxf(S[nt][0], S[nt][1]));
            mx1 = fmaxf(mx1, fmaxf(S[nt][2], S[nt][3]));
        }
        mx0 = fmaxf(mx0, __shfl_xor_sync(0xffffffffu, mx0, 1));
        mx0 = fmaxf(mx0, __shfl_xor_sync(0xffffffffu, mx0, 2));
        mx1 = fmaxf(mx1, __shfl_xor_sync(0xffffffffu, mx1, 1));
        mx1 = fmaxf(mx1, __shfl_xor_sync(0xffffffffu, mx1, 2));
        float nm0 = fmaxf(m0, mx0), nm1 = fmaxf(m1, mx1);
        float a0 = __expf(m0 - nm0), a1 = __expf(m1 - nm1);

        float rs0 = 0.f, rs1 = 0.f;
        #pragma unroll
        for (int nt = 0; nt < 8; nt++) {
            S[nt][0] = __expf(S[nt][0] - nm0);
            S[nt][1] = __expf(S[nt][1] - nm0);
            S[nt][2] = __expf(S[nt][2] - nm1);
            S[nt][3] = __expf(S[nt][3] - nm1);
            rs0 += S[nt][0] + S[nt][1];
            rs1 += S[nt][2] + S[nt][3];
        }
        rs0 += __shfl_xor_sync(0xffffffffu, rs0, 1);
        rs0 += __shfl_xor_sync(0xffffffffu, rs0, 2);
        rs1 += __shfl_xor_sync(0xffffffffu, rs1, 1);
        rs1 += __shfl_xor_sync(0xffffffffu, rs1, 2);
        l0 = l0 * a0 + rs0;
        l1 = l1 * a1 + rs1;
        m0 = nm0; m1 = nm1;
        #pragma unroll
        for (int nt = 0; nt < 8; nt++) {
            O[nt][0] *= a0; O[nt][1] *= a0;
            O[nt][2] *= a1; O[nt][3] *= a1;
        }

        #pragma unroll
        for (int kt = 0; kt < 4; kt++) {
            uint32_t ah[4], al[4];
            splitpair(S[2 * kt][0], S[2 * kt][1], ah[0], al[0]);
            splitpair(S[2 * kt][2], S[2 * kt][3], ah[1], al[1]);
            splitpair(S[2 * kt + 1][0], S[2 * kt + 1][1], ah[2], al[2]);
            splitpair(S[2 * kt + 1][2], S[2 * kt + 1][3], ah[3], al[3]);
            uint32_t vfh[4][4], vfl[4][4];
            #pragma unroll
            for (int g2 = 0; g2 < 4; g2++) {
                int vrow = g2 * 16 + rA;
                uint32_t phys = (uint32_t)(((kt * 2 + kq) ^ (vrow & 7)) * 16);
                ldmx4(vfh[g2], bufV + vrow * 128 + phys);
                ldmx4(vfl[g2], bufV + 8192 + vrow * 128 + phys);
            }
            #pragma unroll
            for (int g2 = 0; g2 < 4; g2++)
                #pragma unroll
                for (int hf = 0; hf < 2; hf++) {
                    int nt = 2 * g2 + hf;
                    mma16816(O[nt], ah, vfh[g2][hf], vfh[g2][hf + 2]);
                    mma16816(O[nt], ah, vfl[g2][hf], vfl[g2][hf + 2]);
                    mma16816(O[nt], al, vfh[g2][hf], vfh[g2][hf + 2]);
                }
        }
        __syncthreads();
    }

    float inv0 = 1.0f / l0, inv1 = 1.0f / l1;
    int r0 = q0 + wid * 16 + gq;
    size_t tok0 = (size_t)(b * SEQ + r0);
    size_t tok1 = tok0 + 8;
    #pragma unroll
    for (int nt = 0; nt < 8; nt++) {
        int col = h * HD + nt * 8 + 2 * tg;
        __half2 h0 = __floats2half2_rn(O[nt][0] * inv0, O[nt][1] * inv0);
        __half2 h1 = __floats2half2_rn(O[nt][2] * inv1, O[nt][3] * inv1);
        *(uint32_t*)&Oh[tok0 * DM + col] = *reinterpret_cast<uint32_t*>(&h0);
        *(uint32_t*)&Oh[tok1 * DM + col] = *reinterpret_cast<uint32_t*>(&h1);
    }
}

// ---------------- depthwise conv, sliding window: 8 outputs/thread ----------------
#define DW_NP 8
__global__ void dwconv_kernel(const __half* __restrict__ in,
                              const float* __restrict__ w,
                              const float* __restrict__ bias,
                              float* __restrict__ out) {
    int i = blockIdx.x * blockDim.x + threadIdx.x;
    if (i >= (NTOK / DW_NP) * DM) return;
    int c = i % DM;
    int tile = i / DM;
    int ntile = tile % (SEQ / DW_NP);
    int b = tile / (SEQ / DW_NP);
    int n0 = ntile * DW_NP;

    __half vin[DW_NP + KSZ - 1];
    #pragma unroll
    for (int j = 0; j < DW_NP + KSZ - 1; j++) {
        int nn = n0 - (KSZ / 2) + j;
        vin[j] = (nn >= 0 && nn < SEQ) ? in[((size_t)b * SEQ + nn) * DM + c]
                                       : __float2half(0.f);
    }
    float acc[DW_NP];
    float bv = bias[c];
    #pragma unroll
    for (int j = 0; j < DW_NP; j++) acc[j] = bv;
    #pragma unroll
    for (int k = 0; k < KSZ; k++) {
        float wk = w[c * KSZ + k];
        #pragma unroll
        for (int j = 0; j < DW_NP; j++)
            acc[j] = fmaf(__half2float(vin[j + k]), wk, acc[j]);
    }
    #pragma unroll
    for (int j = 0; j < DW_NP; j++)
        out[((size_t)b * SEQ + n0 + j) * DM + c] = acc[j];
}

// ---------------- batchnorm stats ----------------
__global__ void bnstats_kernel(const float* __restrict__ in,
                               float* __restrict__ mean, float* __restrict__ var) {
    int c = blockIdx.x;
    float s = 0.f, ss = 0.f;
    for (int r = threadIdx.x; r < NTOK; r += blockDim.x) {
        float v = in[(size_t)r * DM + c];
        s += v;
        ss += v * v;
    }
    #pragma unroll
    for (int o = 16; o > 0; o >>= 1) {
        s += __shfl_xor_sync(0xffffffffu, s, o);
        ss += __shfl_xor_sync(0xffffffffu, ss, o);
    }
    __shared__ float rs[8], rss[8];
    if ((threadIdx.x & 31) == 0) {
        rs[threadIdx.x >> 5] = s;
        rss[threadIdx.x >> 5] = ss;
    }
    __syncthreads();
    if (threadIdx.x == 0) {
        float ts = 0.f, tss = 0.f;
        #pragma unroll
        for (int i = 0; i < 8; i++) { ts += rs[i]; tss += rss[i]; }
        float m = ts / (float)NTOK;
        mean[c] = m;
        var[c] = tss / (float)NTOK - m * m;
    }
}

// ---------------- bn apply + swish -> fp16 single ----------------
__global__ void bnapply_fp16_kernel(const float* __restrict__ in,
                                    const float* __restrict__ mean, const float* __restrict__ var,
                                    const float* __restrict__ g, const float* __restrict__ be,
                                    __half* __restrict__ out) {
    int i = blockIdx.x * blockDim.x + threadIdx.x;
    if (i >= NTOK * DM) return;
    int c = i % DM;
    float y = (in[i] - mean[c]) * rsqrtf(var[c] + EPSF) * g[c] + be[c];
    y = y * sigmoidf_(y);
    out[i] = __float2half(y);
}

// ---------------- host-side helpers ----------------
static __nv_bfloat16* s_b2 = nullptr;

static void tc_gemm_fp16(const __half* A1, const float* W, void* C,
                         int M, int N, int K,
                         const float* bias, const float* res, float scale, int act,
                         int outmode) {
    convB_fp16_kernel<<<dim3(K / 32, N / 32), dim3(32, 8)>>>(
        W, (__half*)s_b2, K, N, outmode == 3 ? 1 : 0);
    hgemm_fp16<<<dim3(N / 128, M / 128), 256, 98304>>>(
        (const uint16_t*)A1, (const uint16_t*)s_b2, C, M, N, K,
        bias, res, scale, act, outmode);
}

extern "C" void kernel_launch(void* const* d_in, const int* in_sizes, int n_in,
                              void* d_out, int out_size) {
    (void)in_sizes; (void)n_in; (void)out_size;
    const float* x          = (const float*)d_in[0];
    const float* cached_kv  = (const float*)d_in[4];
    const float* ff1_norm_w = (const float*)d_in[5];
    const float* ff1_w1     = (const float*)d_in[6];
    const float* ff1_b1     = (const float*)d_in[7];
    const float* ff1_w2     = (const float*)d_in[8];
    const float* ff1_b2     = (const float*)d_in[9];
    const float* attn_norm_w= (const float*)d_in[10];
    const float* qkv_w      = (const float*)d_in[11];
    const float* out_w      = (const float*)d_in[12];
    const float* q_norm_w   = (const float*)d_in[13];
    const float* k_norm_w   = (const float*)d_in[14];
    const float* conv_norm_w= (const float*)d_in[15];
    const float* pw1_w      = (const float*)d_in[16];
    const float* pw1_b      = (const float*)d_in[17];
    const float* dw_w       = (const float*)d_in[18];
    const float* dw_b       = (const float*)d_in[19];
    const float* bn_g       = (const float*)d_in[20];
    const float* bn_b       = (const float*)d_in[21];
    const float* pw2_w      = (const float*)d_in[22];
    const float* pw2_b      = (const float*)d_in[23];
    const float* ff2_norm_w = (const float*)d_in[24];
    const float* ff2_w1     = (const float*)d_in[25];
    const float* ff2_b1     = (const float*)d_in[26];
    const float* ff2_w2     = (const float*)d_in[27];
    const float* ff2_b2     = (const float*)d_in[28];
    const float* out_norm_w = (const float*)d_in[29];

    float* out_x  = (float*)d_out;
    float* out_kv = out_x + (size_t)NTOK * DM;

    float *gX1, *gX2, *gQKV, *gT, *gC, *gM, *gV;
    __nv_bfloat16 *gA2, *gAH, *gQh, *gQl, *gKh, *gKl, *gVth, *gVtl;
    cudaGetSymbolAddress((void**)&gX1,  g_x1);
    cudaGetSymbolAddress((void**)&gX2,  g_x2);
    cudaGetSymbolAddress((void**)&gQKV, g_qkv);
    cudaGetSymbolAddress((void**)&gT,   g_tmp);
    cudaGetSymbolAddress((void**)&gC,   g_conv);
    cudaGetSymbolAddress((void**)&gM,   g_mean);
    cudaGetSymbolAddress((void**)&gV,   g_var);
    cudaGetSymbolAddress((void**)&gA2,  g_a2);
    cudaGetSymbolAddress((void**)&gAH,  g_ah);
    cudaGetSymbolAddress((void**)&s_b2, g_b2);
    cudaGetSymbolAddress((void**)&gQh,  g_qh);
    cudaGetSymbolAddress((void**)&gQl,  g_ql);
    cudaGetSymbolAddress((void**)&gKh,  g_kh);
    cudaGetSymbolAddress((void**)&gKl,  g_kl);
    cudaGetSymbolAddress((void**)&gVth, g_vth);
    cudaGetSymbolAddress((void**)&gVtl, g_vtl);

    __half* gF16 = (__half*)gA2;     // fp16 GEMM input (M, DM)
    __half* gH16 = (__half*)gAH;     // fp16 FF intermediate (M, FFD)
    __half* gT16 = (__half*)gT;      // fp16 GLU output (M, DM)

    cudaFuncSetAttribute(hgemm_fp16, cudaFuncAttributeMaxDynamicSharedMemorySize, 98304);
    cudaFuncSetAttribute(attn_mma, cudaFuncAttributeMaxDynamicSharedMemorySize, 81920);

    const int EW_BLOCKS = (NTOK * DM + 255) / 256;
    const int DW_BLOCKS = ((NTOK / DW_NP) * DM + 255) / 256;
    const int RN_BLOCKS = NTOK / 8;

    // ---- FF1 ----
    rmsnorm_fp16_kernel<<<RN_BLOCKS, 256>>>(x, ff1_norm_w, gF16);
    tc_gemm_fp16(gF16, ff1_w1, gH16, NTOK, FFD, DM, ff1_b1, nullptr, 1.0f, 1, 2);
    tc_gemm_fp16(gH16, ff1_w2, gX1, NTOK, DM, FFD, ff1_b2, x, 0.5f, 0, 0);

    // ---- Attention ----
    rmsnorm_fp16_kernel<<<RN_BLOCKS, 256>>>(gX1, attn_norm_w, gF16);
    tc_gemm_fp16(gF16, qkv_w, gQKV, NTOK, 3 * NH * HD, DM, nullptr, nullptr, 1.0f, 0, 0);
    qkv_post_kernel<<<NTOK * NH / 4, 128>>>(gQKV, q_norm_w, k_norm_w,
                                            gQh, gQl, gKh, gKl, gVth, gVtl, out_kv);
    cache_kernel<<<BSZ * CACHE_T * NH / 4, 128>>>(cached_kv, gKh, gKl, gVth, gVtl, out_kv);
    attn_mma<<<dim3(SEQ / 64, BSZ * NH), 128, 81920>>>(gQh, gQl, gKh, gKl, gVth, gVtl, gF16);
    tc_gemm_fp16(gF16, out_w, gX2, NTOK, DM, DM, nullptr, gX1, 1.0f, 0, 0);

    // ---- Conv module (GLU fused into pw1 epilogue) ----
    rmsnorm_fp16_kernel<<<RN_BLOCKS, 256>>>(gX2, conv_norm_w, gF16);
    tc_gemm_fp16(gF16, pw1_w, gT16, NTOK, 2 * DM, DM, pw1_b, nullptr, 1.0f, 0, 3);
    dwconv_kernel<<<DW_BLOCKS, 256>>>(gT16, dw_w, dw_b, gC);
    bnstats_kernel<<<DM, 256>>>(gC, gM, gV);
    bnapply_fp16_kernel<<<EW_BLOCKS, 256>>>(gC, gM, gV, bn_g, bn_b, gF16);
    tc_gemm_fp16(gF16, pw2_w, gX1, NTOK, DM, DM, pw2_b, nullptr, 1.0f, 0, 0);

    // ---- FF2 ----
    rmsnorm_fp16_kernel<<<RN_BLOCKS, 256>>>(gX1, ff2_norm_w, gF16);
    tc_gemm_fp16(gF16, ff2_w1, gH16, NTOK, FFD, DM, ff2_b1, nullptr, 1.0f, 1, 2);
    tc_gemm_fp16(gH16, ff2_w2, gX2, NTOK, DM, FFD, ff2_b2, gX1, 0.5f, 0, 0);

    // ---- final norm ----
    rmsnorm_kernel<<<RN_BLOCKS, 256>>>(gX2, out_norm_w, out_x);
}

// round 14
// speedup vs baseline: 3.4427x; 1.2202x over previous
#include <cuda_runtime.h>
#include <cuda_bf16.h>
#include <cuda_fp16.h>
#include <math.h>
#include <stdint.h>

// ---------------- problem constants ----------------
#define BSZ      2
#define SEQ      2048
#define NTOK     4096          // B*N
#define CACHE_T  512
#define KVLEN    2560
#define DM       768
#define NH       12
#define HD       64
#define FFD      3072
#define KSZ      31
#define EPSF     1e-5f

// ---------------- scratch (device globals; no allocation) ----------------
__device__ __align__(128) float g_x1[NTOK * DM];
__device__ __align__(128) float g_x2[NTOK * DM];
__device__ __align__(128) float g_qkv[NTOK * 3 * NH * HD];
__device__ __align__(128) float g_tmp[NTOK * DM];            // also __half reuse
__device__ __align__(128) float g_conv[NTOK * DM];
__device__ float g_mean[DM];
__device__ float g_var[DM];
__device__ __align__(128) __nv_bfloat16 g_a2[NTOK * 2 * DM];             // fp16 GEMM input reuse
__device__ __align__(128) __nv_bfloat16 g_ah[(size_t)NTOK * 2 * FFD];    // FF intermediate (fp16 reuse)
__device__ __align__(128) __nv_bfloat16 g_b2[(size_t)FFD * 2 * DM];      // weights (N,2K)
__device__ __align__(128) __half g_qf[BSZ * NH * SEQ * HD];
__device__ __align__(128) __half g_kf[BSZ * NH * KVLEN * HD];
__device__ __align__(128) __half g_vtf[BSZ * NH * HD * KVLEN];           // (b,h,d,t)

// ---------------- helpers ----------------
__device__ __forceinline__ float gelu_tanh(float x) {
    const float c = 0.7978845608028654f;
    float t = tanhf(c * (x + 0.044715f * x * x * x));
    return 0.5f * x * (1.0f + t);
}
__device__ __forceinline__ float sigmoidf_(float x) {
    return 1.0f / (1.0f + expf(-x));
}
__device__ __forceinline__ uint32_t smem_u32(const void* p) {
    uint32_t a;
    asm("{ .reg .u64 t; cvta.to.shared.u64 t, %1; cvt.u32.u64 %0, t; }"
        : "=r"(a) : "l"(p));
    return a;
}
__device__ __forceinline__ void cpasync16(uint32_t dst, const void* src) {
    asm volatile("cp.async.cg.shared.global [%0], [%1], 16;" :: "r"(dst), "l"(src));
}
__device__ __forceinline__ void cpcommit() {
    asm volatile("cp.async.commit_group;");
}
#define CP_WAIT(N) asm volatile("cp.async.wait_group %0;" :: "n"(N))
__device__ __forceinline__ void ldmx4(uint32_t r[4], uint32_t a) {
    asm volatile("ldmatrix.sync.aligned.m8n8.x4.shared.b16 {%0,%1,%2,%3}, [%4];"
                 : "=r"(r[0]), "=r"(r[1]), "=r"(r[2]), "=r"(r[3]) : "r"(a));
}
__device__ __forceinline__ void mma16816h(float c[4], const uint32_t a[4],
                                          uint32_t b0, uint32_t b1) {
    asm volatile(
        "mma.sync.aligned.m16n8k16.row.col.f32.f16.f16.f32 "
        "{%0,%1,%2,%3}, {%4,%5,%6,%7}, {%8,%9}, {%0,%1,%2,%3};"
        : "+f"(c[0]), "+f"(c[1]), "+f"(c[2]), "+f"(c[3])
        : "r"(a[0]), "r"(a[1]), "r"(a[2]), "r"(a[3]), "r"(b0), "r"(b1));
}

// ---------------- weight conversion: W (K,N) fp32 -> (N,2K) fp16 hi|lo ----------------
// glu_interleave=1: output row for orig col n is (n<N/2 ? 2n : 2(n-N/2)+1)
__global__ void convB_fp16_kernel(const float* __restrict__ W,
                                  __half* __restrict__ out, int K, int N,
                                  int glu_interleave) {
    __shared__ float t[32][33];
    int k0 = blockIdx.x * 32, n0 = blockIdx.y * 32;
    int tx = threadIdx.x, ty = threadIdx.y;   // 32 x 8
    #pragma unroll
    for (int i = ty; i < 32; i += 8)
        t[i][tx] = W[(size_t)(k0 + i) * N + n0 + tx];
    __syncthreads();
    int half_n = N >> 1;
    #pragma unroll
    for (int i = ty; i < 32; i += 8) {
        float v = t[tx][i];                   // W[k0+tx][n0+i]
        __half h = __float2half(v);
        float lo = v - __half2float(h);
        int n = n0 + i;
        int row = glu_interleave ? ((n < half_n) ? (2 * n) : (2 * (n - half_n) + 1))
                                 : n;
        size_t b = (size_t)row * (2 * K) + k0 + tx;
        out[b] = h;
        out[b + K] = __float2half(lo);
    }
}

// ---------------- warp-MMA fp16 GEMM, fused hi/lo, 128x128x64 tile, 2-stage ----------------
// 256 threads, 8 warps (2m x 4n), warp tile 64x32. A fragments shared across hi/lo B.
// outmode 0: fp32 + bias/act/scale/res.  2: fp16.  3: GLU fused (interleaved B).
__global__ __launch_bounds__(256)
void hgemm_fp16(const uint16_t* __restrict__ A1,
                const uint16_t* __restrict__ B2,
                void* __restrict__ Cout, int M, int N, int K,
                const float* __restrict__ bias, const float* __restrict__ res,
                float scale, int act, int outmode) {
    extern __shared__ __align__(16) unsigned char dsm[];
    uint32_t sbase = smem_u32(dsm);

    int tid = threadIdx.x;
    int lane = tid & 31;
    int wid = tid >> 5;
    int wm = (wid >> 2) * 64;
    int wn = (wid & 3) * 32;
    int bm = blockIdx.y * 128;
    int bn = blockIdx.x * 128;

    int nkb = K >> 6;

    int lr = tid >> 1;
    int lc = (tid & 1) * 4;
    int sw_r = lr & 7;

    float acc[4][4][4];
    #pragma unroll
    for (int a = 0; a < 4; a++)
        #pragma unroll
        for (int b = 0; b < 4; b++)
            #pragma unroll
            for (int c = 0; c < 4; c++) acc[a][b][c] = 0.f;

    auto issue = [&](int kb, int buf) {
        int off = kb << 6;
        const uint16_t* ag  = A1 + (size_t)(bm + lr) * K + off + lc * 8;
        const uint16_t* bgh = B2 + (size_t)(bn + lr) * (2 * K) + off + lc * 8;
        const uint16_t* bgl = bgh + K;
        uint32_t abuf = sbase + buf * 49152 + lr * 128;
        uint32_t hbuf = abuf + 16384;
        uint32_t lbuf = abuf + 32768;
        #pragma unroll
        for (int j = 0; j < 4; j++) {
            uint32_t phys = (uint32_t)((lc + j) ^ sw_r) * 16;
            cpasync16(abuf + phys, ag + j * 8);
            cpasync16(hbuf + phys, bgh + j * 8);
            cpasync16(lbuf + phys, bgl + j * 8);
        }
        cpcommit();
    };

    issue(0, 0);

    int rA = lane & 15;
    int kq = lane >> 4;
    int swA = rA & 7;

    for (int kb = 0; kb < nkb; kb++) {
        if (kb + 1 < nkb) { issue(kb + 1, (kb + 1) & 1); CP_WAIT(1); }
        else { CP_WAIT(0); }
        __syncthreads();

        uint32_t Ab = sbase + (kb & 1) * 49152;
        uint32_t Bh = Ab + 16384;
        uint32_t Bl = Ab + 32768;

        #pragma unroll
        for (int ks = 0; ks < 4; ks++) {
            uint32_t phys = (uint32_t)(((ks * 2 + kq) ^ swA) * 16);
            uint32_t af[4][4];
            #pragma unroll
            for (int mt = 0; mt < 4; mt++)
                ldmx4(af[mt], Ab + (uint32_t)(wm + mt * 16 + rA) * 128 + phys);
            {
                uint32_t bf[4][2];
                #pragma unroll
                for (int g = 0; g < 2; g++) {
                    uint32_t r[4];
                    ldmx4(r, Bh + (uint32_t)(wn + g * 16 + rA) * 128 + phys);
                    bf[2 * g][0] = r[0]; bf[2 * g][1] = r[2];
                    bf[2 * g + 1][0] = r[1]; bf[2 * g + 1][1] = r[3];
                }
                #pragma unroll
                for (int mt = 0; mt < 4; mt++)
                    #pragma unroll
                    for (int nt = 0; nt < 4; nt++)
                        mma16816h(acc[mt][nt], af[mt], bf[nt][0], bf[nt][1]);
            }
            {
                uint32_t bf[4][2];
                #pragma unroll
                for (int g = 0; g < 2; g++) {
                    uint32_t r[4];
                    ldmx4(r, Bl + (uint32_t)(wn + g * 16 + rA) * 128 + phys);
                    bf[2 * g][0] = r[0]; bf[2 * g][1] = r[2];
                    bf[2 * g + 1][0] = r[1]; bf[2 * g + 1][1] = r[3];
                }
                #pragma unroll
                for (int mt = 0; mt < 4; mt++)
                    #pragma unroll
                    for (int nt = 0; nt < 4; nt++)
                        mma16816h(acc[mt][nt], af[mt], bf[nt][0], bf[nt][1]);
            }
        }
        __syncthreads();
    }

    int gq = lane >> 2;
    int tg = lane & 3;
    #pragma unroll
    for (int mt = 0; mt < 4; mt++) {
        #pragma unroll
        for (int nt = 0; nt < 4; nt++) {
            int row0 = bm + wm + mt * 16 + gq;
            int col = bn + wn + nt * 8 + 2 * tg;
            #pragma unroll
            for (int half = 0; half < 2; half++) {
                int row = row0 + half * 8;
                float v0 = acc[mt][nt][2 * half + 0];
                float v1 = acc[mt][nt][2 * half + 1];
                if (outmode == 3) {
                    int j = col >> 1;
                    float a = v0 + (bias ? bias[j] : 0.f);
                    float b = v1 + (bias ? bias[(N >> 1) + j] : 0.f);
                    float r = a * sigmoidf_(b);
                    ((__half*)Cout)[(size_t)row * (N >> 1) + j] = __float2half(r);
                    continue;
                }
                if (bias) { v0 += bias[col]; v1 += bias[col + 1]; }
                if (act == 1) { v0 = gelu_tanh(v0); v1 = gelu_tanh(v1); }
                v0 *= scale; v1 *= scale;
                if (outmode == 0) {
                    float* C = (float*)Cout;
                    if (res) {
                        v0 += res[(size_t)row * N + col];
                        v1 += res[(size_t)row * N + col + 1];
                    }
                    *(float2*)&C[(size_t)row * N + col] = make_float2(v0, v1);
                } else {
                    __half* C3 = (__half*)Cout;
                    __half2 hv = __floats2half2_rn(v0, v1);
                    *(uint32_t*)&C3[(size_t)row * N + col] =
                        *reinterpret_cast<uint32_t*>(&hv);
                }
            }
        }
    }
}

// ---------------- rmsnorm (warp-per-row) fp32 out (final) ----------------
__global__ __launch_bounds__(256)
void rmsnorm_kernel(const float* __restrict__ x,
                    const float* __restrict__ w,
                    float* __restrict__ y) {
    int row = blockIdx.x * 8 + (threadIdx.x >> 5);
    int lane = threadIdx.x & 31;
    const float4* xr = (const float4*)(x + (size_t)row * DM);
    float4 v[6];
    float ss = 0.f;
    #pragma unroll
    for (int j = 0; j < 6; j++) {
        v[j] = xr[lane + 32 * j];
        ss += v[j].x * v[j].x + v[j].y * v[j].y + v[j].z * v[j].z + v[j].w * v[j].w;
    }
    #pragma unroll
    for (int o = 16; o > 0; o >>= 1) ss += __shfl_xor_sync(0xffffffffu, ss, o);
    float r = rsqrtf(ss / (float)DM + EPSF);
    const float4* wr = (const float4*)w;
    float4* yr = (float4*)(y + (size_t)row * DM);
    #pragma unroll
    for (int j = 0; j < 6; j++) {
        float4 wv = wr[lane + 32 * j];
        float4 o4;
        o4.x = v[j].x * r * wv.x;
        o4.y = v[j].y * r * wv.y;
        o4.z = v[j].z * r * wv.z;
        o4.w = v[j].w * r * wv.w;
        yr[lane + 32 * j] = o4;
    }
}

// ---------------- rmsnorm (warp-per-row) -> fp16 single ----------------
__global__ __launch_bounds__(256)
void rmsnorm_fp16_kernel(const float* __restrict__ x,
                         const float* __restrict__ w,
                         __half* __restrict__ y) {
    int row = blockIdx.x * 8 + (threadIdx.x >> 5);
    int lane = threadIdx.x & 31;
    const float4* xr = (const float4*)(x + (size_t)row * DM);
    float4 v[6];
    float ss = 0.f;
    #pragma unroll
    for (int j = 0; j < 6; j++) {
        v[j] = xr[lane + 32 * j];
        ss += v[j].x * v[j].x + v[j].y * v[j].y + v[j].z * v[j].z + v[j].w * v[j].w;
    }
    #pragma unroll
    for (int o = 16; o > 0; o >>= 1) ss += __shfl_xor_sync(0xffffffffu, ss, o);
    float r = rsqrtf(ss / (float)DM + EPSF);
    const float4* wr = (const float4*)w;
    __half* yr = y + (size_t)row * DM;
    #pragma unroll
    for (int j = 0; j < 6; j++) {
        float4 wv = wr[lane + 32 * j];
        __half2 h0 = __floats2half2_rn(v[j].x * r * wv.x, v[j].y * r * wv.y);
        __half2 h1 = __floats2half2_rn(v[j].z * r * wv.z, v[j].w * r * wv.w);
        uint2 st;
        st.x = *reinterpret_cast<uint32_t*>(&h0);
        st.y = *reinterpret_cast<uint32_t*>(&h1);
        *(uint2*)&yr[(lane + 32 * j) * 4] = st;
    }
}

// ---------------- qkv postproc: head rmsnorm + rope -> fp16 Q/K/Vt + fp32 cache ----------------
__global__ __launch_bounds__(128)
void qkv_post_kernel(const float* __restrict__ qkv,
                     const float* __restrict__ qnw, const float* __restrict__ knw,
                     __half* __restrict__ Qf, __half* __restrict__ Kf,
                     __half* __restrict__ Vtf,
                     float* __restrict__ kv_out) {
    int w = blockIdx.x * 4 + (threadIdx.x >> 5);
    int lane = threadIdx.x & 31;
    int h = w % NH;
    int tok = w / NH;
    int b = tok / SEQ;
    int n = tok % SEQ;

    const float* base = qkv + (size_t)tok * (3 * NH * HD) + h * (HD * 3);
    float q1 = base[lane * 3 + 0], q2 = base[(lane + 32) * 3 + 0];
    float k1 = base[lane * 3 + 1], k2 = base[(lane + 32) * 3 + 1];
    float v1 = base[lane * 3 + 2], v2 = base[(lane + 32) * 3 + 2];

    float sq = q1 * q1 + q2 * q2;
    #pragma unroll
    for (int o = 16; o > 0; o >>= 1) sq += __shfl_xor_sync(0xffffffffu, sq, o);
    float rq = rsqrtf(sq / 64.f + EPSF);
    q1 *= rq * qnw[lane]; q2 *= rq * qnw[lane + 32];

    float sk = k1 * k1 + k2 * k2;
    #pragma unroll
    for (int o = 16; o > 0; o >>= 1) sk += __shfl_xor_sync(0xffffffffu, sk, o);
    float rk = rsqrtf(sk / 64.f + EPSF);
    k1 *= rk * knw[lane]; k2 *= rk * knw[lane + 32];

    int t = CACHE_T + n;
    size_t kb = ((((size_t)b * KVLEN + t) * 2 + 0) * NH + h) * HD;
    kv_out[kb + lane] = k1;
    kv_out[kb + lane + 32] = k2;
    kv_out[kb + NH * HD + lane] = v1;
    kv_out[kb + NH * HD + lane + 32] = v2;

    float inv = 1.0f / powf(10000.0f, (float)lane / 32.0f);
    float ang = (float)t * inv;
    float c = cosf(ang), s = sinf(ang);

    int bh = b * NH + h;
    float qa = (q1 * c - q2 * s) * 0.125f;
    float qb2 = (q2 * c + q1 * s) * 0.125f;
    size_t qoff = ((size_t)bh * SEQ + n) * HD;
    Qf[qoff + lane] = __float2half(qa);
    Qf[qoff + lane + 32] = __float2half(qb2);

    float ka = k1 * c - k2 * s;
    float kb2 = k2 * c + k1 * s;
    size_t koff = ((size_t)bh * KVLEN + t) * HD;
    Kf[koff + lane] = __float2half(ka);
    Kf[koff + lane + 32] = __float2half(kb2);

    size_t voff = ((size_t)bh * HD) * KVLEN + t;
    Vtf[voff + (size_t)lane * KVLEN] = __float2half(v1);
    Vtf[voff + (size_t)(lane + 32) * KVLEN] = __float2half(v2);
}

// ---------------- cached tokens: copy + rope -> fp16 + fp32 cache ----------------
__global__ __launch_bounds__(128)
void cache_kernel(const float* __restrict__ cached,
                  __half* __restrict__ Kf, __half* __restrict__ Vtf,
                  float* __restrict__ kv_out) {
    int w = blockIdx.x * 4 + (threadIdx.x >> 5);
    int lane = threadIdx.x & 31;
    int h = w % NH;
    int bt = w / NH;
    int b = bt / CACHE_T;
    int t = bt % CACHE_T;

    size_t src = ((((size_t)b * CACHE_T + t) * 2 + 0) * NH + h) * HD;
    float k1 = cached[src + lane], k2 = cached[src + lane + 32];
    float v1 = cached[src + NH * HD + lane], v2 = cached[src + NH * HD + lane + 32];

    size_t dst = ((((size_t)b * KVLEN + t) * 2 + 0) * NH + h) * HD;
    kv_out[dst + lane] = k1;
    kv_out[dst + lane + 32] = k2;
    kv_out[dst + NH * HD + lane] = v1;
    kv_out[dst + NH * HD + lane + 32] = v2;

    float inv = 1.0f / powf(10000.0f, (float)lane / 32.0f);
    float ang = (float)t * inv;
    float c = cosf(ang), s = sinf(ang);
    float ka = k1 * c - k2 * s;
    float kb2 = k2 * c + k1 * s;

    int bh = b * NH + h;
    size_t koff = ((size_t)bh * KVLEN + t) * HD;
    Kf[koff + lane] = __float2half(ka);
    Kf[koff + lane + 32] = __float2half(kb2);

    size_t voff = ((size_t)bh * HD) * KVLEN + t;
    Vtf[voff + (size_t)lane * KVLEN] = __float2half(v1);
    Vtf[voff + (size_t)(lane + 32) * KVLEN] = __float2half(v2);
}

// ---------------- attention: fp16 MMA flash, 64 q-rows/block, 64-key chunks ----------------
// smem: 2 stages x [K 8KB | V 8KB] + Q 8KB = 40KB -> 4 CTAs/SM
#define AT_STAGE 16384
__global__ __launch_bounds__(128)
void attn_mma(const __half* __restrict__ Qf, const __half* __restrict__ Kf,
              const __half* __restrict__ Vtf, __half* __restrict__ Oh) {
    extern __shared__ __align__(16) unsigned char dsm[];
    uint32_t sbase = smem_u32(dsm);
    uint32_t qarea = sbase + 2 * AT_STAGE;

    int tid = threadIdx.x, lane = tid & 31, wid = tid >> 5;
    int bh = blockIdx.y;
    int b = bh / NH, h = bh % NH;
    int q0 = blockIdx.x * 64;

    size_t qoff = ((size_t)bh * SEQ + q0) * HD;
    size_t koff = (size_t)bh * KVLEN * HD;
    size_t voff = (size_t)bh * HD * KVLEN;

    int lr = tid >> 1;
    int lc4 = (tid & 1) * 4;

    {
        const __half* qg = Qf + qoff + lr * HD;
        #pragma unroll
        for (int j = 0; j < 4; j++) {
            int ch = lc4 + j;
            uint32_t phys = (uint32_t)((ch ^ (lr & 7)) * 16);
            cpasync16(qarea + lr * 128 + phys, qg + ch * 8);
        }
        cpcommit();
    }

    auto issueKV = [&](int c, int buf) {
        uint32_t dst = sbase + buf * AT_STAGE + lr * 128;
        const __half* kg = Kf + koff + (size_t)(c * 64 + lr) * HD;
        const __half* vg = Vtf + voff + (size_t)lr * KVLEN + c * 64;
        #pragma unroll
        for (int j = 0; j < 4; j++) {
            int ch = lc4 + j;
            uint32_t phys = (uint32_t)((ch ^ (lr & 7)) * 16);
            cpasync16(dst + phys, kg + ch * 8);
            cpasync16(dst + 8192 + phys, vg + ch * 8);
        }
        cpcommit();
    };

    issueKV(0, 0);
    CP_WAIT(1);                   // Q group complete
    __syncthreads();

    int rA = lane & 15, kq = lane >> 4;
    int qrow = wid * 16 + rA;
    int qs = qrow & 7;
    uint32_t qf[4][4];
    #pragma unroll
    for (int kt = 0; kt < 4; kt++) {
        uint32_t phys = (uint32_t)(((kt * 2 + kq) ^ qs) * 16);
        ldmx4(qf[kt], qarea + qrow * 128 + phys);
    }

    int gq = lane >> 2, tg = lane & 3;
    float m0 = -1e30f, m1 = -1e30f, l0 = 0.f, l1 = 0.f;
    float O[8][4];
    #pragma unroll
    for (int nt = 0; nt < 8; nt++)
        #pragma unroll
        for (int i = 0; i < 4; i++) O[nt][i] = 0.f;

    const int NCH = KVLEN / 64;
    for (int c = 0; c < NCH; c++) {
        if (c + 1 < NCH) { issueKV(c + 1, (c + 1) & 1); CP_WAIT(1); }
        else { CP_WAIT(0); }
        __syncthreads();

        uint32_t bufK = sbase + (c & 1) * AT_STAGE;
        uint32_t bufV = bufK + 8192;

        float S[8][4];
        #pragma unroll
        for (int nt = 0; nt < 8; nt++)
            #pragma unroll
            for (int i = 0; i < 4; i++) S[nt][i] = 0.f;

        #pragma unroll
        for (int kt = 0; kt < 4; kt++) {
            uint32_t kf[4][4];
            #pragma unroll
            for (int g2 = 0; g2 < 4; g2++) {
                int krow = g2 * 16 + rA;
                uint32_t phys = (uint32_t)(((kt * 2 + kq) ^ (krow & 7)) * 16);
                ldmx4(kf[g2], bufK + krow * 128 + phys);
            }
            #pragma unroll
            for (int g2 = 0; g2 < 4; g2++)
                #pragma unroll
                for (int hf = 0; hf < 2; hf++)
                    mma16816h(S[2 * g2 + hf], qf[kt], kf[g2][hf], kf[g2][hf + 2]);
        }

        float mx0 = -1e30f, mx1 = -1e30f;
        #pragma unroll
        for (int nt = 0; nt < 8; nt++) {
            mx0 = fmaxf(mx0, fmaxf(S[nt][0], S[nt][1]));
            mx1 = fmaxf(mx1, fmaxf(S[nt][2], S[nt][3]));
        }
        mx0 = fmaxf(mx0, __shfl_xor_sync(0xffffffffu, mx0, 1));
        mx0 = fmaxf(mx0, __shfl_xor_sync(0xffffffffu, mx0, 2));
        mx1 = fmaxf(mx1, __shfl_xor_sync(0xffffffffu, mx1, 1));
        mx1 = fmaxf(mx1, __shfl_xor_sync(0xffffffffu, mx1, 2));
        float nm0 = fmaxf(m0, mx0), nm1 = fmaxf(m1, mx1);
        float a0 = __expf(m0 - nm0), a1 = __expf(m1 - nm1);

        float rs0 = 0.f, rs1 = 0.f;
        #pragma unroll
        for (int nt = 0; nt < 8; nt++) {
            S[nt][0] = __expf(S[nt][0] - nm0);
            S[nt][1] = __expf(S[nt][1] - nm0);
            S[nt][2] = __expf(S[nt][2] - nm1);
            S[nt][3] = __expf(S[nt][3] - nm1);
            rs0 += S[nt][0] + S[nt][1];
            rs1 += S[nt][2] + S[nt][3];
        }
        rs0 += __shfl_xor_sync(0xffffffffu, rs0, 1);
        rs0 += __shfl_xor_sync(0xffffffffu, rs0, 2);
        rs1 += __shfl_xor_sync(0xffffffffu, rs1, 1);
        rs1 += __shfl_xor_sync(0xffffffffu, rs1, 2);
        l0 = l0 * a0 + rs0;
        l1 = l1 * a1 + rs1;
        m0 = nm0; m1 = nm1;
        #pragma unroll
        for (int nt = 0; nt < 8; nt++) {
            O[nt][0] *= a0; O[nt][1] *= a0;
            O[nt][2] *= a1; O[nt][3] *= a1;
        }

        // O += P V (single fp16)
        #pragma unroll
        for (int kt = 0; kt < 4; kt++) {
            uint32_t ah[4];
            {
                __half2 p0 = __floats2half2_rn(S[2 * kt][0], S[2 * kt][1]);
                __half2 p1 = __floats2half2_rn(S[2 * kt][2], S[2 * kt][3]);
                __half2 p2 = __floats2half2_rn(S[2 * kt + 1][0], S[2 * kt + 1][1]);
                __half2 p3 = __floats2half2_rn(S[2 * kt + 1][2], S[2 * kt + 1][3]);
                ah[0] = *reinterpret_cast<uint32_t*>(&p0);
                ah[1] = *reinterpret_cast<uint32_t*>(&p1);
                ah[2] = *reinterpret_cast<uint32_t*>(&p2);
                ah[3] = *reinterpret_cast<uint32_t*>(&p3);
            }
            uint32_t vf[4][4];
            #pragma unroll
            for (int g2 = 0; g2 < 4; g2++) {
                int vrow = g2 * 16 + rA;
                uint32_t phys = (uint32_t)(((kt * 2 + kq) ^ (vrow & 7)) * 16);
                ldmx4(vf[g2], bufV + vrow * 128 + phys);
            }
            #pragma unroll
            for (int g2 = 0; g2 < 4; g2++)
                #pragma unroll
                for (int hf = 0; hf < 2; hf++)
                    mma16816h(O[2 * g2 + hf], ah, vf[g2][hf], vf[g2][hf + 2]);
        }
        __syncthreads();
    }

    float inv0 = 1.0f / l0, inv1 = 1.0f / l1;
    int r0 = q0 + wid * 16 + gq;
    size_t tok0 = (size_t)(b * SEQ + r0);
    size_t tok1 = tok0 + 8;
    #pragma unroll
    for (int nt = 0; nt < 8; nt++) {
        int col = h * HD + nt * 8 + 2 * tg;
        __half2 h0 = __floats2half2_rn(O[nt][0] * inv0, O[nt][1] * inv0);
        __half2 h1 = __floats2half2_rn(O[nt][2] * inv1, O[nt][3] * inv1);
        *(uint32_t*)&Oh[tok0 * DM + col] = *reinterpret_cast<uint32_t*>(&h0);
        *(uint32_t*)&Oh[tok1 * DM + col] = *reinterpret_cast<uint32_t*>(&h1);
    }
}

// ---------------- depthwise conv, sliding window: 8 outputs/thread ----------------
#define DW_NP 8
__global__ void dwconv_kernel(const __half* __restrict__ in,
                              const float* __restrict__ w,
                              const float* __restrict__ bias,
                              float* __restrict__ out) {
    int i = blockIdx.x * blockDim.x + threadIdx.x;
    if (i >= (NTOK / DW_NP) * DM) return;
    int c = i % DM;
    int tile = i / DM;
    int ntile = tile % (SEQ / DW_NP);
    int b = tile / (SEQ / DW_NP);
    int n0 = ntile * DW_NP;

    __half vin[DW_NP + KSZ - 1];
    #pragma unroll
    for (int j = 0; j < DW_NP + KSZ - 1; j++) {
        int nn = n0 - (KSZ / 2) + j;
        vin[j] = (nn >= 0 && nn < SEQ) ? in[((size_t)b * SEQ + nn) * DM + c]
                                       : __float2half(0.f);
    }
    float acc[DW_NP];
    float bv = bias[c];
    #pragma unroll
    for (int j = 0; j < DW_NP; j++) acc[j] = bv;
    #pragma unroll
    for (int k = 0; k < KSZ; k++) {
        float wk = w[c * KSZ + k];
        #pragma unroll
        for (int j = 0; j < DW_NP; j++)
            acc[j] = fmaf(__half2float(vin[j + k]), wk, acc[j]);
    }
    #pragma unroll
    for (int j = 0; j < DW_NP; j++)
        out[((size_t)b * SEQ + n0 + j) * DM + c] = acc[j];
}

// ---------------- batchnorm stats (coalesced: 32 channels x 8 row-groups) ----------------
__global__ __launch_bounds__(256)
void bnstats_kernel(const float* __restrict__ in,
                    float* __restrict__ mean, float* __restrict__ var) {
    int c = blockIdx.x * 32 + (threadIdx.x & 31);
    int ty = threadIdx.x >> 5;                // 0..7
    float s = 0.f, ss = 0.f;
    for (int r = ty; r < NTOK; r += 8) {
        float v = in[(size_t)r * DM + c];
        s += v;
        ss += v * v;
    }
    __shared__ float sm[8][32], sm2[8][32];
    sm[ty][threadIdx.x & 31] = s;
    sm2[ty][threadIdx.x & 31] = ss;
    __syncthreads();
    if (ty == 0) {
        float ts = 0.f, tss = 0.f;
        #pragma unroll
        for (int j = 0; j < 8; j++) {
            ts += sm[j][threadIdx.x & 31];
            tss += sm2[j][threadIdx.x & 31];
        }
        float m = ts / (float)NTOK;
        mean[c] = m;
        var[c] = tss / (float)NTOK - m * m;
    }
}

// ---------------- bn apply + swish -> fp16 single ----------------
__global__ void bnapply_fp16_kernel(const float* __restrict__ in,
                                    const float* __restrict__ mean, const float* __restrict__ var,
                                    const float* __restrict__ g, const float* __restrict__ be,
                                    __half* __restrict__ out) {
    int i = blockIdx.x * blockDim.x + threadIdx.x;
    if (i >= NTOK * DM) return;
    int c = i % DM;
    float y = (in[i] - mean[c]) * rsqrtf(var[c] + EPSF) * g[c] + be[c];
    y = y * sigmoidf_(y);
    out[i] = __float2half(y);
}

// ---------------- host-side helpers ----------------
static __nv_bfloat16* s_b2 = nullptr;

static void tc_gemm_fp16(const __half* A1, const float* W, void* C,
                         int M, int N, int K,
                         const float* bias, const float* res, float scale, int act,
                         int outmode) {
    convB_fp16_kernel<<<dim3(K / 32, N / 32), dim3(32, 8)>>>(
        W, (__half*)s_b2, K, N, outmode == 3 ? 1 : 0);
    hgemm_fp16<<<dim3(N / 128, M / 128), 256, 98304>>>(
        (const uint16_t*)A1, (const uint16_t*)s_b2, C, M, N, K,
        bias, res, scale, act, outmode);
}

extern "C" void kernel_launch(void* const* d_in, const int* in_sizes, int n_in,
                              void* d_out, int out_size) {
    (void)in_sizes; (void)n_in; (void)out_size;
    const float* x          = (const float*)d_in[0];
    const float* cached_kv  = (const float*)d_in[4];
    const float* ff1_norm_w = (const float*)d_in[5];
    const float* ff1_w1     = (const float*)d_in[6];
    const float* ff1_b1     = (const float*)d_in[7];
    const float* ff1_w2     = (const float*)d_in[8];
    const float* ff1_b2     = (const float*)d_in[9];
    const float* attn_norm_w= (const float*)d_in[10];
    const float* qkv_w      = (const float*)d_in[11];
    const float* out_w      = (const float*)d_in[12];
    const float* q_norm_w   = (const float*)d_in[13];
    const float* k_norm_w   = (const float*)d_in[14];
    const float* conv_norm_w= (const float*)d_in[15];
    const float* pw1_w      = (const float*)d_in[16];
    const float* pw1_b      = (const float*)d_in[17];
    const float* dw_w       = (const float*)d_in[18];
    const float* dw_b       = (const float*)d_in[19];
    const float* bn_g       = (const float*)d_in[20];
    const float* bn_b       = (const float*)d_in[21];
    const float* pw2_w      = (const float*)d_in[22];
    const float* pw2_b      = (const float*)d_in[23];
    const float* ff2_norm_w = (const float*)d_in[24];
    const float* ff2_w1     = (const float*)d_in[25];
    const float* ff2_b1     = (const float*)d_in[26];
    const float* ff2_w2     = (const float*)d_in[27];
    const float* ff2_b2     = (const float*)d_in[28];
    const float* out_norm_w = (const float*)d_in[29];

    float* out_x  = (float*)d_out;
    float* out_kv = out_x + (size_t)NTOK * DM;

    float *gX1, *gX2, *gQKV, *gT, *gC, *gM, *gV;
    __nv_bfloat16 *gA2, *gAH;
    __half *gQf, *gKf, *gVtf;
    cudaGetSymbolAddress((void**)&gX1,  g_x1);
    cudaGetSymbolAddress((void**)&gX2,  g_x2);
    cudaGetSymbolAddress((void**)&gQKV, g_qkv);
    cudaGetSymbolAddress((void**)&gT,   g_tmp);
    cudaGetSymbolAddress((void**)&gC,   g_conv);
    cudaGetSymbolAddress((void**)&gM,   g_mean);
    cudaGetSymbolAddress((void**)&gV,   g_var);
    cudaGetSymbolAddress((void**)&gA2,  g_a2);
    cudaGetSymbolAddress((void**)&gAH,  g_ah);
    cudaGetSymbolAddress((void**)&s_b2, g_b2);
    cudaGetSymbolAddress((void**)&gQf,  g_qf);
    cudaGetSymbolAddress((void**)&gKf,  g_kf);
    cudaGetSymbolAddress((void**)&gVtf, g_vtf);

    __half* gF16 = (__half*)gA2;     // fp16 GEMM input (M, DM)
    __half* gH16 = (__half*)gAH;     // fp16 FF intermediate (M, FFD)
    __half* gT16 = (__half*)gT;      // fp16 GLU output (M, DM)

    cudaFuncSetAttribute(hgemm_fp16, cudaFuncAttributeMaxDynamicSharedMemorySize, 98304);
    cudaFuncSetAttribute(attn_mma, cudaFuncAttributeMaxDynamicSharedMemorySize, 40960);

    const int EW_BLOCKS = (NTOK * DM + 255) / 256;
    const int DW_BLOCKS = ((NTOK / DW_NP) * DM + 255) / 256;
    const int RN_BLOCKS = NTOK / 8;

    // ---- FF1 ----
    rmsnorm_fp16_kernel<<<RN_BLOCKS, 256>>>(x, ff1_norm_w, gF16);
    tc_gemm_fp16(gF16, ff1_w1, gH16, NTOK, FFD, DM, ff1_b1, nullptr, 1.0f, 1, 2);
    tc_gemm_fp16(gH16, ff1_w2, gX1, NTOK, DM, FFD, ff1_b2, x, 0.5f, 0, 0);

    // ---- Attention (fp16 core) ----
    rmsnorm_fp16_kernel<<<RN_BLOCKS, 256>>>(gX1, attn_norm_w, gF16);
    tc_gemm_fp16(gF16, qkv_w, gQKV, NTOK, 3 * NH * HD, DM, nullptr, nullptr, 1.0f, 0, 0);
    qkv_post_kernel<<<NTOK * NH / 4, 128>>>(gQKV, q_norm_w, k_norm_w,
                                            gQf, gKf, gVtf, out_kv);
    cache_kernel<<<BSZ * CACHE_T * NH / 4, 128>>>(cached_kv, gKf, gVtf, out_kv);
    attn_mma<<<dim3(SEQ / 64, BSZ * NH), 128, 40960>>>(gQf, gKf, gVtf, gF16);
    tc_gemm_fp16(gF16, out_w, gX2, NTOK, DM, DM, nullptr, gX1, 1.0f, 0, 0);

    // ---- Conv module (GLU fused into pw1 epilogue) ----
    rmsnorm_fp16_kernel<<<RN_BLOCKS, 256>>>(gX2, conv_norm_w, gF16);
    tc_gemm_fp16(gF16, pw1_w, gT16, NTOK, 2 * DM, DM, pw1_b, nullptr, 1.0f, 0, 3);
    dwconv_kernel<<<DW_BLOCKS, 256>>>(gT16, dw_w, dw_b, gC);
    bnstats_kernel<<<DM / 32, 256>>>(gC, gM, gV);
    bnapply_fp16_kernel<<<EW_BLOCKS, 256>>>(gC, gM, gV, bn_g, bn_b, gF16);
    tc_gemm_fp16(gF16, pw2_w, gX1, NTOK, DM, DM, pw2_b, nullptr, 1.0f, 0, 0);

    // ---- FF2 ----
    rmsnorm_fp16_kernel<<<RN_BLOCKS, 256>>>(gX1, ff2_norm_w, gF16);
    tc_gemm_fp16(gF16, ff2_w1, gH16, NTOK, FFD, DM, ff2_b1, nullptr, 1.0f, 1, 2);
    tc_gemm_fp16(gH16, ff2_w2, gX2, NTOK, DM, FFD, ff2_b2, gX1, 0.5f, 0, 0);

    // ---- final norm ----
    rmsnorm_kernel<<<RN_BLOCKS, 256>>>(gX2, out_norm_w, out_x);
}

// round 15
// speedup vs baseline: 4.5656x; 1.3262x over previous
#include <cuda_runtime.h>
#include <cuda_bf16.h>
#include <cuda_fp16.h>
#include <math.h>
#include <stdint.h>

// ---------------- problem constants ----------------
#define BSZ      2
#define SEQ      2048
#define NTOK     4096          // B*N
#define CACHE_T  512
#define KVLEN    2560
#define DM       768
#define NH       12
#define HD       64
#define FFD      3072
#define KSZ      31
#define EPSF     1e-5f

// ---------------- scratch (device globals; no allocation) ----------------
__device__ __align__(128) float g_x1[NTOK * DM];
__device__ __align__(128) float g_x2[NTOK * DM];
__device__ __align__(128) float g_qkv[NTOK * 3 * NH * HD];
__device__ __align__(128) float g_tmp[NTOK * DM];            // also __half reuse
__device__ __align__(128) float g_conv[NTOK * DM];
__device__ float g_mean[DM];
__device__ float g_var[DM];
__device__ __align__(128) float g_rope[2 * KVLEN * 32];      // cos | sin table
__device__ __align__(128) __nv_bfloat16 g_a2[NTOK * 2 * DM];             // fp16 GEMM input reuse
__device__ __align__(128) __nv_bfloat16 g_ah[(size_t)NTOK * 2 * FFD];    // FF intermediate (fp16 reuse)
__device__ __align__(128) __nv_bfloat16 g_b2[(size_t)FFD * 2 * DM];      // weights (N,2K) / (N,K)
__device__ __align__(128) __half g_qf[BSZ * NH * SEQ * HD];
__device__ __align__(128) __half g_kf[BSZ * NH * KVLEN * HD];
__device__ __align__(128) __half g_vtf[BSZ * NH * HD * KVLEN];           // (b,h,d,t)

// ---------------- helpers ----------------
__device__ __forceinline__ float gelu_tanh(float x) {
    const float c = 0.7978845608028654f;
    float t = tanhf(c * (x + 0.044715f * x * x * x));
    return 0.5f * x * (1.0f + t);
}
__device__ __forceinline__ float sigmoidf_(float x) {
    return 1.0f / (1.0f + expf(-x));
}
__device__ __forceinline__ uint32_t smem_u32(const void* p) {
    uint32_t a;
    asm("{ .reg .u64 t; cvta.to.shared.u64 t, %1; cvt.u32.u64 %0, t; }"
        : "=r"(a) : "l"(p));
    return a;
}
__device__ __forceinline__ void cpasync16(uint32_t dst, const void* src) {
    asm volatile("cp.async.cg.shared.global [%0], [%1], 16;" :: "r"(dst), "l"(src));
}
__device__ __forceinline__ void cpcommit() {
    asm volatile("cp.async.commit_group;");
}
#define CP_WAIT(N) asm volatile("cp.async.wait_group %0;" :: "n"(N))
__device__ __forceinline__ void ldmx4(uint32_t r[4], uint32_t a) {
    asm volatile("ldmatrix.sync.aligned.m8n8.x4.shared.b16 {%0,%1,%2,%3}, [%4];"
                 : "=r"(r[0]), "=r"(r[1]), "=r"(r[2]), "=r"(r[3]) : "r"(a));
}
__device__ __forceinline__ void mma16816h(float c[4], const uint32_t a[4],
                                          uint32_t b0, uint32_t b1) {
    asm volatile(
        "mma.sync.aligned.m16n8k16.row.col.f32.f16.f16.f32 "
        "{%0,%1,%2,%3}, {%4,%5,%6,%7}, {%8,%9}, {%0,%1,%2,%3};"
        : "+f"(c[0]), "+f"(c[1]), "+f"(c[2]), "+f"(c[3])
        : "r"(a[0]), "r"(a[1]), "r"(a[2]), "r"(a[3]), "r"(b0), "r"(b1));
}

// ---------------- rope table: cos/sin for (t, freq) computed once ----------------
__global__ void rope_table_kernel(float* __restrict__ tab) {
    int i = blockIdx.x * blockDim.x + threadIdx.x;   // t*32 + lane
    if (i >= KVLEN * 32) return;
    int lane = i & 31;
    int t = i >> 5;
    float inv = 1.0f / powf(10000.0f, (float)lane / 32.0f);
    float ang = (float)t * inv;
    tab[i] = cosf(ang);
    tab[KVLEN * 32 + i] = sinf(ang);
}

// ---------------- weight conversion: W (K,N) fp32 -> fp16 ----------------
// split=1: (N,2K) hi|lo.  split=0: (N,K) single.
// glu_interleave=1: output row for orig col n is (n<N/2 ? 2n : 2(n-N/2)+1)
__global__ void convB_fp16_kernel(const float* __restrict__ W,
                                  __half* __restrict__ out, int K, int N,
                                  int glu_interleave, int split) {
    __shared__ float t[32][33];
    int k0 = blockIdx.x * 32, n0 = blockIdx.y * 32;
    int tx = threadIdx.x, ty = threadIdx.y;   // 32 x 8
    #pragma unroll
    for (int i = ty; i < 32; i += 8)
        t[i][tx] = W[(size_t)(k0 + i) * N + n0 + tx];
    __syncthreads();
    int half_n = N >> 1;
    #pragma unroll
    for (int i = ty; i < 32; i += 8) {
        float v = t[tx][i];                   // W[k0+tx][n0+i]
        __half h = __float2half(v);
        int n = n0 + i;
        int row = glu_interleave ? ((n < half_n) ? (2 * n) : (2 * (n - half_n) + 1))
                                 : n;
        if (split) {
            float lo = v - __half2float(h);
            size_t b = (size_t)row * (2 * K) + k0 + tx;
            out[b] = h;
            out[b + K] = __float2half(lo);
        } else {
            out[(size_t)row * K + k0 + tx] = h;
        }
    }
}

// ---------------- warp-MMA fp16 GEMM, 128x128x64 tile ----------------
// 256 threads, 8 warps (2m x 4n), warp tile 64x32.
// SPLIT=1: B (N,2K) hi|lo, fused passes share A fragments, 2-stage 48KB stages.
// SPLIT=0: B (N,K) single, 3-stage 32KB stages (R7-proven pipeline).
// outmode 0: fp32 + bias/act/scale/res.  2: fp16.  3: GLU fused (interleaved B).
template<int SPLIT>
__global__ __launch_bounds__(256)
void hgemm_fp16_t(const uint16_t* __restrict__ A1,
                  const uint16_t* __restrict__ B2,
                  void* __restrict__ Cout, int M, int N, int K,
                  const float* __restrict__ bias, const float* __restrict__ res,
                  float scale, int act, int outmode) {
    extern __shared__ __align__(16) unsigned char dsm[];
    uint32_t sbase = smem_u32(dsm);
    const uint32_t STG = SPLIT ? 49152u : 32768u;

    int tid = threadIdx.x;
    int lane = tid & 31;
    int wid = tid >> 5;
    int wm = (wid >> 2) * 64;
    int wn = (wid & 3) * 32;
    int bm = blockIdx.y * 128;
    int bn = blockIdx.x * 128;

    int nkb = K >> 6;

    int lr = tid >> 1;
    int lc = (tid & 1) * 4;
    int sw_r = lr & 7;

    float acc[4][4][4];
    #pragma unroll
    for (int a = 0; a < 4; a++)
        #pragma unroll
        for (int b = 0; b < 4; b++)
            #pragma unroll
            for (int c = 0; c < 4; c++) acc[a][b][c] = 0.f;

    auto issue = [&](int kb, int buf) {
        int off = kb << 6;
        const uint16_t* ag = A1 + (size_t)(bm + lr) * K + off + lc * 8;
        uint32_t abuf = sbase + buf * STG + lr * 128;
        if (SPLIT) {
            const uint16_t* bgh = B2 + (size_t)(bn + lr) * (2 * K) + off + lc * 8;
            const uint16_t* bgl = bgh + K;
            uint32_t hbuf = abuf + 16384;
            uint32_t lbuf = abuf + 32768;
            #pragma unroll
            for (int j = 0; j < 4; j++) {
                uint32_t phys = (uint32_t)((lc + j) ^ sw_r) * 16;
                cpasync16(abuf + phys, ag + j * 8);
                cpasync16(hbuf + phys, bgh + j * 8);
                cpasync16(lbuf + phys, bgl + j * 8);
            }
        } else {
            const uint16_t* bg = B2 + (size_t)(bn + lr) * K + off + lc * 8;
            uint32_t bbuf = abuf + 16384;
            #pragma unroll
            for (int j = 0; j < 4; j++) {
                uint32_t phys = (uint32_t)((lc + j) ^ sw_r) * 16;
                cpasync16(abuf + phys, ag + j * 8);
                cpasync16(bbuf + phys, bg + j * 8);
            }
        }
        cpcommit();
    };

    if (SPLIT) {
        issue(0, 0);
    } else {
        issue(0, 0);
        issue(1, 1);
    }

    int rA = lane & 15;
    int kq = lane >> 4;
    int swA = rA & 7;

    for (int kb = 0; kb < nkb; kb++) {
        if (SPLIT) {
            if (kb + 1 < nkb) { issue(kb + 1, (kb + 1) & 1); CP_WAIT(1); }
            else { CP_WAIT(0); }
            __syncthreads();
        } else {
            if (kb + 1 < nkb) { CP_WAIT(1); } else { CP_WAIT(0); }
            __syncthreads();
            if (kb + 2 < nkb) issue(kb + 2, (kb + 2) % 3);
        }

        uint32_t Ab = sbase + (uint32_t)(SPLIT ? (kb & 1) : (kb % 3)) * STG;
        uint32_t Bh = Ab + 16384;

        #pragma unroll
        for (int ks = 0; ks < 4; ks++) {
            uint32_t phys = (uint32_t)(((ks * 2 + kq) ^ swA) * 16);
            uint32_t af[4][4];
            #pragma unroll
            for (int mt = 0; mt < 4; mt++)
                ldmx4(af[mt], Ab + (uint32_t)(wm + mt * 16 + rA) * 128 + phys);
            {
                uint32_t bf[4][2];
                #pragma unroll
                for (int g = 0; g < 2; g++) {
                    uint32_t r[4];
                    ldmx4(r, Bh + (uint32_t)(wn + g * 16 + rA) * 128 + phys);
                    bf[2 * g][0] = r[0]; bf[2 * g][1] = r[2];
                    bf[2 * g + 1][0] = r[1]; bf[2 * g + 1][1] = r[3];
                }
                #pragma unroll
                for (int mt = 0; mt < 4; mt++)
                    #pragma unroll
                    for (int nt = 0; nt < 4; nt++)
                        mma16816h(acc[mt][nt], af[mt], bf[nt][0], bf[nt][1]);
            }
            if (SPLIT) {
                uint32_t Bl = Ab + 32768;
                uint32_t bf[4][2];
                #pragma unroll
                for (int g = 0; g < 2; g++) {
                    uint32_t r[4];
                    ldmx4(r, Bl + (uint32_t)(wn + g * 16 + rA) * 128 + phys);
                    bf[2 * g][0] = r[0]; bf[2 * g][1] = r[2];
                    bf[2 * g + 1][0] = r[1]; bf[2 * g + 1][1] = r[3];
                }
                #pragma unroll
                for (int mt = 0; mt < 4; mt++)
                    #pragma unroll
                    for (int nt = 0; nt < 4; nt++)
                        mma16816h(acc[mt][nt], af[mt], bf[nt][0], bf[nt][1]);
            }
        }
        if (SPLIT) __syncthreads();   // 2-stage: protect buffer before next issue
        // SPLIT=0: 3-stage, top barrier of next iter guards buffer reuse
    }

    int gq = lane >> 2;
    int tg = lane & 3;
    #pragma unroll
    for (int mt = 0; mt < 4; mt++) {
        #pragma unroll
        for (int nt = 0; nt < 4; nt++) {
            int row0 = bm + wm + mt * 16 + gq;
            int col = bn + wn + nt * 8 + 2 * tg;
            #pragma unroll
            for (int half = 0; half < 2; half++) {
                int row = row0 + half * 8;
                float v0 = acc[mt][nt][2 * half + 0];
                float v1 = acc[mt][nt][2 * half + 1];
                if (outmode == 3) {
                    int j = col >> 1;
                    float a = v0 + (bias ? bias[j] : 0.f);
                    float b = v1 + (bias ? bias[(N >> 1) + j] : 0.f);
                    float r = a * sigmoidf_(b);
                    ((__half*)Cout)[(size_t)row * (N >> 1) + j] = __float2half(r);
                    continue;
                }
                if (bias) { v0 += bias[col]; v1 += bias[col + 1]; }
                if (act == 1) { v0 = gelu_tanh(v0); v1 = gelu_tanh(v1); }
                v0 *= scale; v1 *= scale;
                if (outmode == 0) {
                    float* C = (float*)Cout;
                    if (res) {
                        v0 += res[(size_t)row * N + col];
                        v1 += res[(size_t)row * N + col + 1];
                    }
                    *(float2*)&C[(size_t)row * N + col] = make_float2(v0, v1);
                } else {
                    __half* C3 = (__half*)Cout;
                    __half2 hv = __floats2half2_rn(v0, v1);
                    *(uint32_t*)&C3[(size_t)row * N + col] =
                        *reinterpret_cast<uint32_t*>(&hv);
                }
            }
        }
    }
}

// ---------------- rmsnorm (warp-per-row) fp32 out (final) ----------------
__global__ __launch_bounds__(256)
void rmsnorm_kernel(const float* __restrict__ x,
                    const float* __restrict__ w,
                    float* __restrict__ y) {
    int row = blockIdx.x * 8 + (threadIdx.x >> 5);
    int lane = threadIdx.x & 31;
    const float4* xr = (const float4*)(x + (size_t)row * DM);
    float4 v[6];
    float ss = 0.f;
    #pragma unroll
    for (int j = 0; j < 6; j++) {
        v[j] = xr[lane + 32 * j];
        ss += v[j].x * v[j].x + v[j].y * v[j].y + v[j].z * v[j].z + v[j].w * v[j].w;
    }
    #pragma unroll
    for (int o = 16; o > 0; o >>= 1) ss += __shfl_xor_sync(0xffffffffu, ss, o);
    float r = rsqrtf(ss / (float)DM + EPSF);
    const float4* wr = (const float4*)w;
    float4* yr = (float4*)(y + (size_t)row * DM);
    #pragma unroll
    for (int j = 0; j < 6; j++) {
        float4 wv = wr[lane + 32 * j];
        float4 o4;
        o4.x = v[j].x * r * wv.x;
        o4.y = v[j].y * r * wv.y;
        o4.z = v[j].z * r * wv.z;
        o4.w = v[j].w * r * wv.w;
        yr[lane + 32 * j] = o4;
    }
}

// ---------------- rmsnorm (warp-per-row) -> fp16 single ----------------
__global__ __launch_bounds__(256)
void rmsnorm_fp16_kernel(const float* __restrict__ x,
                         const float* __restrict__ w,
                         __half* __restrict__ y) {
    int row = blockIdx.x * 8 + (threadIdx.x >> 5);
    int lane = threadIdx.x & 31;
    const float4* xr = (const float4*)(x + (size_t)row * DM);
    float4 v[6];
    float ss = 0.f;
    #pragma unroll
    for (int j = 0; j < 6; j++) {
        v[j] = xr[lane + 32 * j];
        ss += v[j].x * v[j].x + v[j].y * v[j].y + v[j].z * v[j].z + v[j].w * v[j].w;
    }
    #pragma unroll
    for (int o = 16; o > 0; o >>= 1) ss += __shfl_xor_sync(0xffffffffu, ss, o);
    float r = rsqrtf(ss / (float)DM + EPSF);
    const float4* wr = (const float4*)w;
    __half* yr = y + (size_t)row * DM;
    #pragma unroll
    for (int j = 0; j < 6; j++) {
        float4 wv = wr[lane + 32 * j];
        __half2 h0 = __floats2half2_rn(v[j].x * r * wv.x, v[j].y * r * wv.y);
        __half2 h1 = __floats2half2_rn(v[j].z * r * wv.z, v[j].w * r * wv.w);
        uint2 st;
        st.x = *reinterpret_cast<uint32_t*>(&h0);
        st.y = *reinterpret_cast<uint32_t*>(&h1);
        *(uint2*)&yr[(lane + 32 * j) * 4] = st;
    }
}

// ---------------- qkv postproc: head rmsnorm + rope -> fp16 Q/K/Vt + fp32 cache ----------------
__global__ __launch_bounds__(128)
void qkv_post_kernel(const float* __restrict__ qkv,
                     const float* __restrict__ qnw, const float* __restrict__ knw,
                     const float* __restrict__ rope,
                     __half* __restrict__ Qf, __half* __restrict__ Kf,
                     __half* __restrict__ Vtf,
                     float* __restrict__ kv_out) {
    int w = blockIdx.x * 4 + (threadIdx.x >> 5);
    int lane = threadIdx.x & 31;
    int h = w % NH;
    int tok = w / NH;
    int b = tok / SEQ;
    int n = tok % SEQ;

    const float* base = qkv + (size_t)tok * (3 * NH * HD) + h * (HD * 3);
    float q1 = base[lane * 3 + 0], q2 = base[(lane + 32) * 3 + 0];
    float k1 = base[lane * 3 + 1], k2 = base[(lane + 32) * 3 + 1];
    float v1 = base[lane * 3 + 2], v2 = base[(lane + 32) * 3 + 2];

    float sq = q1 * q1 + q2 * q2;
    #pragma unroll
    for (int o = 16; o > 0; o >>= 1) sq += __shfl_xor_sync(0xffffffffu, sq, o);
    float rq = rsqrtf(sq / 64.f + EPSF);
    q1 *= rq * qnw[lane]; q2 *= rq * qnw[lane + 32];

    float sk = k1 * k1 + k2 * k2;
    #pragma unroll
    for (int o = 16; o > 0; o >>= 1) sk += __shfl_xor_sync(0xffffffffu, sk, o);
    float rk = rsqrtf(sk / 64.f + EPSF);
    k1 *= rk * knw[lane]; k2 *= rk * knw[lane + 32];

    int t = CACHE_T + n;
    size_t kb = ((((size_t)b * KVLEN + t) * 2 + 0) * NH + h) * HD;
    kv_out[kb + lane] = k1;
    kv_out[kb + lane + 32] = k2;
    kv_out[kb + NH * HD + lane] = v1;
    kv_out[kb + NH * HD + lane + 32] = v2;

    float c = rope[t * 32 + lane];
    float s = rope[KVLEN * 32 + t * 32 + lane];

    int bh = b * NH + h;
    float qa = (q1 * c - q2 * s) * 0.125f;
    float qb2 = (q2 * c + q1 * s) * 0.125f;
    size_t qoff = ((size_t)bh * SEQ + n) * HD;
    Qf[qoff + lane] = __float2half(qa);
    Qf[qoff + lane + 32] = __float2half(qb2);

    float ka = k1 * c - k2 * s;
    float kb2 = k2 * c + k1 * s;
    size_t koff = ((size_t)bh * KVLEN + t) * HD;
    Kf[koff + lane] = __float2half(ka);
    Kf[koff + lane + 32] = __float2half(kb2);

    size_t voff = ((size_t)bh * HD) * KVLEN + t;
    Vtf[voff + (size_t)lane * KVLEN] = __float2half(v1);
    Vtf[voff + (size_t)(lane + 32) * KVLEN] = __float2half(v2);
}

// ---------------- cached tokens: copy + rope -> fp16 + fp32 cache ----------------
__global__ __launch_bounds__(128)
void cache_kernel(const float* __restrict__ cached,
                  const float* __restrict__ rope,
                  __half* __restrict__ Kf, __half* __restrict__ Vtf,
                  float* __restrict__ kv_out) {
    int w = blockIdx.x * 4 + (threadIdx.x >> 5);
    int lane = threadIdx.x & 31;
    int h = w % NH;
    int bt = w / NH;
    int b = bt / CACHE_T;
    int t = bt % CACHE_T;

    size_t src = ((((size_t)b * CACHE_T + t) * 2 + 0) * NH + h) * HD;
    float k1 = cached[src + lane], k2 = cached[src + lane + 32];
    float v1 = cached[src + NH * HD + lane], v2 = cached[src + NH * HD + lane + 32];

    size_t dst = ((((size_t)b * KVLEN + t) * 2 + 0) * NH + h) * HD;
    kv_out[dst + lane] = k1;
    kv_out[dst + lane + 32] = k2;
    kv_out[dst + NH * HD + lane] = v1;
    kv_out[dst + NH * HD + lane + 32] = v2;

    float c = rope[t * 32 + lane];
    float s = rope[KVLEN * 32 + t * 32 + lane];
    float ka = k1 * c - k2 * s;
    float kb2 = k2 * c + k1 * s;

    int bh = b * NH + h;
    size_t koff = ((size_t)bh * KVLEN + t) * HD;
    Kf[koff + lane] = __float2half(ka);
    Kf[koff + lane + 32] = __float2half(kb2);

    size_t voff = ((size_t)bh * HD) * KVLEN + t;
    Vtf[voff + (size_t)lane * KVLEN] = __float2half(v1);
    Vtf[voff + (size_t)(lane + 32) * KVLEN] = __float2half(v2);
}

// ---------------- attention: fp16 MMA flash, 64 q-rows/block, 64-key chunks ----------------
// smem: 2 stages x [K 8KB | V 8KB] + Q 8KB = 40KB -> 4 CTAs/SM
#define AT_STAGE 16384
__global__ __launch_bounds__(128)
void attn_mma(const __half* __restrict__ Qf, const __half* __restrict__ Kf,
              const __half* __restrict__ Vtf, __half* __restrict__ Oh) {
    extern __shared__ __align__(16) unsigned char dsm[];
    uint32_t sbase = smem_u32(dsm);
    uint32_t qarea = sbase + 2 * AT_STAGE;

    int tid = threadIdx.x, lane = tid & 31, wid = tid >> 5;
    int bh = blockIdx.y;
    int b = bh / NH, h = bh % NH;
    int q0 = blockIdx.x * 64;

    size_t qoff = ((size_t)bh * SEQ + q0) * HD;
    size_t koff = (size_t)bh * KVLEN * HD;
    size_t voff = (size_t)bh * HD * KVLEN;

    int lr = tid >> 1;
    int lc4 = (tid & 1) * 4;

    {
        const __half* qg = Qf + qoff + lr * HD;
        #pragma unroll
        for (int j = 0; j < 4; j++) {
            int ch = lc4 + j;
            uint32_t phys = (uint32_t)((ch ^ (lr & 7)) * 16);
            cpasync16(qarea + lr * 128 + phys, qg + ch * 8);
        }
        cpcommit();
    }

    auto issueKV = [&](int c, int buf) {
        uint32_t dst = sbase + buf * AT_STAGE + lr * 128;
        const __half* kg = Kf + koff + (size_t)(c * 64 + lr) * HD;
        const __half* vg = Vtf + voff + (size_t)lr * KVLEN + c * 64;
        #pragma unroll
        for (int j = 0; j < 4; j++) {
            int ch = lc4 + j;
            uint32_t phys = (uint32_t)((ch ^ (lr & 7)) * 16);
            cpasync16(dst + phys, kg + ch * 8);
            cpasync16(dst + 8192 + phys, vg + ch * 8);
        }
        cpcommit();
    };

    issueKV(0, 0);
    CP_WAIT(1);                   // Q group complete
    __syncthreads();

    int rA = lane & 15, kq = lane >> 4;
    int qrow = wid * 16 + rA;
    int qs = qrow & 7;
    uint32_t qf[4][4];
    #pragma unroll
    for (int kt = 0; kt < 4; kt++) {
        uint32_t phys = (uint32_t)(((kt * 2 + kq) ^ qs) * 16);
        ldmx4(qf[kt], qarea + qrow * 128 + phys);
    }

    int gq = lane >> 2, tg = lane & 3;
    float m0 = -1e30f, m1 = -1e30f, l0 = 0.f, l1 = 0.f;
    float O[8][4];
    #pragma unroll
    for (int nt = 0; nt < 8; nt++)
        #pragma unroll
        for (int i = 0; i < 4; i++) O[nt][i] = 0.f;

    const int NCH = KVLEN / 64;
    for (int c = 0; c < NCH; c++) {
        if (c + 1 < NCH) { issueKV(c + 1, (c + 1) & 1); CP_WAIT(1); }
        else { CP_WAIT(0); }
        __syncthreads();

        uint32_t bufK = sbase + (c & 1) * AT_STAGE;
        uint32_t bufV = bufK + 8192;

        float S[8][4];
        #pragma unroll
        for (int nt = 0; nt < 8; nt++)
            #pragma unroll
            for (int i = 0; i < 4; i++) S[nt][i] = 0.f;

        #pragma unroll
        for (int kt = 0; kt < 4; kt++) {
            uint32_t kf[4][4];
            #pragma unroll
            for (int g2 = 0; g2 < 4; g2++) {
                int krow = g2 * 16 + rA;
                uint32_t phys = (uint32_t)(((kt * 2 + kq) ^ (krow & 7)) * 16);
                ldmx4(kf[g2], bufK + krow * 128 + phys);
            }
            #pragma unroll
            for (int g2 = 0; g2 < 4; g2++)
                #pragma unroll
                for (int hf = 0; hf < 2; hf++)
                    mma16816h(S[2 * g2 + hf], qf[kt], kf[g2][hf], kf[g2][hf + 2]);
        }

        float mx0 = -1e30f, mx1 = -1e30f;
        #pragma unroll
        for (int nt = 0; nt < 8; nt++) {
            mx0 = fmaxf(mx0, fmaxf(S[nt][0], S[nt][1]));
            mx1 = fmaxf(mx1, fmaxf(S[nt][2], S[nt][3]));
        }
        mx0 = fmaxf(mx0, __shfl_xor_sync(0xffffffffu, mx0, 1));
        mx0 = fmaxf(mx0, __shfl_xor_sync(0xffffffffu, mx0, 2));
        mx1 = fmaxf(mx1, __shfl_xor_sync(0xffffffffu, mx1, 1));
        mx1 = fmaxf(mx1, __shfl_xor_sync(0xffffffffu, mx1, 2));
        float nm0 = fmaxf(m0, mx0), nm1 = fmaxf(m1, mx1);
        float a0 = __expf(m0 - nm0), a1 = __expf(m1 - nm1);

        float rs0 = 0.f, rs1 = 0.f;
        #pragma unroll
        for (int nt = 0; nt < 8; nt++) {
            S[nt][0] = __expf(S[nt][0] - nm0);
            S[nt][1] = __expf(S[nt][1] - nm0);
            S[nt][2] = __expf(S[nt][2] - nm1);
            S[nt][3] = __expf(S[nt][3] - nm1);
            rs0 += S[nt][0] + S[nt][1];
            rs1 += S[nt][2] + S[nt][3];
        }
        rs0 += __shfl_xor_sync(0xffffffffu, rs0, 1);
        rs0 += __shfl_xor_sync(0xffffffffu, rs0, 2);
        rs1 += __shfl_xor_sync(0xffffffffu, rs1, 1);
        rs1 += __shfl_xor_sync(0xffffffffu, rs1, 2);
        l0 = l0 * a0 + rs0;
        l1 = l1 * a1 + rs1;
        m0 = nm0; m1 = nm1;
        #pragma unroll
        for (int nt = 0; nt < 8; nt++) {
            O[nt][0] *= a0; O[nt][1] *= a0;
            O[nt][2] *= a1; O[nt][3] *= a1;
        }

        // O += P V (single fp16)
        #pragma unroll
        for (int kt = 0; kt < 4; kt++) {
            uint32_t ah[4];
            {
                __half2 p0 = __floats2half2_rn(S[2 * kt][0], S[2 * kt][1]);
                __half2 p1 = __floats2half2_rn(S[2 * kt][2], S[2 * kt][3]);
                __half2 p2 = __floats2half2_rn(S[2 * kt + 1][0], S[2 * kt + 1][1]);
                __half2 p3 = __floats2half2_rn(S[2 * kt + 1][2], S[2 * kt + 1][3]);
                ah[0] = *reinterpret_cast<uint32_t*>(&p0);
                ah[1] = *reinterpret_cast<uint32_t*>(&p1);
                ah[2] = *reinterpret_cast<uint32_t*>(&p2);
                ah[3] = *reinterpret_cast<uint32_t*>(&p3);
            }
            uint32_t vf[4][4];
            #pragma unroll
            for (int g2 = 0; g2 < 4; g2++) {
                int vrow = g2 * 16 + rA;
                uint32_t phys = (uint32_t)(((kt * 2 + kq) ^ (vrow & 7)) * 16);
                ldmx4(vf[g2], bufV + vrow * 128 + phys);
            }
            #pragma unroll
            for (int g2 = 0; g2 < 4; g2++)
                #pragma unroll
                for (int hf = 0; hf < 2; hf++)
                    mma16816h(O[2 * g2 + hf], ah, vf[g2][hf], vf[g2][hf + 2]);
        }
        __syncthreads();
    }

    float inv0 = 1.0f / l0, inv1 = 1.0f / l1;
    int r0 = q0 + wid * 16 + gq;
    size_t tok0 = (size_t)(b * SEQ + r0);
    size_t tok1 = tok0 + 8;
    #pragma unroll
    for (int nt = 0; nt < 8; nt++) {
        int col = h * HD + nt * 8 + 2 * tg;
        __half2 h0 = __floats2half2_rn(O[nt][0] * inv0, O[nt][1] * inv0);
        __half2 h1 = __floats2half2_rn(O[nt][2] * inv1, O[nt][3] * inv1);
        *(uint32_t*)&Oh[tok0 * DM + col] = *reinterpret_cast<uint32_t*>(&h0);
        *(uint32_t*)&Oh[tok1 * DM + col] = *reinterpret_cast<uint32_t*>(&h1);
    }
}

// ---------------- depthwise conv, sliding window: 8 outputs/thread ----------------
#define DW_NP 8
__global__ void dwconv_kernel(const __half* __restrict__ in,
                              const float* __restrict__ w,
                              const float* __restrict__ bias,
                              float* __restrict__ out) {
    int i = blockIdx.x * blockDim.x + threadIdx.x;
    if (i >= (NTOK / DW_NP) * DM) return;
    int c = i % DM;
    int tile = i / DM;
    int ntile = tile % (SEQ / DW_NP);
    int b = tile / (SEQ / DW_NP);
    int n0 = ntile * DW_NP;

    __half vin[DW_NP + KSZ - 1];
    #pragma unroll
    for (int j = 0; j < DW_NP + KSZ - 1; j++) {
        int nn = n0 - (KSZ / 2) + j;
        vin[j] = (nn >= 0 && nn < SEQ) ? in[((size_t)b * SEQ + nn) * DM + c]
                                       : __float2half(0.f);
    }
    float acc[DW_NP];
    float bv = bias[c];
    #pragma unroll
    for (int j = 0; j < DW_NP; j++) acc[j] = bv;
    #pragma unroll
    for (int k = 0; k < KSZ; k++) {
        float wk = w[c * KSZ + k];
        #pragma unroll
        for (int j = 0; j < DW_NP; j++)
            acc[j] = fmaf(__half2float(vin[j + k]), wk, acc[j]);
    }
    #pragma unroll
    for (int j = 0; j < DW_NP; j++)
        out[((size_t)b * SEQ + n0 + j) * DM + c] = acc[j];
}

// ---------------- batchnorm stats (coalesced: 32 channels x 8 row-groups) ----------------
__global__ __launch_bounds__(256)
void bnstats_kernel(const float* __restrict__ in,
                    float* __restrict__ mean, float* __restrict__ var) {
    int c = blockIdx.x * 32 + (threadIdx.x & 31);
    int ty = threadIdx.x >> 5;                // 0..7
    float s = 0.f, ss = 0.f;
    for (int r = ty; r < NTOK; r += 8) {
        float v = in[(size_t)r * DM + c];
        s += v;
        ss += v * v;
    }
    __shared__ float sm[8][32], sm2[8][32];
    sm[ty][threadIdx.x & 31] = s;
    sm2[ty][threadIdx.x & 31] = ss;
    __syncthreads();
    if (ty == 0) {
        float ts = 0.f, tss = 0.f;
        #pragma unroll
        for (int j = 0; j < 8; j++) {
            ts += sm[j][threadIdx.x & 31];
            tss += sm2[j][threadIdx.x & 31];
        }
        float m = ts / (float)NTOK;
        mean[c] = m;
        var[c] = tss / (float)NTOK - m * m;
    }
}

// ---------------- bn apply + swish -> fp16 single ----------------
__global__ void bnapply_fp16_kernel(const float* __restrict__ in,
                                    const float* __restrict__ mean, const float* __restrict__ var,
                                    const float* __restrict__ g, const float* __restrict__ be,
                                    __half* __restrict__ out) {
    int i = blockIdx.x * blockDim.x + threadIdx.x;
    if (i >= NTOK * DM) return;
    int c = i % DM;
    float y = (in[i] - mean[c]) * rsqrtf(var[c] + EPSF) * g[c] + be[c];
    y = y * sigmoidf_(y);
    out[i] = __float2half(y);
}

// ---------------- host-side helpers ----------------
static __nv_bfloat16* s_b2 = nullptr;

static void tc_gemm_fp16(const __half* A1, const float* W, void* C,
                         int M, int N, int K,
                         const float* bias, const float* res, float scale, int act,
                         int outmode, int split) {
    convB_fp16_kernel<<<dim3(K / 32, N / 32), dim3(32, 8)>>>(
        W, (__half*)s_b2, K, N, outmode == 3 ? 1 : 0, split);
    if (split)
        hgemm_fp16_t<1><<<dim3(N / 128, M / 128), 256, 98304>>>(
            (const uint16_t*)A1, (const uint16_t*)s_b2, C, M, N, K,
            bias, res, scale, act, outmode);
    else
        hgemm_fp16_t<0><<<dim3(N / 128, M / 128), 256, 98304>>>(
            (const uint16_t*)A1, (const uint16_t*)s_b2, C, M, N, K,
            bias, res, scale, act, outmode);
}

extern "C" void kernel_launch(void* const* d_in, const int* in_sizes, int n_in,
                              void* d_out, int out_size) {
    (void)in_sizes; (void)n_in; (void)out_size;
    const float* x          = (const float*)d_in[0];
    const float* cached_kv  = (const float*)d_in[4];
    const float* ff1_norm_w = (const float*)d_in[5];
    const float* ff1_w1     = (const float*)d_in[6];
    const float* ff1_b1     = (const float*)d_in[7];
    const float* ff1_w2     = (const float*)d_in[8];
    const float* ff1_b2     = (const float*)d_in[9];
    const float* attn_norm_w= (const float*)d_in[10];
    const float* qkv_w      = (const float*)d_in[11];
    const float* out_w      = (const float*)d_in[12];
    const float* q_norm_w   = (const float*)d_in[13];
    const float* k_norm_w   = (const float*)d_in[14];
    const float* conv_norm_w= (const float*)d_in[15];
    const float* pw1_w      = (const float*)d_in[16];
    const float* pw1_b      = (const float*)d_in[17];
    const float* dw_w       = (const float*)d_in[18];
    const float* dw_b       = (const float*)d_in[19];
    const float* bn_g       = (const float*)d_in[20];
    const float* bn_b       = (const float*)d_in[21];
    const float* pw2_w      = (const float*)d_in[22];
    const float* pw2_b      = (const float*)d_in[23];
    const float* ff2_norm_w = (const float*)d_in[24];
    const float* ff2_w1     = (const float*)d_in[25];
    const float* ff2_b1     = (const float*)d_in[26];
    const float* ff2_w2     = (const float*)d_in[27];
    const float* ff2_b2     = (const float*)d_in[28];
    const float* out_norm_w = (const float*)d_in[29];

    float* out_x  = (float*)d_out;
    float* out_kv = out_x + (size_t)NTOK * DM;

    float *gX1, *gX2, *gQKV, *gT, *gC, *gM, *gV, *gRope;
    __nv_bfloat16 *gA2, *gAH;
    __half *gQf, *gKf, *gVtf;
    cudaGetSymbolAddress((void**)&gX1,  g_x1);
    cudaGetSymbolAddress((void**)&gX2,  g_x2);
    cudaGetSymbolAddress((void**)&gQKV, g_qkv);
    cudaGetSymbolAddress((void**)&gT,   g_tmp);
    cudaGetSymbolAddress((void**)&gC,   g_conv);
    cudaGetSymbolAddress((void**)&gM,   g_mean);
    cudaGetSymbolAddress((void**)&gV,   g_var);
    cudaGetSymbolAddress((void**)&gRope, g_rope);
    cudaGetSymbolAddress((void**)&gA2,  g_a2);
    cudaGetSymbolAddress((void**)&gAH,  g_ah);
    cudaGetSymbolAddress((void**)&s_b2, g_b2);
    cudaGetSymbolAddress((void**)&gQf,  g_qf);
    cudaGetSymbolAddress((void**)&gKf,  g_kf);
    cudaGetSymbolAddress((void**)&gVtf, g_vtf);

    __half* gF16 = (__half*)gA2;     // fp16 GEMM input (M, DM)
    __half* gH16 = (__half*)gAH;     // fp16 FF intermediate (M, FFD)
    __half* gT16 = (__half*)gT;      // fp16 GLU output (M, DM)

    cudaFuncSetAttribute(hgemm_fp16_t<0>, cudaFuncAttributeMaxDynamicSharedMemorySize, 98304);
    cudaFuncSetAttribute(hgemm_fp16_t<1>, cudaFuncAttributeMaxDynamicSharedMemorySize, 98304);
    cudaFuncSetAttribute(attn_mma, cudaFuncAttributeMaxDynamicSharedMemorySize, 40960);

    const int EW_BLOCKS = (NTOK * DM + 255) / 256;
    const int DW_BLOCKS = ((NTOK / DW_NP) * DM + 255) / 256;
    const int RN_BLOCKS = NTOK / 8;

    // ---- rope table (once per call; same values every call) ----
    rope_table_kernel<<<(KVLEN * 32 + 255) / 256, 256>>>(gRope);

    // ---- FF1 (single-fp16 weights) ----
    rmsnorm_fp16_kernel<<<RN_BLOCKS, 256>>>(x, ff1_norm_w, gF16);
    tc_gemm_fp16(gF16, ff1_w1, gH16, NTOK, FFD, DM, ff1_b1, nullptr, 1.0f, 1, 2, 0);
    tc_gemm_fp16(gH16, ff1_w2, gX1, NTOK, DM, FFD, ff1_b2, x, 0.5f, 0, 0, 0);

    // ---- Attention (fp16 core; qkv/out keep hi|lo weights) ----
    rmsnorm_fp16_kernel<<<RN_BLOCKS, 256>>>(gX1, attn_norm_w, gF16);
    tc_gemm_fp16(gF16, qkv_w, gQKV, NTOK, 3 * NH * HD, DM, nullptr, nullptr, 1.0f, 0, 0, 1);
    qkv_post_kernel<<<NTOK * NH / 4, 128>>>(gQKV, q_norm_w, k_norm_w, gRope,
                                            gQf, gKf, gVtf, out_kv);
    cache_kernel<<<BSZ * CACHE_T * NH / 4, 128>>>(cached_kv, gRope, gKf, gVtf, out_kv);
    attn_mma<<<dim3(SEQ / 64, BSZ * NH), 128, 40960>>>(gQf, gKf, gVtf, gF16);
    tc_gemm_fp16(gF16, out_w, gX2, NTOK, DM, DM, nullptr, gX1, 1.0f, 0, 0, 1);

    // ---- Conv module (GLU fused into pw1 epilogue; hi|lo weights) ----
    rmsnorm_fp16_kernel<<<RN_BLOCKS, 256>>>(gX2, conv_norm_w, gF16);
    tc_gemm_fp16(gF16, pw1_w, gT16, NTOK, 2 * DM, DM, pw1_b, nullptr, 1.0f, 0, 3, 1);
    dwconv_kernel<<<DW_BLOCKS, 256>>>(gT16, dw_w, dw_b, gC);
    bnstats_kernel<<<DM / 32, 256>>>(gC, gM, gV);
    bnapply_fp16_kernel<<<EW_BLOCKS, 256>>>(gC, gM, gV, bn_g, bn_b, gF16);
    tc_gemm_fp16(gF16, pw2_w, gX1, NTOK, DM, DM, pw2_b, nullptr, 1.0f, 0, 0, 1);

    // ---- FF2 (single-fp16 weights) ----
    rmsnorm_fp16_kernel<<<RN_BLOCKS, 256>>>(gX1, ff2_norm_w, gF16);
    tc_gemm_fp16(gF16, ff2_w1, gH16, NTOK, FFD, DM, ff2_b1, nullptr, 1.0f, 1, 2, 0);
    tc_gemm_fp16(gH16, ff2_w2, gX2, NTOK, DM, FFD, ff2_b2, gX1, 0.5f, 0, 0, 0);

    // ---- final norm ----
    rmsnorm_kernel<<<RN_BLOCKS, 256>>>(gX2, out_norm_w, out_x);
}

// round 16
// speedup vs baseline: 5.2278x; 1.1451x over previous
#include <cuda_runtime.h>
#include <cuda_bf16.h>
#include <cuda_fp16.h>
#include <math.h>
#include <stdint.h>

// ---------------- problem constants ----------------
#define BSZ      2
#define SEQ      2048
#define NTOK     4096          // B*N
#define CACHE_T  512
#define KVLEN    2560
#define DM       768
#define NH       12
#define HD       64
#define FFD      3072
#define KSZ      31
#define EPSF     1e-5f

// ---------------- scratch (device globals; no allocation) ----------------
__device__ __align__(128) float g_x1[NTOK * DM];
__device__ __align__(128) float g_x2[NTOK * DM];
__device__ __align__(128) float g_qkv[NTOK * 3 * NH * HD];
__device__ __align__(128) float g_tmp[NTOK * DM];            // also __half reuse
__device__ __align__(128) float g_conv[NTOK * DM];
__device__ float g_mean[DM];
__device__ float g_var[DM];
__device__ __align__(128) float g_rope[2 * KVLEN * 32];      // cos | sin table
__device__ __align__(128) __nv_bfloat16 g_a2[NTOK * 2 * DM];             // fp16 GEMM input reuse
__device__ __align__(128) __nv_bfloat16 g_ah[(size_t)NTOK * 2 * FFD];    // FF intermediate (fp16 reuse)
__device__ __align__(128) __nv_bfloat16 g_b2[(size_t)FFD * 2 * DM];      // weights (N,K) fp16
__device__ __align__(128) __half g_qf[BSZ * NH * SEQ * HD];
__device__ __align__(128) __half g_kf[BSZ * NH * KVLEN * HD];
__device__ __align__(128) __half g_vtf[BSZ * NH * HD * KVLEN];           // (b,h,d,t)

// ---------------- helpers ----------------
__device__ __forceinline__ float gelu_tanh(float x) {
    const float c = 0.7978845608028654f;
    float t = tanhf(c * (x + 0.044715f * x * x * x));
    return 0.5f * x * (1.0f + t);
}
__device__ __forceinline__ float sigmoidf_(float x) {
    return 1.0f / (1.0f + expf(-x));
}
__device__ __forceinline__ uint32_t smem_u32(const void* p) {
    uint32_t a;
    asm("{ .reg .u64 t; cvta.to.shared.u64 t, %1; cvt.u32.u64 %0, t; }"
        : "=r"(a) : "l"(p));
    return a;
}
__device__ __forceinline__ void cpasync16(uint32_t dst, const void* src) {
    asm volatile("cp.async.cg.shared.global [%0], [%1], 16;" :: "r"(dst), "l"(src));
}
__device__ __forceinline__ void cpcommit() {
    asm volatile("cp.async.commit_group;");
}
#define CP_WAIT(N) asm volatile("cp.async.wait_group %0;" :: "n"(N))
__device__ __forceinline__ void ldmx4(uint32_t r[4], uint32_t a) {
    asm volatile("ldmatrix.sync.aligned.m8n8.x4.shared.b16 {%0,%1,%2,%3}, [%4];"
                 : "=r"(r[0]), "=r"(r[1]), "=r"(r[2]), "=r"(r[3]) : "r"(a));
}
__device__ __forceinline__ void mma16816h(float c[4], const uint32_t a[4],
                                          uint32_t b0, uint32_t b1) {
    asm volatile(
        "mma.sync.aligned.m16n8k16.row.col.f32.f16.f16.f32 "
        "{%0,%1,%2,%3}, {%4,%5,%6,%7}, {%8,%9}, {%0,%1,%2,%3};"
        : "+f"(c[0]), "+f"(c[1]), "+f"(c[2]), "+f"(c[3])
        : "r"(a[0]), "r"(a[1]), "r"(a[2]), "r"(a[3]), "r"(b0), "r"(b1));
}

// ---------------- rope table: cos/sin for (t, freq) computed once ----------------
__global__ void rope_table_kernel(float* __restrict__ tab) {
    int i = blockIdx.x * blockDim.x + threadIdx.x;   // t*32 + lane
    if (i >= KVLEN * 32) return;
    int lane = i & 31;
    int t = i >> 5;
    float inv = 1.0f / powf(10000.0f, (float)lane / 32.0f);
    float ang = (float)t * inv;
    tab[i] = cosf(ang);
    tab[KVLEN * 32 + i] = sinf(ang);
}

// ---------------- weight conversion: W (K,N) fp32 -> (N,K) fp16 ----------------
// glu_interleave=1: output row for orig col n is (n<N/2 ? 2n : 2(n-N/2)+1)
__global__ void convB_fp16_kernel(const float* __restrict__ W,
                                  __half* __restrict__ out, int K, int N,
                                  int glu_interleave) {
    __shared__ float t[32][33];
    int k0 = blockIdx.x * 32, n0 = blockIdx.y * 32;
    int tx = threadIdx.x, ty = threadIdx.y;   // 32 x 8
    #pragma unroll
    for (int i = ty; i < 32; i += 8)
        t[i][tx] = W[(size_t)(k0 + i) * N + n0 + tx];
    __syncthreads();
    int half_n = N >> 1;
    #pragma unroll
    for (int i = ty; i < 32; i += 8) {
        float v = t[tx][i];                   // W[k0+tx][n0+i]
        int n = n0 + i;
        int row = glu_interleave ? ((n < half_n) ? (2 * n) : (2 * (n - half_n) + 1))
                                 : n;
        out[(size_t)row * K + k0 + tx] = __float2half(v);
    }
}

// ---------------- warp-MMA fp16 GEMM, 128x128x64 tile, 3-stage ----------------
// 256 threads, 8 warps (2m x 4n), warp tile 64x32. A (M,K) fp16, B (N,K) fp16.
// outmode 0: fp32 + bias/act/scale/res.  2: fp16.  3: GLU fused (interleaved B).
__global__ __launch_bounds__(256)
void hgemm_fp16(const uint16_t* __restrict__ A1,
                const uint16_t* __restrict__ B1,
                void* __restrict__ Cout, int M, int N, int K,
                const float* __restrict__ bias, const float* __restrict__ res,
                float scale, int act, int outmode) {
    extern __shared__ __align__(16) unsigned char dsm[];
    uint32_t sbase = smem_u32(dsm);

    int tid = threadIdx.x;
    int lane = tid & 31;
    int wid = tid >> 5;
    int wm = (wid >> 2) * 64;
    int wn = (wid & 3) * 32;
    int bm = blockIdx.y * 128;
    int bn = blockIdx.x * 128;

    int nkb = K >> 6;

    int lr = tid >> 1;
    int lc = (tid & 1) * 4;
    int sw_r = lr & 7;

    float acc[4][4][4];
    #pragma unroll
    for (int a = 0; a < 4; a++)
        #pragma unroll
        for (int b = 0; b < 4; b++)
            #pragma unroll
            for (int c = 0; c < 4; c++) acc[a][b][c] = 0.f;

    auto issue = [&](int kb, int buf) {
        int off = kb << 6;
        const uint16_t* ag = A1 + (size_t)(bm + lr) * K + off + lc * 8;
        const uint16_t* bg = B1 + (size_t)(bn + lr) * K + off + lc * 8;
        uint32_t abuf = sbase + buf * 32768 + lr * 128;
        uint32_t bbuf = abuf + 16384;
        #pragma unroll
        for (int j = 0; j < 4; j++) {
            uint32_t phys = (uint32_t)((lc + j) ^ sw_r) * 16;
            cpasync16(abuf + phys, ag + j * 8);
            cpasync16(bbuf + phys, bg + j * 8);
        }
        cpcommit();
    };

    issue(0, 0);
    issue(1, 1);

    int rA = lane & 15;
    int kq = lane >> 4;
    int swA = rA & 7;

    for (int kb = 0; kb < nkb; kb++) {
        if (kb + 1 < nkb) { CP_WAIT(1); } else { CP_WAIT(0); }
        __syncthreads();
        if (kb + 2 < nkb) issue(kb + 2, (kb + 2) % 3);

        uint32_t Ab = sbase + (uint32_t)(kb % 3) * 32768;
        uint32_t Bb = Ab + 16384;

        #pragma unroll
        for (int ks = 0; ks < 4; ks++) {
            uint32_t phys = (uint32_t)(((ks * 2 + kq) ^ swA) * 16);
            uint32_t af[4][4];
            #pragma unroll
            for (int mt = 0; mt < 4; mt++)
                ldmx4(af[mt], Ab + (uint32_t)(wm + mt * 16 + rA) * 128 + phys);
            uint32_t bf[4][2];
            #pragma unroll
            for (int g = 0; g < 2; g++) {
                uint32_t r[4];
                ldmx4(r, Bb + (uint32_t)(wn + g * 16 + rA) * 128 + phys);
                bf[2 * g][0] = r[0]; bf[2 * g][1] = r[2];
                bf[2 * g + 1][0] = r[1]; bf[2 * g + 1][1] = r[3];
            }
            #pragma unroll
            for (int mt = 0; mt < 4; mt++)
                #pragma unroll
                for (int nt = 0; nt < 4; nt++)
                    mma16816h(acc[mt][nt], af[mt], bf[nt][0], bf[nt][1]);
        }
        // no trailing sync: next iteration's top barrier guards buffer reuse
    }

    int gq = lane >> 2;
    int tg = lane & 3;
    #pragma unroll
    for (int mt = 0; mt < 4; mt++) {
        #pragma unroll
        for (int nt = 0; nt < 4; nt++) {
            int row0 = bm + wm + mt * 16 + gq;
            int col = bn + wn + nt * 8 + 2 * tg;
            #pragma unroll
            for (int half = 0; half < 2; half++) {
                int row = row0 + half * 8;
                float v0 = acc[mt][nt][2 * half + 0];
                float v1 = acc[mt][nt][2 * half + 1];
                if (outmode == 3) {
                    int j = col >> 1;
                    float a = v0 + (bias ? bias[j] : 0.f);
                    float b = v1 + (bias ? bias[(N >> 1) + j] : 0.f);
                    float r = a * sigmoidf_(b);
                    ((__half*)Cout)[(size_t)row * (N >> 1) + j] = __float2half(r);
                    continue;
                }
                if (bias) { v0 += bias[col]; v1 += bias[col + 1]; }
                if (act == 1) { v0 = gelu_tanh(v0); v1 = gelu_tanh(v1); }
                v0 *= scale; v1 *= scale;
                if (outmode == 0) {
                    float* C = (float*)Cout;
                    if (res) {
                        v0 += res[(size_t)row * N + col];
                        v1 += res[(size_t)row * N + col + 1];
                    }
                    *(float2*)&C[(size_t)row * N + col] = make_float2(v0, v1);
                } else {
                    __half* C3 = (__half*)Cout;
                    __half2 hv = __floats2half2_rn(v0, v1);
                    *(uint32_t*)&C3[(size_t)row * N + col] =
                        *reinterpret_cast<uint32_t*>(&hv);
                }
            }
        }
    }
}

// ---------------- rmsnorm (warp-per-row) fp32 out (final) ----------------
__global__ __launch_bounds__(256)
void rmsnorm_kernel(const float* __restrict__ x,
                    const float* __restrict__ w,
                    float* __restrict__ y) {
    int row = blockIdx.x * 8 + (threadIdx.x >> 5);
    int lane = threadIdx.x & 31;
    const float4* xr = (const float4*)(x + (size_t)row * DM);
    float4 v[6];
    float ss = 0.f;
    #pragma unroll
    for (int j = 0; j < 6; j++) {
        v[j] = xr[lane + 32 * j];
        ss += v[j].x * v[j].x + v[j].y * v[j].y + v[j].z * v[j].z + v[j].w * v[j].w;
    }
    #pragma unroll
    for (int o = 16; o > 0; o >>= 1) ss += __shfl_xor_sync(0xffffffffu, ss, o);
    float r = rsqrtf(ss / (float)DM + EPSF);
    const float4* wr = (const float4*)w;
    float4* yr = (float4*)(y + (size_t)row * DM);
    #pragma unroll
    for (int j = 0; j < 6; j++) {
        float4 wv = wr[lane + 32 * j];
        float4 o4;
        o4.x = v[j].x * r * wv.x;
        o4.y = v[j].y * r * wv.y;
        o4.z = v[j].z * r * wv.z;
        o4.w = v[j].w * r * wv.w;
        yr[lane + 32 * j] = o4;
    }
}

// ---------------- rmsnorm (warp-per-row) -> fp16 single ----------------
__global__ __launch_bounds__(256)
void rmsnorm_fp16_kernel(const float* __restrict__ x,
                         const float* __restrict__ w,
                         __half* __restrict__ y) {
    int row = blockIdx.x * 8 + (threadIdx.x >> 5);
    int lane = threadIdx.x & 31;
    const float4* xr = (const float4*)(x + (size_t)row * DM);
    float4 v[6];
    float ss = 0.f;
    #pragma unroll
    for (int j = 0; j < 6; j++) {
        v[j] = xr[lane + 32 * j];
        ss += v[j].x * v[j].x + v[j].y * v[j].y + v[j].z * v[j].z + v[j].w * v[j].w;
    }
    #pragma unroll
    for (int o = 16; o > 0; o >>= 1) ss += __shfl_xor_sync(0xffffffffu, ss, o);
    float r = rsqrtf(ss / (float)DM + EPSF);
    const float4* wr = (const float4*)w;
    __half* yr = y + (size_t)row * DM;
    #pragma unroll
    for (int j = 0; j < 6; j++) {
        float4 wv = wr[lane + 32 * j];
        __half2 h0 = __floats2half2_rn(v[j].x * r * wv.x, v[j].y * r * wv.y);
        __half2 h1 = __floats2half2_rn(v[j].z * r * wv.z, v[j].w * r * wv.w);
        uint2 st;
        st.x = *reinterpret_cast<uint32_t*>(&h0);
        st.y = *reinterpret_cast<uint32_t*>(&h1);
        *(uint2*)&yr[(lane + 32 * j) * 4] = st;
    }
}

// ---------------- qkv postproc: head rmsnorm + rope -> fp16 Q/K/Vt + fp32 cache ----------------
__global__ __launch_bounds__(128)
void qkv_post_kernel(const float* __restrict__ qkv,
                     const float* __restrict__ qnw, const float* __restrict__ knw,
                     const float* __restrict__ rope,
                     __half* __restrict__ Qf, __half* __restrict__ Kf,
                     __half* __restrict__ Vtf,
                     float* __restrict__ kv_out) {
    int w = blockIdx.x * 4 + (threadIdx.x >> 5);
    int lane = threadIdx.x & 31;
    int h = w % NH;
    int tok = w / NH;
    int b = tok / SEQ;
    int n = tok % SEQ;

    const float* base = qkv + (size_t)tok * (3 * NH * HD) + h * (HD * 3);
    float q1 = base[lane * 3 + 0], q2 = base[(lane + 32) * 3 + 0];
    float k1 = base[lane * 3 + 1], k2 = base[(lane + 32) * 3 + 1];
    float v1 = base[lane * 3 + 2], v2 = base[(lane + 32) * 3 + 2];

    float sq = q1 * q1 + q2 * q2;
    #pragma unroll
    for (int o = 16; o > 0; o >>= 1) sq += __shfl_xor_sync(0xffffffffu, sq, o);
    float rq = rsqrtf(sq / 64.f + EPSF);
    q1 *= rq * qnw[lane]; q2 *= rq * qnw[lane + 32];

    float sk = k1 * k1 + k2 * k2;
    #pragma unroll
    for (int o = 16; o > 0; o >>= 1) sk += __shfl_xor_sync(0xffffffffu, sk, o);
    float rk = rsqrtf(sk / 64.f + EPSF);
    k1 *= rk * knw[lane]; k2 *= rk * knw[lane + 32];

    int t = CACHE_T + n;
    size_t kb = ((((size_t)b * KVLEN + t) * 2 + 0) * NH + h) * HD;
    kv_out[kb + lane] = k1;
    kv_out[kb + lane + 32] = k2;
    kv_out[kb + NH * HD + lane] = v1;
    kv_out[kb + NH * HD + lane + 32] = v2;

    float c = rope[t * 32 + lane];
    float s = rope[KVLEN * 32 + t * 32 + lane];

    int bh = b * NH + h;
    float qa = (q1 * c - q2 * s) * 0.125f;
    float qb2 = (q2 * c + q1 * s) * 0.125f;
    size_t qoff = ((size_t)bh * SEQ + n) * HD;
    Qf[qoff + lane] = __float2half(qa);
    Qf[qoff + lane + 32] = __float2half(qb2);

    float ka = k1 * c - k2 * s;
    float kb2 = k2 * c + k1 * s;
    size_t koff = ((size_t)bh * KVLEN + t) * HD;
    Kf[koff + lane] = __float2half(ka);
    Kf[koff + lane + 32] = __float2half(kb2);

    size_t voff = ((size_t)bh * HD) * KVLEN + t;
    Vtf[voff + (size_t)lane * KVLEN] = __float2half(v1);
    Vtf[voff + (size_t)(lane + 32) * KVLEN] = __float2half(v2);
}

// ---------------- cached tokens: copy + rope -> fp16 + fp32 cache ----------------
__global__ __launch_bounds__(128)
void cache_kernel(const float* __restrict__ cached,
                  const float* __restrict__ rope,
                  __half* __restrict__ Kf, __half* __restrict__ Vtf,
                  float* __restrict__ kv_out) {
    int w = blockIdx.x * 4 + (threadIdx.x >> 5);
    int lane = threadIdx.x & 31;
    int h = w % NH;
    int bt = w / NH;
    int b = bt / CACHE_T;
    int t = bt % CACHE_T;

    size_t src = ((((size_t)b * CACHE_T + t) * 2 + 0) * NH + h) * HD;
    float k1 = cached[src + lane], k2 = cached[src + lane + 32];
    float v1 = cached[src + NH * HD + lane], v2 = cached[src + NH * HD + lane + 32];

    size_t dst = ((((size_t)b * KVLEN + t) * 2 + 0) * NH + h) * HD;
    kv_out[dst + lane] = k1;
    kv_out[dst + lane + 32] = k2;
    kv_out[dst + NH * HD + lane] = v1;
    kv_out[dst + NH * HD + lane + 32] = v2;

    float c = rope[t * 32 + lane];
    float s = rope[KVLEN * 32 + t * 32 + lane];
    float ka = k1 * c - k2 * s;
    float kb2 = k2 * c + k1 * s;

    int bh = b * NH + h;
    size_t koff = ((size_t)bh * KVLEN + t) * HD;
    Kf[koff + lane] = __float2half(ka);
    Kf[koff + lane + 32] = __float2half(kb2);

    size_t voff = ((size_t)bh * HD) * KVLEN + t;
    Vtf[voff + (size_t)lane * KVLEN] = __float2half(v1);
    Vtf[voff + (size_t)(lane + 32) * KVLEN] = __float2half(v2);
}

// ---------------- attention: fp16 MMA flash, 64 q-rows/block, 64-key chunks ----------------
// smem: 2 stages x [K 8KB | V 8KB] + Q 8KB = 40KB -> 4 CTAs/SM
#define AT_STAGE 16384
__global__ __launch_bounds__(128)
void attn_mma(const __half* __restrict__ Qf, const __half* __restrict__ Kf,
              const __half* __restrict__ Vtf, __half* __restrict__ Oh) {
    extern __shared__ __align__(16) unsigned char dsm[];
    uint32_t sbase = smem_u32(dsm);
    uint32_t qarea = sbase + 2 * AT_STAGE;

    int tid = threadIdx.x, lane = tid & 31, wid = tid >> 5;
    int bh = blockIdx.y;
    int b = bh / NH, h = bh % NH;
    int q0 = blockIdx.x * 64;

    size_t qoff = ((size_t)bh * SEQ + q0) * HD;
    size_t koff = (size_t)bh * KVLEN * HD;
    size_t voff = (size_t)bh * HD * KVLEN;

    int lr = tid >> 1;
    int lc4 = (tid & 1) * 4;

    {
        const __half* qg = Qf + qoff + lr * HD;
        #pragma unroll
        for (int j = 0; j < 4; j++) {
            int ch = lc4 + j;
            uint32_t phys = (uint32_t)((ch ^ (lr & 7)) * 16);
            cpasync16(qarea + lr * 128 + phys, qg + ch * 8);
        }
        cpcommit();
    }

    auto issueKV = [&](int c, int buf) {
        uint32_t dst = sbase + buf * AT_STAGE + lr * 128;
        const __half* kg = Kf + koff + (size_t)(c * 64 + lr) * HD;
        const __half* vg = Vtf + voff + (size_t)lr * KVLEN + c * 64;
        #pragma unroll
        for (int j = 0; j < 4; j++) {
            int ch = lc4 + j;
            uint32_t phys = (uint32_t)((ch ^ (lr & 7)) * 16);
            cpasync16(dst + phys, kg + ch * 8);
            cpasync16(dst + 8192 + phys, vg + ch * 8);
        }
        cpcommit();
    };

    issueKV(0, 0);
    CP_WAIT(1);                   // Q group complete
    __syncthreads();

    int rA = lane & 15, kq = lane >> 4;
    int qrow = wid * 16 + rA;
    int qs = qrow & 7;
    uint32_t qf[4][4];
    #pragma unroll
    for (int kt = 0; kt < 4; kt++) {
        uint32_t phys = (uint32_t)(((kt * 2 + kq) ^ qs) * 16);
        ldmx4(qf[kt], qarea + qrow * 128 + phys);
    }

    int gq = lane >> 2, tg = lane & 3;
    float m0 = -1e30f, m1 = -1e30f, l0 = 0.f, l1 = 0.f;
    float O[8][4];
    #pragma unroll
    for (int nt = 0; nt < 8; nt++)
        #pragma unroll
        for (int i = 0; i < 4; i++) O[nt][i] = 0.f;

    const int NCH = KVLEN / 64;
    for (int c = 0; c < NCH; c++) {
        if (c + 1 < NCH) { issueKV(c + 1, (c + 1) & 1); CP_WAIT(1); }
        else { CP_WAIT(0); }
        __syncthreads();

        uint32_t bufK = sbase + (c & 1) * AT_STAGE;
        uint32_t bufV = bufK + 8192;

        float S[8][4];
        #pragma unroll
        for (int nt = 0; nt < 8; nt++)
            #pragma unroll
            for (int i = 0; i < 4; i++) S[nt][i] = 0.f;

        #pragma unroll
        for (int kt = 0; kt < 4; kt++) {
            uint32_t kf[4][4];
            #pragma unroll
            for (int g2 = 0; g2 < 4; g2++) {
                int krow = g2 * 16 + rA;
                uint32_t phys = (uint32_t)(((kt * 2 + kq) ^ (krow & 7)) * 16);
                ldmx4(kf[g2], bufK + krow * 128 + phys);
            }
            #pragma unroll
            for (int g2 = 0; g2 < 4; g2++)
                #pragma unroll
                for (int hf = 0; hf < 2; hf++)
                    mma16816h(S[2 * g2 + hf], qf[kt], kf[g2][hf], kf[g2][hf + 2]);
        }

        float mx0 = -1e30f, mx1 = -1e30f;
        #pragma unroll
        for (int nt = 0; nt < 8; nt++) {
            mx0 = fmaxf(mx0, fmaxf(S[nt][0], S[nt][1]));
            mx1 = fmaxf(mx1, fmaxf(S[nt][2], S[nt][3]));
        }
        mx0 = fmaxf(mx0, __shfl_xor_sync(0xffffffffu, mx0, 1));
        mx0 = fmaxf(mx0, __shfl_xor_sync(0xffffffffu, mx0, 2));
        mx1 = fmaxf(mx1, __shfl_xor_sync(0xffffffffu, mx1, 1));
        mx1 = fmaxf(mx1, __shfl_xor_sync(0xffffffffu, mx1, 2));
        float nm0 = fmaxf(m0, mx0), nm1 = fmaxf(m1, mx1);
        float a0 = __expf(m0 - nm0), a1 = __expf(m1 - nm1);

        float rs0 = 0.f, rs1 = 0.f;
        #pragma unroll
        for (int nt = 0; nt < 8; nt++) {
            S[nt][0] = __expf(S[nt][0] - nm0);
            S[nt][1] = __expf(S[nt][1] - nm0);
            S[nt][2] = __expf(S[nt][2] - nm1);
            S[nt][3] = __expf(S[nt][3] - nm1);
            rs0 += S[nt][0] + S[nt][1];
            rs1 += S[nt][2] + S[nt][3];
        }
        rs0 += __shfl_xor_sync(0xffffffffu, rs0, 1);
        rs0 += __shfl_xor_sync(0xffffffffu, rs0, 2);
        rs1 += __shfl_xor_sync(0xffffffffu, rs1, 1);
        rs1 += __shfl_xor_sync(0xffffffffu, rs1, 2);
        l0 = l0 * a0 + rs0;
        l1 = l1 * a1 + rs1;
        m0 = nm0; m1 = nm1;
        #pragma unroll
        for (int nt = 0; nt < 8; nt++) {
            O[nt][0] *= a0; O[nt][1] *= a0;
            O[nt][2] *= a1; O[nt][3] *= a1;
        }

        // O += P V (single fp16)
        #pragma unroll
        for (int kt = 0; kt < 4; kt++) {
            uint32_t ah[4];
            {
                __half2 p0 = __floats2half2_rn(S[2 * kt][0], S[2 * kt][1]);
                __half2 p1 = __floats2half2_rn(S[2 * kt][2], S[2 * kt][3]);
                __half2 p2 = __floats2half2_rn(S[2 * kt + 1][0], S[2 * kt + 1][1]);
                __half2 p3 = __floats2half2_rn(S[2 * kt + 1][2], S[2 * kt + 1][3]);
                ah[0] = *reinterpret_cast<uint32_t*>(&p0);
                ah[1] = *reinterpret_cast<uint32_t*>(&p1);
                ah[2] = *reinterpret_cast<uint32_t*>(&p2);
                ah[3] = *reinterpret_cast<uint32_t*>(&p3);
            }
            uint32_t vf[4][4];
            #pragma unroll
            for (int g2 = 0; g2 < 4; g2++) {
                int vrow = g2 * 16 + rA;
                uint32_t phys = (uint32_t)(((kt * 2 + kq) ^ (vrow & 7)) * 16);
                ldmx4(vf[g2], bufV + vrow * 128 + phys);
            }
            #pragma unroll
            for (int g2 = 0; g2 < 4; g2++)
                #pragma unroll
                for (int hf = 0; hf < 2; hf++)
                    mma16816h(O[2 * g2 + hf], ah, vf[g2][hf], vf[g2][hf + 2]);
        }
        __syncthreads();
    }

    float inv0 = 1.0f / l0, inv1 = 1.0f / l1;
    int r0 = q0 + wid * 16 + gq;
    size_t tok0 = (size_t)(b * SEQ + r0);
    size_t tok1 = tok0 + 8;
    #pragma unroll
    for (int nt = 0; nt < 8; nt++) {
        int col = h * HD + nt * 8 + 2 * tg;
        __half2 h0 = __floats2half2_rn(O[nt][0] * inv0, O[nt][1] * inv0);
        __half2 h1 = __floats2half2_rn(O[nt][2] * inv1, O[nt][3] * inv1);
        *(uint32_t*)&Oh[tok0 * DM + col] = *reinterpret_cast<uint32_t*>(&h0);
        *(uint32_t*)&Oh[tok1 * DM + col] = *reinterpret_cast<uint32_t*>(&h1);
    }
}

// ---------------- depthwise conv, sliding window: 8 outputs/thread ----------------
#define DW_NP 8
__global__ void dwconv_kernel(const __half* __restrict__ in,
                              const float* __restrict__ w,
                              const float* __restrict__ bias,
                              float* __restrict__ out) {
    int i = blockIdx.x * blockDim.x + threadIdx.x;
    if (i >= (NTOK / DW_NP) * DM) return;
    int c = i % DM;
    int tile = i / DM;
    int ntile = tile % (SEQ / DW_NP);
    int b = tile / (SEQ / DW_NP);
    int n0 = ntile * DW_NP;

    __half vin[DW_NP + KSZ - 1];
    #pragma unroll
    for (int j = 0; j < DW_NP + KSZ - 1; j++) {
        int nn = n0 - (KSZ / 2) + j;
        vin[j] = (nn >= 0 && nn < SEQ) ? in[((size_t)b * SEQ + nn) * DM + c]
                                       : __float2half(0.f);
    }
    float acc[DW_NP];
    float bv = bias[c];
    #pragma unroll
    for (int j = 0; j < DW_NP; j++) acc[j] = bv;
    #pragma unroll
    for (int k = 0; k < KSZ; k++) {
        float wk = w[c * KSZ + k];
        #pragma unroll
        for (int j = 0; j < DW_NP; j++)
            acc[j] = fmaf(__half2float(vin[j + k]), wk, acc[j]);
    }
    #pragma unroll
    for (int j = 0; j < DW_NP; j++)
        out[((size_t)b * SEQ + n0 + j) * DM + c] = acc[j];
}

// ---------------- batchnorm stats (coalesced: 32 channels x 8 row-groups) ----------------
__global__ __launch_bounds__(256)
void bnstats_kernel(const float* __restrict__ in,
                    float* __restrict__ mean, float* __restrict__ var) {
    int c = blockIdx.x * 32 + (threadIdx.x & 31);
    int ty = threadIdx.x >> 5;                // 0..7
    float s = 0.f, ss = 0.f;
    for (int r = ty; r < NTOK; r += 8) {
        float v = in[(size_t)r * DM + c];
        s += v;
        ss += v * v;
    }
    __shared__ float sm[8][32], sm2[8][32];
    sm[ty][threadIdx.x & 31] = s;
    sm2[ty][threadIdx.x & 31] = ss;
    __syncthreads();
    if (ty == 0) {
        float ts = 0.f, tss = 0.f;
        #pragma unroll
        for (int j = 0; j < 8; j++) {
            ts += sm[j][threadIdx.x & 31];
            tss += sm2[j][threadIdx.x & 31];
        }
        float m = ts / (float)NTOK;
        mean[c] = m;
        var[c] = tss / (float)NTOK - m * m;
    }
}

// ---------------- bn apply + swish -> fp16 single ----------------
__global__ void bnapply_fp16_kernel(const float* __restrict__ in,
                                    const float* __restrict__ mean, const float* __restrict__ var,
                                    const float* __restrict__ g, const float* __restrict__ be,
                                    __half* __restrict__ out) {
    int i = blockIdx.x * blockDim.x + threadIdx.x;
    if (i >= NTOK * DM) return;
    int c = i % DM;
    float y = (in[i] - mean[c]) * rsqrtf(var[c] + EPSF) * g[c] + be[c];
    y = y * sigmoidf_(y);
    out[i] = __float2half(y);
}

// ---------------- host-side helpers ----------------
static __nv_bfloat16* s_b2 = nullptr;

static void tc_gemm_fp16(const __half* A1, const float* W, void* C,
                         int M, int N, int K,
                         const float* bias, const float* res, float scale, int act,
                         int outmode) {
    convB_fp16_kernel<<<dim3(K / 32, N / 32), dim3(32, 8)>>>(
        W, (__half*)s_b2, K, N, outmode == 3 ? 1 : 0);
    hgemm_fp16<<<dim3(N / 128, M / 128), 256, 98304>>>(
        (const uint16_t*)A1, (const uint16_t*)s_b2, C, M, N, K,
        bias, res, scale, act, outmode);
}

extern "C" void kernel_launch(void* const* d_in, const int* in_sizes, int n_in,
                              void* d_out, int out_size) {
    (void)in_sizes; (void)n_in; (void)out_size;
    const float* x          = (const float*)d_in[0];
    const float* cached_kv  = (const float*)d_in[4];
    const float* ff1_norm_w = (const float*)d_in[5];
    const float* ff1_w1     = (const float*)d_in[6];
    const float* ff1_b1     = (const float*)d_in[7];
    const float* ff1_w2     = (const float*)d_in[8];
    const float* ff1_b2     = (const float*)d_in[9];
    const float* attn_norm_w= (const float*)d_in[10];
    const float* qkv_w      = (const float*)d_in[11];
    const float* out_w      = (const float*)d_in[12];
    const float* q_norm_w   = (const float*)d_in[13];
    const float* k_norm_w   = (const float*)d_in[14];
    const float* conv_norm_w= (const float*)d_in[15];
    const float* pw1_w      = (const float*)d_in[16];
    const float* pw1_b      = (const float*)d_in[17];
    const float* dw_w       = (const float*)d_in[18];
    const float* dw_b       = (const float*)d_in[19];
    const float* bn_g       = (const float*)d_in[20];
    const float* bn_b       = (const float*)d_in[21];
    const float* pw2_w      = (const float*)d_in[22];
    const float* pw2_b      = (const float*)d_in[23];
    const float* ff2_norm_w = (const float*)d_in[24];
    const float* ff2_w1     = (const float*)d_in[25];
    const float* ff2_b1     = (const float*)d_in[26];
    const float* ff2_w2     = (const float*)d_in[27];
    const float* ff2_b2     = (const float*)d_in[28];
    const float* out_norm_w = (const float*)d_in[29];

    float* out_x  = (float*)d_out;
    float* out_kv = out_x + (size_t)NTOK * DM;

    float *gX1, *gX2, *gQKV, *gT, *gC, *gM, *gV, *gRope;
    __nv_bfloat16 *gA2, *gAH;
    __half *gQf, *gKf, *gVtf;
    cudaGetSymbolAddress((void**)&gX1,  g_x1);
    cudaGetSymbolAddress((void**)&gX2,  g_x2);
    cudaGetSymbolAddress((void**)&gQKV, g_qkv);
    cudaGetSymbolAddress((void**)&gT,   g_tmp);
    cudaGetSymbolAddress((void**)&gC,   g_conv);
    cudaGetSymbolAddress((void**)&gM,   g_mean);
    cudaGetSymbolAddress((void**)&gV,   g_var);
    cudaGetSymbolAddress((void**)&gRope, g_rope);
    cudaGetSymbolAddress((void**)&gA2,  g_a2);
    cudaGetSymbolAddress((void**)&gAH,  g_ah);
    cudaGetSymbolAddress((void**)&s_b2, g_b2);
    cudaGetSymbolAddress((void**)&gQf,  g_qf);
    cudaGetSymbolAddress((void**)&gKf,  g_kf);
    cudaGetSymbolAddress((void**)&gVtf, g_vtf);

    __half* gF16 = (__half*)gA2;     // fp16 GEMM input (M, DM)
    __half* gH16 = (__half*)gAH;     // fp16 FF intermediate (M, FFD)
    __half* gT16 = (__half*)gT;      // fp16 GLU output (M, DM)

    cudaFuncSetAttribute(hgemm_fp16, cudaFuncAttributeMaxDynamicSharedMemorySize, 98304);
    cudaFuncSetAttribute(attn_mma, cudaFuncAttributeMaxDynamicSharedMemorySize, 40960);

    const int EW_BLOCKS = (NTOK * DM + 255) / 256;
    const int DW_BLOCKS = ((NTOK / DW_NP) * DM + 255) / 256;
    const int RN_BLOCKS = NTOK / 8;

    // ---- rope table (same values every call; deterministic) ----
    rope_table_kernel<<<(KVLEN * 32 + 255) / 256, 256>>>(gRope);

    // ---- FF1 ----
    rmsnorm_fp16_kernel<<<RN_BLOCKS, 256>>>(x, ff1_norm_w, gF16);
    tc_gemm_fp16(gF16, ff1_w1, gH16, NTOK, FFD, DM, ff1_b1, nullptr, 1.0f, 1, 2);
    tc_gemm_fp16(gH16, ff1_w2, gX1, NTOK, DM, FFD, ff1_b2, x, 0.5f, 0, 0);

    // ---- Attention ----
    rmsnorm_fp16_kernel<<<RN_BLOCKS, 256>>>(gX1, attn_norm_w, gF16);
    tc_gemm_fp16(gF16, qkv_w, gQKV, NTOK, 3 * NH * HD, DM, nullptr, nullptr, 1.0f, 0, 0);
    qkv_post_kernel<<<NTOK * NH / 4, 128>>>(gQKV, q_norm_w, k_norm_w, gRope,
                                            gQf, gKf, gVtf, out_kv);
    cache_kernel<<<BSZ * CACHE_T * NH / 4, 128>>>(cached_kv, gRope, gKf, gVtf, out_kv);
    attn_mma<<<dim3(SEQ / 64, BSZ * NH), 128, 40960>>>(gQf, gKf, gVtf, gF16);
    tc_gemm_fp16(gF16, out_w, gX2, NTOK, DM, DM, nullptr, gX1, 1.0f, 0, 0);

    // ---- Conv module (GLU fused into pw1 epilogue) ----
    rmsnorm_fp16_kernel<<<RN_BLOCKS, 256>>>(gX2, conv_norm_w, gF16);
    tc_gemm_fp16(gF16, pw1_w, gT16, NTOK, 2 * DM, DM, pw1_b, nullptr, 1.0f, 0, 3);
    dwconv_kernel<<<DW_BLOCKS, 256>>>(gT16, dw_w, dw_b, gC);
    bnstats_kernel<<<DM / 32, 256>>>(gC, gM, gV);
    bnapply_fp16_kernel<<<EW_BLOCKS, 256>>>(gC, gM, gV, bn_g, bn_b, gF16);
    tc_gemm_fp16(gF16, pw2_w, gX1, NTOK, DM, DM, pw2_b, nullptr, 1.0f, 0, 0);

    // ---- FF2 ----
    rmsnorm_fp16_kernel<<<RN_BLOCKS, 256>>>(gX1, ff2_norm_w, gF16);
    tc_gemm_fp16(gF16, ff2_w1, gH16, NTOK, FFD, DM, ff2_b1, nullptr, 1.0f, 1, 2);
    tc_gemm_fp16(gH16, ff2_w2, gX2, NTOK, DM, FFD, ff2_b2, gX1, 0.5f, 0, 0);

    // ---- final norm ----
    rmsnorm_kernel<<<RN_BLOCKS, 256>>>(gX2, out_norm_w, out_x);
}